// round 1
// baseline (speedup 1.0000x reference)
#include <cuda_runtime.h>
#include <cuda_bf16.h>
#include <cstdint>

// ---------------- problem constants ----------------
#define NATOM 25600
#define NAA   204800
#define EATOM 102400
#define EAA   1024000
#define EM2P  512000
#define DIM   200
#define HCD   100
#define NB    512

// ---------------- scratch layout (floats) ----------------
// one big __device__ array; offsets below
static const long OFF_AX   = 0;                       // 25600*200
static const long OFF_PX   = OFF_AX   + 5120000L;     // 204800*200
static const long OFF_HSA  = OFF_PX   + 40960000L;    // 25600*100
static const long OFF_HSB  = OFF_HSA  + 2560000L;     // 204800*100
static const long OFF_ALS  = OFF_HSB  + 20480000L;    // 204800*2
static const long OFF_ALD  = OFF_ALS  + 409600L;      // 204800*2
static const long OFF_M    = OFF_ALD  + 409600L;      // 204800*2
static const long OFF_Z    = OFF_M    + 409600L;      // 204800*2
static const long OFF_V    = OFF_Z    + 409600L;      // 200*2 (pad to 512)
static const long OFF_T    = OFF_V    + 512L;         // 204800
static const long OFF_R    = OFF_T    + 204800L;      // 204800
static const long OFF_AGG  = OFF_R    + 204800L;      // 204800
static const long OFF_SPRE = OFF_AGG  + 204800L;      // 204800
static const long OFF_SGM  = OFF_SPRE + 204800L;      // 512
static const long OFF_SGZ  = OFF_SGM  + 512L;         // 512
static const long OFF_CNT  = OFF_SGZ  + 512L;         // 512
static const long OFF_GSUM = OFF_CNT  + 512L;         // 512
static const long OFF_GSQ  = OFF_GSUM + 512L;         // 512
static const long SCRATCH_FLOATS = OFF_GSQ + 512L;    // 71,580,672 floats (~286MB)

__device__ __align__(256) float g_scratch[SCRATCH_FLOATS];

// ---------------- device helpers ----------------
__device__ __forceinline__ float eluf(float x)  { return x > 0.f ? x : expm1f(x); }
__device__ __forceinline__ float lreluf(float x){ return x > 0.f ? x : 0.2f * x; }

__device__ __forceinline__ void atomicMaxF(float* a, float v) {
    // monotone-toward-max for any sign mix
    if (v >= 0.f) atomicMax((int*)a, __float_as_int(v));
    else          atomicMin((unsigned int*)a, __float_as_uint(v));
}

__device__ __forceinline__ float warp_sum(float v) {
    #pragma unroll
    for (int o = 16; o > 0; o >>= 1) v += __shfl_down_sync(0xffffffffu, v, o);
    return v;
}

// ---------------- generic small kernels ----------------
__global__ void fill_k(float* p, float v, int n) {
    int i = blockIdx.x * blockDim.x + threadIdx.x;
    if (i < n) p[i] = v;
}

__global__ void elu_k(const float* __restrict__ x, float* __restrict__ y, long n) {
    long i = (long)blockIdx.x * blockDim.x + threadIdx.x;
    if (i < n) y[i] = eluf(x[i]);
}

// ---------------- GEMM: Y[N,100] = X[N,200] @ W[200,100], fused ALS ----------------
// 4 rows per block, 128 threads. ALS[n,h] = sum_c Y[n,h*50+c]*aflat[h*50+c]
__global__ void gemm_als_k(const float* __restrict__ X, const float* __restrict__ W,
                           float* __restrict__ Y, float* __restrict__ ALS,
                           const float* __restrict__ aflat, int N) {
    __shared__ float xs[4 * DIM];
    __shared__ float prod[4][HCD];
    int row0 = blockIdx.x * 4;
    int tid  = threadIdx.x;

    for (int i = tid; i < 4 * DIM; i += 128) {
        int r = i / DIM, k = i - r * DIM;
        int row = row0 + r;
        xs[i] = (row < N) ? X[(size_t)row * DIM + k] : 0.f;
    }
    __syncthreads();

    if (tid < HCD) {
        float a0 = 0.f, a1 = 0.f, a2 = 0.f, a3 = 0.f;
        #pragma unroll 8
        for (int k = 0; k < DIM; k++) {
            float w = W[k * HCD + tid];
            a0 += xs[k] * w;
            a1 += xs[DIM + k] * w;
            a2 += xs[2 * DIM + k] * w;
            a3 += xs[3 * DIM + k] * w;
        }
        float af = aflat[tid];
        prod[0][tid] = a0 * af; prod[1][tid] = a1 * af;
        prod[2][tid] = a2 * af; prod[3][tid] = a3 * af;
        if (row0 + 0 < N) Y[(size_t)(row0 + 0) * HCD + tid] = a0;
        if (row0 + 1 < N) Y[(size_t)(row0 + 1) * HCD + tid] = a1;
        if (row0 + 2 < N) Y[(size_t)(row0 + 2) * HCD + tid] = a2;
        if (row0 + 3 < N) Y[(size_t)(row0 + 3) * HCD + tid] = a3;
    }
    __syncthreads();

    if (tid < 8) {
        int r = tid >> 1, h = tid & 1;
        if (row0 + r < N) {
            float s = 0.f;
            #pragma unroll
            for (int c = 0; c < 50; c++) s += prod[r][h * 50 + c];
            ALS[(size_t)(row0 + r) * 2 + h] = s;
        }
    }
}

// ---------------- fold v[k,h] = sum_c Wdst[k, h*50+c] * adst[h,c] ----------------
__global__ void fold_v_k(const float* __restrict__ Wdst, const float* __restrict__ adst,
                         float* __restrict__ v) {
    int i = blockIdx.x * blockDim.x + threadIdx.x;
    if (i >= 2 * DIM) return;
    int k = i >> 1, h = i & 1;
    float s = 0.f;
    #pragma unroll
    for (int c = 0; c < 50; c++) s += Wdst[k * HCD + h * 50 + c] * adst[h * 50 + c];
    v[2 * k + h] = s;
}

// ---------------- ald[n,h] = X[n,:] @ v[:,h], warp per node ----------------
__global__ void ald_k(const float* __restrict__ X, const float* __restrict__ v,
                      float* __restrict__ ald, int N) {
    int w = (blockIdx.x * blockDim.x + threadIdx.x) >> 5;
    int lane = threadIdx.x & 31;
    if (w >= N) return;
    const float* xr = X + (size_t)w * DIM;
    float a0 = 0.f, a1 = 0.f;
    for (int k = lane; k < DIM; k += 32) {
        float x = xr[k];
        a0 += x * v[2 * k];
        a1 += x * v[2 * k + 1];
    }
    a0 = warp_sum(a0); a1 = warp_sum(a1);
    if (lane == 0) { ald[2 * w] = a0; ald[2 * w + 1] = a1; }
}

// ---------------- edge pass A: per-dst logit max ----------------
__global__ void edge_max_k(const int* __restrict__ src, const int* __restrict__ dst,
                           int E, int nloop,
                           const float* __restrict__ als, const float* __restrict__ ald,
                           float* __restrict__ m) {
    int e = blockIdx.x * blockDim.x + threadIdx.x;
    if (e >= E + nloop) return;
    int s, d;
    if (e < E) { s = src[e]; d = dst[e]; } else { s = e - E; d = e - E; }
    float l0 = lreluf(als[2 * s]     + ald[2 * d]);
    float l1 = lreluf(als[2 * s + 1] + ald[2 * d + 1]);
    atomicMaxF(&m[2 * d],     l0);
    atomicMaxF(&m[2 * d + 1], l1);
}

// ---------------- edge pass B: accumulate z and unnormalized out ----------------
// warp per edge; out row stride 200, column offset coloff (0 = intra, 100 = inter)
__global__ void edge_acc_k(const int* __restrict__ src, const int* __restrict__ dst,
                           int E, int nloop,
                           const float* __restrict__ als, const float* __restrict__ ald,
                           const float* __restrict__ m, const float* __restrict__ hs,
                           float* __restrict__ z, float* __restrict__ out, int coloff) {
    int w = (blockIdx.x * blockDim.x + threadIdx.x) >> 5;
    int lane = threadIdx.x & 31;
    if (w >= E + nloop) return;
    int s, d;
    if (w < E) { s = src[w]; d = dst[w]; } else { s = w - E; d = w - E; }
    float e0 = __expf(lreluf(als[2 * s]     + ald[2 * d])     - m[2 * d]);
    float e1 = __expf(lreluf(als[2 * s + 1] + ald[2 * d + 1]) - m[2 * d + 1]);
    if (lane == 0) atomicAdd(&z[2 * d],     e0);
    if (lane == 1) atomicAdd(&z[2 * d + 1], e1);
    if (lane < 25) {
        int j = lane * 4;
        const float4 h4 = *(const float4*)(hs + (size_t)s * HCD + j);
        float w0 = (j     < 50 ? e0 : e1) * h4.x;
        float w1 = (j + 1 < 50 ? e0 : e1) * h4.y;
        float w2 = (j + 2 < 50 ? e0 : e1) * h4.z;
        float w3 = (j + 3 < 50 ? e0 : e1) * h4.w;
        float* p = out + (size_t)d * DIM + coloff + j;
        asm volatile("red.global.add.v4.f32 [%0], {%1,%2,%3,%4};"
                     :: "l"(p), "f"(w0), "f"(w1), "f"(w2), "f"(w3) : "memory");
    }
}

// ---------------- GAT finalize: divide by z, add bias ----------------
__global__ void gat_fin_k(float* __restrict__ out, const float* __restrict__ z,
                          const float* __restrict__ bias, int N, int coloff) {
    int i = blockIdx.x * blockDim.x + threadIdx.x;
    if (i >= N * HCD) return;
    int n = i / HCD, j = i - n * HCD;
    int h = (j >= 50);
    float* p = out + (size_t)n * DIM + coloff + j;
    *p = *p / (z[2 * n + h] + 1e-16f) + bias[j];
}

// ---------------- graph layernorm ----------------
__global__ void count_k(const int* __restrict__ batch, float* __restrict__ cnt, int N) {
    int i = blockIdx.x * blockDim.x + threadIdx.x;
    if (i < N) atomicAdd(&cnt[batch[i]], 1.f);
}

__global__ void ln_stats_k(const float* __restrict__ x, const int* __restrict__ batch,
                           float* __restrict__ gsum, float* __restrict__ gsq, int N) {
    int w = (blockIdx.x * blockDim.x + threadIdx.x) >> 5;
    int lane = threadIdx.x & 31;
    if (w >= N) return;
    const float* xr = x + (size_t)w * DIM;
    float s = 0.f, q = 0.f;
    for (int k = lane; k < DIM; k += 32) { float v = xr[k]; s += v; q += v * v; }
    s = warp_sum(s); q = warp_sum(q);
    if (lane == 0) {
        int g = batch[w];
        atomicAdd(&gsum[g], s);
        atomicAdd(&gsq[g], q);
    }
}

__global__ void ln_apply_k(float* __restrict__ x, const int* __restrict__ batch,
                           const float* __restrict__ cnt, const float* __restrict__ gsum,
                           const float* __restrict__ gsq,
                           const float* __restrict__ wv, const float* __restrict__ bv, int N) {
    long i = (long)blockIdx.x * blockDim.x + threadIdx.x;
    if (i >= (long)N * DIM) return;
    int n = (int)(i / DIM), j = (int)(i - (long)n * DIM);
    int g = batch[n];
    float norm = fmaxf(cnt[g], 1.f) * (float)DIM;
    float mean = gsum[g] / norm;
    float var  = gsq[g] / norm - mean * mean;
    float y = (x[i] - mean) * rsqrtf(var + 1e-5f) * wv[j] + bv[j];
    x[i] = eluf(y);
}

// ---------------- SAG pooling ----------------
__global__ void sag_tr_k(const float* __restrict__ x, const float* __restrict__ Wrel,
                         const float* __restrict__ Wroot,
                         float* __restrict__ T, float* __restrict__ R, int N) {
    int w = (blockIdx.x * blockDim.x + threadIdx.x) >> 5;
    int lane = threadIdx.x & 31;
    if (w >= N) return;
    const float* xr = x + (size_t)w * DIM;
    float t = 0.f, r = 0.f;
    for (int k = lane; k < DIM; k += 32) {
        float v = xr[k];
        t += v * Wrel[k];
        r += v * Wroot[k];
    }
    t = warp_sum(t); r = warp_sum(r);
    if (lane == 0) { T[w] = t; R[w] = r; }
}

__global__ void sag_edge_k(const int* __restrict__ src, const int* __restrict__ dst, int E,
                           const float* __restrict__ T, float* __restrict__ agg) {
    int e = blockIdx.x * blockDim.x + threadIdx.x;
    if (e < E) atomicAdd(&agg[dst[e]], T[src[e]]);
}

__global__ void sag_spre_k(const float* __restrict__ agg, const float* __restrict__ R,
                           const float* __restrict__ brel, const int* __restrict__ batch,
                           float* __restrict__ spre, float* __restrict__ sgm, int N) {
    int i = blockIdx.x * blockDim.x + threadIdx.x;
    if (i >= N) return;
    float s = agg[i] + brel[0] + R[i];
    spre[i] = s;
    atomicMaxF(&sgm[batch[i]], s);
}

__global__ void sag_z_k(const float* __restrict__ spre, const int* __restrict__ batch,
                        const float* __restrict__ sgm, float* __restrict__ sgz, int N) {
    int i = blockIdx.x * blockDim.x + threadIdx.x;
    if (i >= N) return;
    int g = batch[i];
    atomicAdd(&sgz[g], __expf(spre[i] - sgm[g]));
}

__global__ void sag_scale_k(float* __restrict__ x, const float* __restrict__ spre,
                            const float* __restrict__ sgm, const float* __restrict__ sgz,
                            const int* __restrict__ batch, float* __restrict__ G, int N) {
    long i = (long)blockIdx.x * blockDim.x + threadIdx.x;
    if (i >= (long)N * DIM) return;
    int n = (int)(i / DIM), j = (int)(i - (long)n * DIM);
    int g = batch[n];
    float score = __expf(spre[n] - sgm[g]) / (sgz[g] + 1e-16f);
    float v = x[i] * score;
    x[i] = v;
    atomicAdd(&G[(size_t)g * DIM + j], v);
}

// ---------------- host orchestration ----------------
static void run_gat(const float* Xsrc, const float* Xdst,
                    const float* Wsrc, const float* Wdst,
                    const float* a_src, const float* a_dst, const float* bias,
                    const int* src, const int* dst, int E, int Ns, int Nd, int nloop,
                    float* HS, float* out, int coloff,
                    float* ALS, float* ALD, float* M, float* Z, float* V) {
    fill_k<<<(2 * Nd + 255) / 256, 256>>>(M, -1e30f, 2 * Nd);
    cudaMemsetAsync(Z, 0, (size_t)2 * Nd * sizeof(float));
    gemm_als_k<<<(Ns + 3) / 4, 128>>>(Xsrc, Wsrc, HS, ALS, a_src, Ns);
    fold_v_k<<<2, 256>>>(Wdst, a_dst, V);
    ald_k<<<(Nd * 32 + 255) / 256, 256>>>(Xdst, V, ALD, Nd);
    int tot = E + nloop;
    edge_max_k<<<(tot + 255) / 256, 256>>>(src, dst, E, nloop, ALS, ALD, M);
    edge_acc_k<<<((long)tot * 32 + 255) / 256, 256>>>(src, dst, E, nloop, ALS, ALD, M, HS, Z, out, coloff);
    gat_fin_k<<<((long)Nd * HCD + 255) / 256, 256>>>(out, Z, bias, Nd, coloff);
}

static void run_ln(float* x, const int* batch, const float* w, const float* b, int N,
                   float* CNT, float* GSUM, float* GSQ) {
    cudaMemsetAsync(CNT,  0, NB * sizeof(float));
    cudaMemsetAsync(GSUM, 0, NB * sizeof(float));
    cudaMemsetAsync(GSQ,  0, NB * sizeof(float));
    count_k<<<(N + 255) / 256, 256>>>(batch, CNT, N);
    ln_stats_k<<<(N * 32 + 255) / 256, 256>>>(x, batch, GSUM, GSQ, N);
    ln_apply_k<<<((long)N * DIM + 255) / 256, 256>>>(x, batch, CNT, GSUM, GSQ, w, b, N);
}

static void run_sag(float* x, const int* src, const int* dst, int E, const int* batch,
                    const float* Wrel, const float* brel, const float* Wroot,
                    float* G, int N,
                    float* T, float* R, float* AGG, float* SPRE, float* SGM, float* SGZ) {
    cudaMemsetAsync(AGG, 0, (size_t)N * sizeof(float));
    fill_k<<<(NB + 255) / 256, 256>>>(SGM, -1e30f, NB);
    cudaMemsetAsync(SGZ, 0, NB * sizeof(float));
    sag_tr_k<<<(N * 32 + 255) / 256, 256>>>(x, Wrel, Wroot, T, R, N);
    sag_edge_k<<<(E + 255) / 256, 256>>>(src, dst, E, T, AGG);
    sag_spre_k<<<(N + 255) / 256, 256>>>(AGG, R, brel, batch, SPRE, SGM, N);
    sag_z_k<<<(N + 255) / 256, 256>>>(SPRE, batch, SGM, SGZ, N);
    sag_scale_k<<<((long)N * DIM + 255) / 256, 256>>>(x, SPRE, SGM, SGZ, batch, G, N);
}

extern "C" void kernel_launch(void* const* d_in, const int* in_sizes, int n_in,
                              void* d_out, int out_size) {
    const float* atom_x  = (const float*)d_in[0];
    const int*   aei     = (const int*)  d_in[1];
    const int*   abatch  = (const int*)  d_in[2];
    const float* aa_x    = (const float*)d_in[3];
    const int*   pei     = (const int*)  d_in[4];
    // d_in[5] = aa_edge_attr (unused by reference)
    const int*   pbatch  = (const int*)  d_in[6];
    const int*   m2p     = (const int*)  d_in[7];
    const float* Wd      = (const float*)d_in[8];
    const float* ad_src  = (const float*)d_in[9];
    const float* ad_dst  = (const float*)d_in[10];
    const float* bd      = (const float*)d_in[11];
    const float* Wp      = (const float*)d_in[12];
    const float* ap_src  = (const float*)d_in[13];
    const float* ap_dst  = (const float*)d_in[14];
    const float* bp      = (const float*)d_in[15];
    const float* Wi_src  = (const float*)d_in[16];
    const float* Wi_dst  = (const float*)d_in[17];
    const float* ai_src  = (const float*)d_in[18];
    const float* ai_dst  = (const float*)d_in[19];
    const float* bi      = (const float*)d_in[20];
    const float* ln_d_w  = (const float*)d_in[21];
    const float* ln_d_b  = (const float*)d_in[22];
    const float* ln_p_w  = (const float*)d_in[23];
    const float* ln_p_b  = (const float*)d_in[24];
    const float* pd_Wrel = (const float*)d_in[25];
    const float* pd_brel = (const float*)d_in[26];
    const float* pd_Wroot= (const float*)d_in[27];
    const float* pp_Wrel = (const float*)d_in[28];
    const float* pp_brel = (const float*)d_in[29];
    const float* pp_Wroot= (const float*)d_in[30];

    float* S = nullptr;
    cudaGetSymbolAddress((void**)&S, g_scratch);

    float* AX   = S + OFF_AX;
    float* PX   = S + OFF_PX;
    float* HSA  = S + OFF_HSA;
    float* HSB  = S + OFF_HSB;
    float* ALS  = S + OFF_ALS;
    float* ALD  = S + OFF_ALD;
    float* M    = S + OFF_M;
    float* Z    = S + OFF_Z;
    float* V    = S + OFF_V;
    float* T    = S + OFF_T;
    float* R    = S + OFF_R;
    float* AGG  = S + OFF_AGG;
    float* SPRE = S + OFF_SPRE;
    float* SGM  = S + OFF_SGM;
    float* SGZ  = S + OFF_SGZ;
    float* CNT  = S + OFF_CNT;
    float* GSUM = S + OFF_GSUM;
    float* GSQ  = S + OFF_GSQ;

    float* out = (float*)d_out;
    float* OA  = out;                                  // atom_out / atom_h [25600,200]
    float* OP  = out + (size_t)NATOM * DIM;            // aa_out / aa_h     [204800,200]
    float* DG  = out + (size_t)(NATOM + NAA) * DIM;    // drug_g [512,200]
    float* PG  = DG + (size_t)NB * DIM;                // prot_g [512,200]

    // zero the whole output (it is the GAT accumulation target, and d_out is poisoned)
    cudaMemsetAsync(d_out, 0, (size_t)out_size * sizeof(float));

    // elu inputs
    elu_k<<<((long)NATOM * DIM + 255) / 256, 256>>>(atom_x, AX, (long)NATOM * DIM);
    elu_k<<<((long)NAA * DIM + 255) / 256, 256>>>(aa_x, PX, (long)NAA * DIM);

    const int* a_src_e = aei;               // atom edges: row0=src, row1=dst
    const int* a_dst_e = aei + EATOM;
    const int* p_src_e = pei;
    const int* p_dst_e = pei + EAA;
    const int* m_atom  = m2p;               // row0 = atom indices
    const int* m_aa    = m2p + EM2P;        // row1 = aa indices
    const int  nloop_i = NATOM;             // min(NATOM, NAA)

    // --- atom intra: GAT(ax -> ax) into OA cols [0,100) ---
    run_gat(AX, AX, Wd, Wd, ad_src, ad_dst, bd,
            a_src_e, a_dst_e, EATOM, NATOM, NATOM, NATOM,
            HSA, OA, 0, ALS, ALD, M, Z, V);

    // --- atom inter: GAT(px -> ax), src=m2p[1](aa), dst=m2p[0](atom) into OA cols [100,200) ---
    run_gat(PX, AX, Wi_src, Wi_dst, ai_src, ai_dst, bi,
            m_aa, m_atom, EM2P, NAA, NATOM, nloop_i,
            HSB, OA, HCD, ALS, ALD, M, Z, V);

    // --- LN + elu over atom concat -> atom_h in OA ---
    run_ln(OA, abatch, ln_d_w, ln_d_b, NATOM, CNT, GSUM, GSQ);

    // --- aa intra: GAT(px -> px) into OP cols [0,100) ---
    run_gat(PX, PX, Wp, Wp, ap_src, ap_dst, bp,
            p_src_e, p_dst_e, EAA, NAA, NAA, NAA,
            HSB, OP, 0, ALS, ALD, M, Z, V);

    // --- aa inter: GAT(atom_h -> px), src=m2p[0](atom), dst=m2p[1](aa) into OP cols [100,200) ---
    run_gat(OA, PX, Wi_src, Wi_dst, ai_src, ai_dst, bi,
            m_atom, m_aa, EM2P, NATOM, NAA, nloop_i,
            HSA, OP, HCD, ALS, ALD, M, Z, V);

    // --- LN + elu over aa concat -> aa_h in OP ---
    run_ln(OP, pbatch, ln_p_w, ln_p_b, NAA, CNT, GSUM, GSQ);

    // --- SAG pool + graph sums ---
    run_sag(OA, a_src_e, a_dst_e, EATOM, abatch, pd_Wrel, pd_brel, pd_Wroot, DG, NATOM,
            T, R, AGG, SPRE, SGM, SGZ);
    run_sag(OP, p_src_e, p_dst_e, EAA, pbatch, pp_Wrel, pp_brel, pp_Wroot, PG, NAA,
            T, R, AGG, SPRE, SGM, SGZ);
}

// round 3
// speedup vs baseline: 1.0966x; 1.0966x over previous
#include <cuda_runtime.h>
#include <cuda_bf16.h>
#include <cstdint>

// ---------------- problem constants ----------------
#define NATOM 25600
#define NAA   204800
#define EATOM 102400
#define EAA   1024000
#define EM2P  512000
#define DIM   200
#define HCD   100
#define NB    512

// ---------------- scratch layout (floats) ----------------
static const long OFF_HSA   = 0;                        // 25600*100
static const long OFF_HSB   = OFF_HSA   + 2560000L;     // 204800*100
static const long OFF_ALS   = OFF_HSB   + 20480000L;    // 204800*2
static const long OFF_ALD   = OFF_ALS   + 409600L;      // 204800*2
static const long OFF_M     = OFF_ALD   + 409600L;      // 204800*2
static const long OFF_Z1    = OFF_M     + 409600L;      // 204800*2
static const long OFF_Z2    = OFF_Z1    + 409600L;      // 204800*2
static const long OFF_V     = OFF_Z2    + 409600L;      // 400 (pad 512)
static const long OFF_T     = OFF_V     + 512L;         // 204800
static const long OFF_R     = OFF_T     + 204800L;      // 204800
static const long OFF_AGG   = OFF_R     + 204800L;      // 204800
static const long OFF_SPREA = OFF_AGG   + 204800L;      // 25600  (atom)
static const long OFF_SPREP = OFF_SPREA + 25600L;       // 204800 (aa)
static const long OFF_SGMA  = OFF_SPREP + 204800L;      // 512
static const long OFF_SGZA  = OFF_SGMA  + 512L;         // 512
static const long OFF_SGMP  = OFF_SGZA  + 512L;         // 512
static const long OFF_SGZP  = OFF_SGMP  + 512L;         // 512
static const long OFF_CNT   = OFF_SGZP  + 512L;         // 512
static const long OFF_GSUM  = OFF_CNT   + 512L;         // 512
static const long OFF_GSQ   = OFF_GSUM  + 512L;         // 512
static const long SCRATCH_FLOATS = OFF_GSQ + 512L;

__device__ __align__(256) float g_scratch[SCRATCH_FLOATS];

// ---------------- device helpers ----------------
__device__ __forceinline__ float eluf(float x)  { return x > 0.f ? x : expm1f(x); }
__device__ __forceinline__ float lreluf(float x){ return x > 0.f ? x : 0.2f * x; }

__device__ __forceinline__ void atomicMaxF(float* a, float v) {
    if (v >= 0.f) atomicMax((int*)a, __float_as_int(v));
    else          atomicMin((unsigned int*)a, __float_as_uint(v));
}

__device__ __forceinline__ float warp_sum(float v) {
    #pragma unroll
    for (int o = 16; o > 0; o >>= 1) v += __shfl_down_sync(0xffffffffu, v, o);
    return v;
}

// ---------------- generic small kernels ----------------
__global__ void fill_k(float* p, float v, int n) {
    int i = blockIdx.x * blockDim.x + threadIdx.x;
    if (i < n) p[i] = v;
}

// ---------------- register-blocked GEMM ----------------
// Y[N,100] = elu?(X[N,200]) @ W[200,100]; ALS[n,h] = sum_c Y[n,h*50+c]*aflat[h*50+c]
// block: 200 threads = 8 row-groups (ty) x 25 col-groups (tx); 64 rows/block.
#define GEMM_SMEM (size_t)((20000 + 12800) * sizeof(float))
__global__ void __launch_bounds__(200, 1)
gemm2_k(const float* __restrict__ X, const float* __restrict__ W,
        float* __restrict__ Y, float* __restrict__ ALS,
        const float* __restrict__ aflat, int N, int do_elu) {
    extern __shared__ float sm[];
    float* Ws = sm;               // 200*100
    float* Xs = sm + 20000;       // [k][r] : 200*64
    __shared__ float als_part[64 * 2 * 25];

    int tid = threadIdx.x;
    int tx = tid % 25, ty = tid / 25;
    int row0 = blockIdx.x * 64;

    for (int i = tid; i < 5000; i += 200)
        ((float4*)Ws)[i] = ((const float4*)W)[i];

    for (int i = tid; i < 64 * 50; i += 200) {
        int r = i / 50, kq = i % 50;
        int row = row0 + r;
        float4 v = make_float4(0.f, 0.f, 0.f, 0.f);
        if (row < N) v = ((const float4*)(X + (size_t)row * DIM))[kq];
        if (do_elu) { v.x = eluf(v.x); v.y = eluf(v.y); v.z = eluf(v.z); v.w = eluf(v.w); }
        int kb = kq * 4;
        Xs[(kb + 0) * 64 + r] = v.x;
        Xs[(kb + 1) * 64 + r] = v.y;
        Xs[(kb + 2) * 64 + r] = v.z;
        Xs[(kb + 3) * 64 + r] = v.w;
    }
    __syncthreads();

    float acc[8][4];
    #pragma unroll
    for (int r = 0; r < 8; r++)
        #pragma unroll
        for (int c = 0; c < 4; c++) acc[r][c] = 0.f;

    const float* wp = Ws + 4 * tx;
    const float* xp = Xs + 8 * ty;

    #pragma unroll 4
    for (int k = 0; k < DIM; k++) {
        float4 w4 = *(const float4*)(wp + k * HCD);
        float4 xa = *(const float4*)(xp + k * 64);
        float4 xb = *(const float4*)(xp + k * 64 + 4);
        float xr[8] = {xa.x, xa.y, xa.z, xa.w, xb.x, xb.y, xb.z, xb.w};
        #pragma unroll
        for (int r = 0; r < 8; r++) {
            acc[r][0] += xr[r] * w4.x;
            acc[r][1] += xr[r] * w4.y;
            acc[r][2] += xr[r] * w4.z;
            acc[r][3] += xr[r] * w4.w;
        }
    }

    float af0 = aflat[4 * tx], af1 = aflat[4 * tx + 1],
          af2 = aflat[4 * tx + 2], af3 = aflat[4 * tx + 3];
    int c0 = 4 * tx;

    #pragma unroll
    for (int r = 0; r < 8; r++) {
        int lrow = 8 * ty + r;
        int row = row0 + lrow;
        float s0 = 0.f, s1 = 0.f;
        float p0 = acc[r][0] * af0, p1 = acc[r][1] * af1,
              p2 = acc[r][2] * af2, p3 = acc[r][3] * af3;
        if (c0 + 0 < 50) s0 += p0; else s1 += p0;
        if (c0 + 1 < 50) s0 += p1; else s1 += p1;
        if (c0 + 2 < 50) s0 += p2; else s1 += p2;
        if (c0 + 3 < 50) s0 += p3; else s1 += p3;
        als_part[lrow * 50 + tx]      = s0;
        als_part[lrow * 50 + 25 + tx] = s1;
        if (row < N)
            *(float4*)(Y + (size_t)row * HCD + c0) =
                make_float4(acc[r][0], acc[r][1], acc[r][2], acc[r][3]);
    }
    __syncthreads();

    if (tid < 128) {
        int r = tid >> 1, h = tid & 1;
        int row = row0 + r;
        if (row < N) {
            float s = 0.f;
            const float* pp = als_part + r * 50 + h * 25;
            #pragma unroll
            for (int i = 0; i < 25; i++) s += pp[i];
            ALS[(size_t)row * 2 + h] = s;
        }
    }
}

// ---------------- fold v[k,h] = sum_c Wdst[k, h*50+c] * adst[h,c] ----------------
__global__ void fold_v_k(const float* __restrict__ Wdst, const float* __restrict__ adst,
                         float* __restrict__ v) {
    int i = blockIdx.x * blockDim.x + threadIdx.x;
    if (i >= 2 * DIM) return;
    int k = i >> 1, h = i & 1;
    float s = 0.f;
    #pragma unroll
    for (int c = 0; c < 50; c++) s += Wdst[k * HCD + h * 50 + c] * adst[h * 50 + c];
    v[2 * k + h] = s;
}

// ---------------- ald[n,h] = elu?(X[n,:]) @ v[:,h], warp per node ----------------
__global__ void ald_k(const float* __restrict__ X, const float* __restrict__ v,
                      float* __restrict__ ald, int N, int do_elu) {
    int w = (blockIdx.x * blockDim.x + threadIdx.x) >> 5;
    int lane = threadIdx.x & 31;
    if (w >= N) return;
    const float* xr = X + (size_t)w * DIM;
    float a0 = 0.f, a1 = 0.f;
    for (int k = lane; k < DIM; k += 32) {
        float x = xr[k];
        if (do_elu) x = eluf(x);
        a0 += x * v[2 * k];
        a1 += x * v[2 * k + 1];
    }
    a0 = warp_sum(a0); a1 = warp_sum(a1);
    if (lane == 0) { ald[2 * w] = a0; ald[2 * w + 1] = a1; }
}

// ---------------- edge pass A: per-dst logit max ----------------
__global__ void edge_max_k(const int* __restrict__ src, const int* __restrict__ dst,
                           int E, int nloop,
                           const float* __restrict__ als, const float* __restrict__ ald,
                           float* __restrict__ m) {
    int e = blockIdx.x * blockDim.x + threadIdx.x;
    if (e >= E + nloop) return;
    int s, d;
    if (e < E) { s = src[e]; d = dst[e]; } else { s = e - E; d = e - E; }
    float l0 = lreluf(als[2 * s]     + ald[2 * d]);
    float l1 = lreluf(als[2 * s + 1] + ald[2 * d + 1]);
    atomicMaxF(&m[2 * d],     l0);
    atomicMaxF(&m[2 * d + 1], l1);
}

// ---------------- edge pass B: accumulate z and unnormalized out ----------------
__global__ void edge_acc_k(const int* __restrict__ src, const int* __restrict__ dst,
                           int E, int nloop,
                           const float* __restrict__ als, const float* __restrict__ ald,
                           const float* __restrict__ m, const float* __restrict__ hs,
                           float* __restrict__ z, float* __restrict__ out, int coloff) {
    int w = (blockIdx.x * blockDim.x + threadIdx.x) >> 5;
    int lane = threadIdx.x & 31;
    if (w >= E + nloop) return;
    int s, d;
    if (w < E) { s = src[w]; d = dst[w]; } else { s = w - E; d = w - E; }
    float e0 = __expf(lreluf(als[2 * s]     + ald[2 * d])     - m[2 * d]);
    float e1 = __expf(lreluf(als[2 * s + 1] + ald[2 * d + 1]) - m[2 * d + 1]);
    if (lane == 0) atomicAdd(&z[2 * d],     e0);
    if (lane == 1) atomicAdd(&z[2 * d + 1], e1);
    if (lane < 25) {
        int j = lane * 4;
        const float4 h4 = *(const float4*)(hs + (size_t)s * HCD + j);
        float w0 = (j     < 50 ? e0 : e1) * h4.x;
        float w1 = (j + 1 < 50 ? e0 : e1) * h4.y;
        float w2 = (j + 2 < 50 ? e0 : e1) * h4.z;
        float w3 = (j + 3 < 50 ? e0 : e1) * h4.w;
        float* p = out + (size_t)d * DIM + coloff + j;
        asm volatile("red.global.add.v4.f32 [%0], {%1,%2,%3,%4};"
                     :: "l"(p), "f"(w0), "f"(w1), "f"(w2), "f"(w3) : "memory");
    }
}

// ---------------- fused: gat finalize (virtual) + LN stats ----------------
__global__ void ln_stats_fused_k(const float* __restrict__ out,
                                 const float* __restrict__ z1, const float* __restrict__ z2,
                                 const float* __restrict__ b1, const float* __restrict__ b2,
                                 const int* __restrict__ batch,
                                 float* __restrict__ gsum, float* __restrict__ gsq, int N) {
    int n = (blockIdx.x * blockDim.x + threadIdx.x) >> 5;
    int lane = threadIdx.x & 31;
    if (n >= N) return;
    float iz10 = 1.f / (z1[2 * n] + 1e-16f),     iz11 = 1.f / (z1[2 * n + 1] + 1e-16f);
    float iz20 = 1.f / (z2[2 * n] + 1e-16f),     iz21 = 1.f / (z2[2 * n + 1] + 1e-16f);
    const float* xr = out + (size_t)n * DIM;
    float s = 0.f, q = 0.f;
    for (int j = lane; j < DIM; j += 32) {
        float val = xr[j], y;
        if (j < HCD) y = val * (j < 50 ? iz10 : iz11) + b1[j];
        else { int jj = j - HCD; y = val * (jj < 50 ? iz20 : iz21) + b2[jj]; }
        s += y; q += y * y;
    }
    s = warp_sum(s); q = warp_sum(q);
    if (lane == 0) {
        int g = batch[n];
        atomicAdd(&gsum[g], s);
        atomicAdd(&gsq[g], q);
    }
}

// ---------------- fused: finalize + LN apply + elu + SAG T/R dots ----------------
__global__ void ln_apply_fused_k(float* __restrict__ x,
                                 const float* __restrict__ z1, const float* __restrict__ z2,
                                 const float* __restrict__ b1, const float* __restrict__ b2,
                                 const int* __restrict__ batch,
                                 const float* __restrict__ cnt, const float* __restrict__ gsum,
                                 const float* __restrict__ gsq,
                                 const float* __restrict__ wv, const float* __restrict__ bv,
                                 const float* __restrict__ Wrel, const float* __restrict__ Wroot,
                                 float* __restrict__ T, float* __restrict__ R, int N) {
    int n = (blockIdx.x * blockDim.x + threadIdx.x) >> 5;
    int lane = threadIdx.x & 31;
    if (n >= N) return;
    int g = batch[n];
    float norm = fmaxf(cnt[g], 1.f) * (float)DIM;
    float mean = gsum[g] / norm;
    float var  = gsq[g] / norm - mean * mean;
    float rstd = rsqrtf(var + 1e-5f);
    float iz10 = 1.f / (z1[2 * n] + 1e-16f),     iz11 = 1.f / (z1[2 * n + 1] + 1e-16f);
    float iz20 = 1.f / (z2[2 * n] + 1e-16f),     iz21 = 1.f / (z2[2 * n + 1] + 1e-16f);
    float* xr = x + (size_t)n * DIM;
    float t = 0.f, r = 0.f;
    for (int j = lane; j < DIM; j += 32) {
        float val = xr[j], y;
        if (j < HCD) y = val * (j < 50 ? iz10 : iz11) + b1[j];
        else { int jj = j - HCD; y = val * (jj < 50 ? iz20 : iz21) + b2[jj]; }
        float e = eluf((y - mean) * rstd * wv[j] + bv[j]);
        xr[j] = e;
        t += e * Wrel[j];
        r += e * Wroot[j];
    }
    t = warp_sum(t); r = warp_sum(r);
    if (lane == 0) { T[n] = t; R[n] = r; }
}

// ---------------- per-graph node counts ----------------
__global__ void count_k(const int* __restrict__ batch, float* __restrict__ cnt, int N) {
    int i = blockIdx.x * blockDim.x + threadIdx.x;
    if (i < N) atomicAdd(&cnt[batch[i]], 1.f);
}

// ---------------- SAG pooling ----------------
__global__ void sag_edge_k(const int* __restrict__ src, const int* __restrict__ dst, int E,
                           const float* __restrict__ T, float* __restrict__ agg) {
    int e = blockIdx.x * blockDim.x + threadIdx.x;
    if (e < E) atomicAdd(&agg[dst[e]], T[src[e]]);
}

__global__ void sag_spre_k(const float* __restrict__ agg, const float* __restrict__ R,
                           const float* __restrict__ brel, const int* __restrict__ batch,
                           float* __restrict__ spre, float* __restrict__ sgm, int N) {
    int i = blockIdx.x * blockDim.x + threadIdx.x;
    if (i >= N) return;
    float s = agg[i] + brel[0] + R[i];
    spre[i] = s;
    atomicMaxF(&sgm[batch[i]], s);
}

__global__ void sag_z_k(const float* __restrict__ spre, const int* __restrict__ batch,
                        const float* __restrict__ sgm, float* __restrict__ sgz, int N) {
    int i = blockIdx.x * blockDim.x + threadIdx.x;
    if (i >= N) return;
    int g = batch[i];
    atomicAdd(&sgz[g], __expf(spre[i] - sgm[g]));
}

// thread per float4: scale x in place + vector-RED into per-graph sum
__global__ void sag_scale_k(float* __restrict__ x, const float* __restrict__ spre,
                            const float* __restrict__ sgm, const float* __restrict__ sgz,
                            const int* __restrict__ batch, float* __restrict__ G, int N) {
    long i = (long)blockIdx.x * blockDim.x + threadIdx.x;
    if (i >= (long)N * 50) return;
    int n = (int)(i / 50), q = (int)(i - (long)n * 50);
    int g = batch[n];
    float score = __expf(spre[n] - sgm[g]) / (sgz[g] + 1e-16f);
    float4 v = *(float4*)(x + (size_t)n * DIM + 4 * q);
    v.x *= score; v.y *= score; v.z *= score; v.w *= score;
    *(float4*)(x + (size_t)n * DIM + 4 * q) = v;
    float* p = G + (size_t)g * DIM + 4 * q;
    asm volatile("red.global.add.v4.f32 [%0], {%1,%2,%3,%4};"
                 :: "l"(p), "f"(v.x), "f"(v.y), "f"(v.z), "f"(v.w) : "memory");
}

// ---------------- host orchestration ----------------
static void run_gat(const float* Xsrc, const float* Xdst, int elu_src, int elu_dst,
                    const float* Wsrc, const float* Wdst,
                    const float* a_src, const float* a_dst,
                    const int* src, const int* dst, int E, int Ns, int Nd, int nloop,
                    float* HS, float* out, int coloff,
                    float* ALS, float* ALD, float* M, float* Z, float* V) {
    fill_k<<<(2 * Nd + 255) / 256, 256>>>(M, -1e30f, 2 * Nd);
    cudaMemsetAsync(Z, 0, (size_t)2 * Nd * sizeof(float));
    gemm2_k<<<(Ns + 63) / 64, 200, GEMM_SMEM>>>(Xsrc, Wsrc, HS, ALS, a_src, Ns, elu_src);
    fold_v_k<<<2, 256>>>(Wdst, a_dst, V);
    ald_k<<<(Nd * 32 + 255) / 256, 256>>>(Xdst, V, ALD, Nd, elu_dst);
    int tot = E + nloop;
    edge_max_k<<<(tot + 255) / 256, 256>>>(src, dst, E, nloop, ALS, ALD, M);
    edge_acc_k<<<((long)tot * 32 + 255) / 256, 256>>>(src, dst, E, nloop, ALS, ALD, M, HS, Z, out, coloff);
}

static void run_ln(float* x, const int* batch,
                   const float* z1, const float* z2,
                   const float* b1, const float* b2,
                   const float* lnw, const float* lnb,
                   const float* Wrel, const float* Wroot,
                   float* T, float* R, int N,
                   float* CNT, float* GSUM, float* GSQ) {
    cudaMemsetAsync(CNT,  0, NB * sizeof(float));
    cudaMemsetAsync(GSUM, 0, NB * sizeof(float));
    cudaMemsetAsync(GSQ,  0, NB * sizeof(float));
    count_k<<<(N + 255) / 256, 256>>>(batch, CNT, N);
    ln_stats_fused_k<<<(N * 32 + 255) / 256, 256>>>(x, z1, z2, b1, b2, batch, GSUM, GSQ, N);
    ln_apply_fused_k<<<(N * 32 + 255) / 256, 256>>>(x, z1, z2, b1, b2, batch, CNT, GSUM, GSQ,
                                                    lnw, lnb, Wrel, Wroot, T, R, N);
}

// SAG scalar phase: per-node score pre-activations + per-graph softmax scalars.
// Does NOT touch x — the in-place scaling is a separate deferred launch.
static void run_sag_scalars(const int* src, const int* dst, int E, const int* batch,
                            const float* brel, const float* T, const float* R,
                            float* AGG, float* SPRE, float* SGM, float* SGZ, int N) {
    cudaMemsetAsync(AGG, 0, (size_t)N * sizeof(float));
    fill_k<<<(NB + 255) / 256, 256>>>(SGM, -1e30f, NB);
    cudaMemsetAsync(SGZ, 0, NB * sizeof(float));
    sag_edge_k<<<(E + 255) / 256, 256>>>(src, dst, E, T, AGG);
    sag_spre_k<<<(N + 255) / 256, 256>>>(AGG, R, brel, batch, SPRE, SGM, N);
    sag_z_k<<<(N + 255) / 256, 256>>>(SPRE, batch, SGM, SGZ, N);
}

extern "C" void kernel_launch(void* const* d_in, const int* in_sizes, int n_in,
                              void* d_out, int out_size) {
    const float* atom_x  = (const float*)d_in[0];
    const int*   aei     = (const int*)  d_in[1];
    const int*   abatch  = (const int*)  d_in[2];
    const float* aa_x    = (const float*)d_in[3];
    const int*   pei     = (const int*)  d_in[4];
    // d_in[5] = aa_edge_attr (unused by reference)
    const int*   pbatch  = (const int*)  d_in[6];
    const int*   m2p     = (const int*)  d_in[7];
    const float* Wd      = (const float*)d_in[8];
    const float* ad_src  = (const float*)d_in[9];
    const float* ad_dst  = (const float*)d_in[10];
    const float* bd      = (const float*)d_in[11];
    const float* Wp      = (const float*)d_in[12];
    const float* ap_src  = (const float*)d_in[13];
    const float* ap_dst  = (const float*)d_in[14];
    const float* bp      = (const float*)d_in[15];
    const float* Wi_src  = (const float*)d_in[16];
    const float* Wi_dst  = (const float*)d_in[17];
    const float* ai_src  = (const float*)d_in[18];
    const float* ai_dst  = (const float*)d_in[19];
    const float* bi      = (const float*)d_in[20];
    const float* ln_d_w  = (const float*)d_in[21];
    const float* ln_d_b  = (const float*)d_in[22];
    const float* ln_p_w  = (const float*)d_in[23];
    const float* ln_p_b  = (const float*)d_in[24];
    const float* pd_Wrel = (const float*)d_in[25];
    const float* pd_brel = (const float*)d_in[26];
    const float* pd_Wroot= (const float*)d_in[27];
    const float* pp_Wrel = (const float*)d_in[28];
    const float* pp_brel = (const float*)d_in[29];
    const float* pp_Wroot= (const float*)d_in[30];

    cudaFuncSetAttribute(gemm2_k, cudaFuncAttributeMaxDynamicSharedMemorySize, (int)GEMM_SMEM);

    float* S = nullptr;
    cudaGetSymbolAddress((void**)&S, g_scratch);

    float* HSA   = S + OFF_HSA;
    float* HSB   = S + OFF_HSB;
    float* ALS   = S + OFF_ALS;
    float* ALD   = S + OFF_ALD;
    float* M     = S + OFF_M;
    float* Z1    = S + OFF_Z1;
    float* Z2    = S + OFF_Z2;
    float* V     = S + OFF_V;
    float* T     = S + OFF_T;
    float* R     = S + OFF_R;
    float* AGG   = S + OFF_AGG;
    float* SPREA = S + OFF_SPREA;
    float* SPREP = S + OFF_SPREP;
    float* SGMA  = S + OFF_SGMA;
    float* SGZA  = S + OFF_SGZA;
    float* SGMP  = S + OFF_SGMP;
    float* SGZP  = S + OFF_SGZP;
    float* CNT   = S + OFF_CNT;
    float* GSUM  = S + OFF_GSUM;
    float* GSQ   = S + OFF_GSQ;

    float* out = (float*)d_out;
    float* OA  = out;                                  // atom_h -> atom_out [25600,200]
    float* OP  = out + (size_t)NATOM * DIM;            // aa_h -> aa_out    [204800,200]
    float* DG  = out + (size_t)(NATOM + NAA) * DIM;    // drug_g [512,200]
    float* PG  = DG + (size_t)NB * DIM;                // prot_g [512,200]

    cudaMemsetAsync(d_out, 0, (size_t)out_size * sizeof(float));

    const int* a_src_e = aei;
    const int* a_dst_e = aei + EATOM;
    const int* p_src_e = pei;
    const int* p_dst_e = pei + EAA;
    const int* m_atom  = m2p;
    const int* m_aa    = m2p + EM2P;
    const int  nloop_i = NATOM;   // min(NATOM, NAA)

    // 1) atom intra: GAT(elu(atom_x) -> elu(atom_x)) into OA[:,0:100), z->Z1
    run_gat(atom_x, atom_x, 1, 1, Wd, Wd, ad_src, ad_dst,
            a_src_e, a_dst_e, EATOM, NATOM, NATOM, NATOM,
            HSA, OA, 0, ALS, ALD, M, Z1, V);

    // 2) atom inter: GAT(elu(aa_x) -> elu(atom_x)) into OA[:,100:200), z->Z2
    run_gat(aa_x, atom_x, 1, 1, Wi_src, Wi_dst, ai_src, ai_dst,
            m_aa, m_atom, EM2P, NAA, NATOM, nloop_i,
            HSB, OA, HCD, ALS, ALD, M, Z2, V);

    // 3) atom LN (finalize fused) -> atom_h in OA, SAG dots T/R
    run_ln(OA, abatch, Z1, Z2, bd, bi, ln_d_w, ln_d_b,
           pd_Wrel, pd_Wroot, T, R, NATOM, CNT, GSUM, GSQ);

    // 4) atom SAG scalars (doesn't modify OA)
    run_sag_scalars(a_src_e, a_dst_e, EATOM, abatch, pd_brel, T, R,
                    AGG, SPREA, SGMA, SGZA, NATOM);

    // 5) aa intra: GAT(elu(aa_x) -> elu(aa_x)) into OP[:,0:100), z->Z1
    run_gat(aa_x, aa_x, 1, 1, Wp, Wp, ap_src, ap_dst,
            p_src_e, p_dst_e, EAA, NAA, NAA, NAA,
            HSB, OP, 0, ALS, ALD, M, Z1, V);

    // 6) aa inter: GAT(atom_h -> elu(aa_x)) into OP[:,100:200), z->Z2
    //    (consumes OA = atom_h BEFORE it gets scaled into atom_out)
    run_gat(OA, aa_x, 0, 1, Wi_src, Wi_dst, ai_src, ai_dst,
            m_atom, m_aa, EM2P, NATOM, NAA, nloop_i,
            HSA, OP, HCD, ALS, ALD, M, Z2, V);

    // 7) DEFERRED atom SAG scale: OA -> atom_out (in place), accumulate drug_g
    sag_scale_k<<<((long)NATOM * 50 + 255) / 256, 256>>>(OA, SPREA, SGMA, SGZA, abatch, DG, NATOM);

    // 8) aa LN (finalize fused) -> aa_h in OP, SAG dots T/R
    run_ln(OP, pbatch, Z1, Z2, bp, bi, ln_p_w, ln_p_b,
           pp_Wrel, pp_Wroot, T, R, NAA, CNT, GSUM, GSQ);

    // 9) aa SAG scalars + scale -> aa_out, prot_g
    run_sag_scalars(p_src_e, p_dst_e, EAA, pbatch, pp_brel, T, R,
                    AGG, SPREP, SGMP, SGZP, NAA);
    sag_scale_k<<<((long)NAA * 50 + 255) / 256, 256>>>(OP, SPREP, SGMP, SGZP, pbatch, PG, NAA);
}

// round 4
// speedup vs baseline: 1.2750x; 1.1627x over previous
#include <cuda_runtime.h>
#include <cuda_bf16.h>
#include <cstdint>

// ---------------- problem constants ----------------
#define NATOM 25600
#define NAA   204800
#define EATOM 102400
#define EAA   1024000
#define EM2P  512000
#define DIM   200
#define HCD   100
#define NB    512

// ---------------- scratch layout (floats) ----------------
static const long OFF_HSA   = 0;                        // 25600*100
static const long OFF_HSB   = OFF_HSA   + 2560000L;     // 204800*100
static const long OFF_ALS1  = OFF_HSB   + 20480000L;    // 204800*2
static const long OFF_ALD1  = OFF_ALS1  + 409600L;      // 204800*2
static const long OFF_ALS2  = OFF_ALD1  + 409600L;      // 204800*2
static const long OFF_ALD2  = OFF_ALS2  + 409600L;      // 204800*2
static const long OFF_Z1    = OFF_ALD2  + 409600L;      // 204800*2
static const long OFF_Z2    = OFF_Z1    + 409600L;      // 204800*2  (Z1,Z2 contiguous)
static const long OFF_V     = OFF_Z2    + 409600L;      // 400 pad 512
static const long OFF_T     = OFF_V     + 512L;         // 204800
static const long OFF_R     = OFF_T     + 204800L;      // 204800
static const long OFF_AGG   = OFF_R     + 204800L;      // 204800
static const long OFF_SPREA = OFF_AGG   + 204800L;      // 25600
static const long OFF_SPREP = OFF_SPREA + 25600L;       // 204800
static const long OFF_SGMA  = OFF_SPREP + 204800L;      // 512
static const long OFF_SGZA  = OFF_SGMA  + 512L;         // 512
static const long OFF_SGMP  = OFF_SGZA  + 512L;         // 512
static const long OFF_SGZP  = OFF_SGMP  + 512L;         // 512
static const long OFF_CNT   = OFF_SGZP  + 512L;         // 512  (CNT,GSUM,GSQ contiguous)
static const long OFF_GSUM  = OFF_CNT   + 512L;         // 512
static const long OFF_GSQ   = OFF_GSUM  + 512L;         // 512
static const long SCRATCH_FLOATS = OFF_GSQ + 512L;

__device__ __align__(256) float g_scratch[SCRATCH_FLOATS];

// ---------------- device helpers ----------------
__device__ __forceinline__ float eluf(float x)  { return x > 0.f ? x : expm1f(x); }
__device__ __forceinline__ float lreluf(float x){ return x > 0.f ? x : 0.2f * x; }

__device__ __forceinline__ void atomicMaxF(float* a, float v) {
    if (v >= 0.f) atomicMax((int*)a, __float_as_int(v));
    else          atomicMin((unsigned int*)a, __float_as_uint(v));
}

__device__ __forceinline__ float warp_sum(float v) {
    #pragma unroll
    for (int o = 16; o > 0; o >>= 1) v += __shfl_down_sync(0xffffffffu, v, o);
    return v;
}

// ---------------- generic small kernels ----------------
__global__ void fill_k(float* p, float v, int n) {
    int i = blockIdx.x * blockDim.x + threadIdx.x;
    if (i < n) p[i] = v;
}

// ---------------- register-blocked GEMM with dual attention-dot epilogue -----
// Y[N,100] = elu?(X[N,200]) @ W[200,100]
// ALS[n,h] = sum_c Y[n,h*50+c]*a_src[h*50+c]
// ALD[n,h] = sum_c Y[n,h*50+c]*a_dst[h*50+c]   (only if ALD != nullptr)
// block: 200 threads = 8 row-groups (ty) x 25 col-groups (tx); 64 rows/block.
#define GEMM_SMEM (size_t)((20000 + 12800) * sizeof(float))
__global__ void __launch_bounds__(200, 1)
gemm2_k(const float* __restrict__ X, const float* __restrict__ W,
        float* __restrict__ Y, float* __restrict__ ALS,
        const float* __restrict__ a_src, const float* __restrict__ a_dst,
        float* __restrict__ ALD, int N, int do_elu) {
    extern __shared__ float sm[];
    float* Ws = sm;               // 200*100
    float* Xs = sm + 20000;       // [k][r] : 200*64
    __shared__ float part_s[3200];   // [row][head][tx]
    __shared__ float part_d[3200];

    int tid = threadIdx.x;
    int tx = tid % 25, ty = tid / 25;
    int row0 = blockIdx.x * 64;

    for (int i = tid; i < 5000; i += 200)
        ((float4*)Ws)[i] = ((const float4*)W)[i];

    for (int i = tid; i < 64 * 50; i += 200) {
        int r = i / 50, kq = i % 50;
        int row = row0 + r;
        float4 v = make_float4(0.f, 0.f, 0.f, 0.f);
        if (row < N) v = ((const float4*)(X + (size_t)row * DIM))[kq];
        if (do_elu) { v.x = eluf(v.x); v.y = eluf(v.y); v.z = eluf(v.z); v.w = eluf(v.w); }
        int kb = kq * 4;
        Xs[(kb + 0) * 64 + r] = v.x;
        Xs[(kb + 1) * 64 + r] = v.y;
        Xs[(kb + 2) * 64 + r] = v.z;
        Xs[(kb + 3) * 64 + r] = v.w;
    }
    __syncthreads();

    float acc[8][4];
    #pragma unroll
    for (int r = 0; r < 8; r++)
        #pragma unroll
        for (int c = 0; c < 4; c++) acc[r][c] = 0.f;

    const float* wp = Ws + 4 * tx;
    const float* xp = Xs + 8 * ty;

    #pragma unroll 4
    for (int k = 0; k < DIM; k++) {
        float4 w4 = *(const float4*)(wp + k * HCD);
        float4 xa = *(const float4*)(xp + k * 64);
        float4 xb = *(const float4*)(xp + k * 64 + 4);
        float xr[8] = {xa.x, xa.y, xa.z, xa.w, xb.x, xb.y, xb.z, xb.w};
        #pragma unroll
        for (int r = 0; r < 8; r++) {
            acc[r][0] += xr[r] * w4.x;
            acc[r][1] += xr[r] * w4.y;
            acc[r][2] += xr[r] * w4.z;
            acc[r][3] += xr[r] * w4.w;
        }
    }

    int c0 = 4 * tx;
    float4 af = *(const float4*)(a_src + c0);
    float4 bf = ALD ? *(const float4*)(a_dst + c0) : make_float4(0.f,0.f,0.f,0.f);

    #pragma unroll
    for (int r = 0; r < 8; r++) {
        int lrow = 8 * ty + r;
        int row = row0 + lrow;
        float s0 = 0.f, s1 = 0.f, t0 = 0.f, t1 = 0.f;
        float ps[4] = {acc[r][0]*af.x, acc[r][1]*af.y, acc[r][2]*af.z, acc[r][3]*af.w};
        float pd[4] = {acc[r][0]*bf.x, acc[r][1]*bf.y, acc[r][2]*bf.z, acc[r][3]*bf.w};
        #pragma unroll
        for (int q = 0; q < 4; q++) {
            if (c0 + q < 50) { s0 += ps[q]; t0 += pd[q]; }
            else             { s1 += ps[q]; t1 += pd[q]; }
        }
        part_s[lrow * 50 + tx]      = s0;
        part_s[lrow * 50 + 25 + tx] = s1;
        part_d[lrow * 50 + tx]      = t0;
        part_d[lrow * 50 + 25 + tx] = t1;
        if (row < N)
            *(float4*)(Y + (size_t)row * HCD + c0) =
                make_float4(acc[r][0], acc[r][1], acc[r][2], acc[r][3]);
    }
    __syncthreads();

    if (tid < 128) {
        int r = tid >> 1, h = tid & 1;
        int row = row0 + r;
        if (row < N) {
            float s = 0.f, t = 0.f;
            const float* ps = part_s + r * 50 + h * 25;
            const float* pd = part_d + r * 50 + h * 25;
            #pragma unroll
            for (int i = 0; i < 25; i++) { s += ps[i]; t += pd[i]; }
            ALS[(size_t)row * 2 + h] = s;
            if (ALD) ALD[(size_t)row * 2 + h] = t;
        }
    }
}

// ---------------- fold v[k,h] = sum_c Wdst[k, h*50+c] * adst[h,c] ----------------
__global__ void fold_v_k(const float* __restrict__ Wdst, const float* __restrict__ adst,
                         float* __restrict__ v) {
    int i = blockIdx.x * blockDim.x + threadIdx.x;
    if (i >= 2 * DIM) return;
    int k = i >> 1, h = i & 1;
    float s = 0.f;
    #pragma unroll
    for (int c = 0; c < 50; c++) s += Wdst[k * HCD + h * 50 + c] * adst[h * 50 + c];
    v[2 * k + h] = s;
}

// ---------------- ald[n,h] = elu?(X[n,:]) @ v[:,h]  (float4, warp/node) ----------
__global__ void ald_vec_k(const float* __restrict__ X, const float* __restrict__ v,
                          float* __restrict__ ald, int N, int do_elu) {
    int n = (blockIdx.x * blockDim.x + threadIdx.x) >> 5;
    int lane = threadIdx.x & 31;
    if (n >= N) return;
    const float4* xr = (const float4*)(X + (size_t)n * DIM);
    const float4* v4 = (const float4*)v;
    float a0 = 0.f, a1 = 0.f;
    #pragma unroll
    for (int c = lane; c < 50; c += 32) {
        float4 x = xr[c];
        if (do_elu) { x.x = eluf(x.x); x.y = eluf(x.y); x.z = eluf(x.z); x.w = eluf(x.w); }
        float4 va = v4[2 * c];       // k=4c,4c+1 (h0,h1 interleaved)
        float4 vb = v4[2 * c + 1];   // k=4c+2,4c+3
        a0 += x.x * va.x + x.y * va.z + x.z * vb.x + x.w * vb.z;
        a1 += x.x * va.y + x.y * va.w + x.z * vb.y + x.w * vb.w;
    }
    a0 = warp_sum(a0); a1 = warp_sum(a1);
    if (lane == 0) ((float2*)ald)[n] = make_float2(a0, a1);
}

// ---------------- edge pass: accumulate z and unnormalized out (no max) -------
__global__ void edge_acc_k(const int* __restrict__ src, const int* __restrict__ dst,
                           int E, int nloop,
                           const float* __restrict__ als, const float* __restrict__ ald,
                           const float* __restrict__ hs,
                           float* __restrict__ z, float* __restrict__ out, int coloff) {
    int w = (blockIdx.x * blockDim.x + threadIdx.x) >> 5;
    int lane = threadIdx.x & 31;
    if (w >= E + nloop) return;
    int s, d;
    if (w < E) { s = src[w]; d = dst[w]; } else { s = w - E; d = w - E; }
    float2 as = ((const float2*)als)[s];
    float2 ad = ((const float2*)ald)[d];
    float e0 = __expf(lreluf(as.x + ad.x));
    float e1 = __expf(lreluf(as.y + ad.y));
    if (lane == 25) atomicAdd(&z[2 * d],     e0);
    if (lane == 26) atomicAdd(&z[2 * d + 1], e1);
    if (lane < 25) {
        int j = lane * 4;
        const float4 h4 = *(const float4*)(hs + (size_t)s * HCD + j);
        float w0 = (j     < 50 ? e0 : e1) * h4.x;
        float w1 = (j + 1 < 50 ? e0 : e1) * h4.y;
        float w2 = (j + 2 < 50 ? e0 : e1) * h4.z;
        float w3 = (j + 3 < 50 ? e0 : e1) * h4.w;
        float* p = out + (size_t)d * DIM + coloff + j;
        asm volatile("red.global.add.v4.f32 [%0], {%1,%2,%3,%4};"
                     :: "l"(p), "f"(w0), "f"(w1), "f"(w2), "f"(w3) : "memory");
    }
}

// ---------------- fused: finalize (virtual) + LN stats + graph counts ---------
__global__ void ln_stats_fused_k(const float* __restrict__ out,
                                 const float* __restrict__ z1, const float* __restrict__ z2,
                                 const float* __restrict__ b1, const float* __restrict__ b2,
                                 const int* __restrict__ batch,
                                 float* __restrict__ cnt,
                                 float* __restrict__ gsum, float* __restrict__ gsq, int N) {
    int n = (blockIdx.x * blockDim.x + threadIdx.x) >> 5;
    int lane = threadIdx.x & 31;
    if (n >= N) return;
    float2 zz1 = ((const float2*)z1)[n];
    float2 zz2 = ((const float2*)z2)[n];
    float iz10 = 1.f / (zz1.x + 1e-16f), iz11 = 1.f / (zz1.y + 1e-16f);
    float iz20 = 1.f / (zz2.x + 1e-16f), iz21 = 1.f / (zz2.y + 1e-16f);
    const float4* xr = (const float4*)(out + (size_t)n * DIM);
    float s = 0.f, q = 0.f;
    #pragma unroll
    for (int c = lane; c < 50; c += 32) {
        float4 val = xr[c];
        int j = 4 * c;
        float4 b = (c < 25) ? ((const float4*)b1)[c] : ((const float4*)b2)[c - 25];
        float izA, izB;
        if (c < 25) { izA = iz10; izB = iz11; } else { izA = iz20; izB = iz21; }
        int jj = (c < 25) ? j : j - 100;
        float y0 = val.x * (jj     < 50 ? izA : izB) + b.x;
        float y1 = val.y * (jj + 1 < 50 ? izA : izB) + b.y;
        float y2 = val.z * (jj + 2 < 50 ? izA : izB) + b.z;
        float y3 = val.w * (jj + 3 < 50 ? izA : izB) + b.w;
        s += y0 + y1 + y2 + y3;
        q += y0*y0 + y1*y1 + y2*y2 + y3*y3;
    }
    s = warp_sum(s); q = warp_sum(q);
    if (lane == 0) {
        int g = batch[n];
        atomicAdd(&cnt[g], 1.f);
        atomicAdd(&gsum[g], s);
        atomicAdd(&gsq[g], q);
    }
}

// ---------------- fused: finalize + LN apply + elu + SAG T/R dots -------------
__global__ void ln_apply_fused_k(float* __restrict__ x,
                                 const float* __restrict__ z1, const float* __restrict__ z2,
                                 const float* __restrict__ b1, const float* __restrict__ b2,
                                 const int* __restrict__ batch,
                                 const float* __restrict__ cnt, const float* __restrict__ gsum,
                                 const float* __restrict__ gsq,
                                 const float* __restrict__ wv, const float* __restrict__ bv,
                                 const float* __restrict__ Wrel, const float* __restrict__ Wroot,
                                 float* __restrict__ T, float* __restrict__ R, int N) {
    int n = (blockIdx.x * blockDim.x + threadIdx.x) >> 5;
    int lane = threadIdx.x & 31;
    if (n >= N) return;
    int g = batch[n];
    float norm = fmaxf(cnt[g], 1.f) * (float)DIM;
    float mean = gsum[g] / norm;
    float var  = gsq[g] / norm - mean * mean;
    float rstd = rsqrtf(var + 1e-5f);
    float2 zz1 = ((const float2*)z1)[n];
    float2 zz2 = ((const float2*)z2)[n];
    float iz10 = 1.f / (zz1.x + 1e-16f), iz11 = 1.f / (zz1.y + 1e-16f);
    float iz20 = 1.f / (zz2.x + 1e-16f), iz21 = 1.f / (zz2.y + 1e-16f);
    float4* xr = (float4*)(x + (size_t)n * DIM);
    float t = 0.f, r = 0.f;
    #pragma unroll
    for (int c = lane; c < 50; c += 32) {
        float4 val = xr[c];
        int j = 4 * c;
        float4 b = (c < 25) ? ((const float4*)b1)[c] : ((const float4*)b2)[c - 25];
        float izA, izB;
        if (c < 25) { izA = iz10; izB = iz11; } else { izA = iz20; izB = iz21; }
        int jj = (c < 25) ? j : j - 100;
        float4 w4 = ((const float4*)wv)[c];
        float4 bb = ((const float4*)bv)[c];
        float4 wr = ((const float4*)Wrel)[c];
        float4 wo = ((const float4*)Wroot)[c];
        float y0 = val.x * (jj     < 50 ? izA : izB) + b.x;
        float y1 = val.y * (jj + 1 < 50 ? izA : izB) + b.y;
        float y2 = val.z * (jj + 2 < 50 ? izA : izB) + b.z;
        float y3 = val.w * (jj + 3 < 50 ? izA : izB) + b.w;
        float e0 = eluf((y0 - mean) * rstd * w4.x + bb.x);
        float e1 = eluf((y1 - mean) * rstd * w4.y + bb.y);
        float e2 = eluf((y2 - mean) * rstd * w4.z + bb.z);
        float e3 = eluf((y3 - mean) * rstd * w4.w + bb.w);
        xr[c] = make_float4(e0, e1, e2, e3);
        t += e0*wr.x + e1*wr.y + e2*wr.z + e3*wr.w;
        r += e0*wo.x + e1*wo.y + e2*wo.z + e3*wo.w;
    }
    t = warp_sum(t); r = warp_sum(r);
    if (lane == 0) { T[n] = t; R[n] = r; }
}

// ---------------- SAG pooling ----------------
__global__ void sag_edge_k(const int* __restrict__ src, const int* __restrict__ dst, int E,
                           const float* __restrict__ T, float* __restrict__ agg) {
    int e = blockIdx.x * blockDim.x + threadIdx.x;
    if (e < E) atomicAdd(&agg[dst[e]], T[src[e]]);
}

__global__ void sag_spre_k(const float* __restrict__ agg, const float* __restrict__ R,
                           const float* __restrict__ brel, const int* __restrict__ batch,
                           float* __restrict__ spre, float* __restrict__ sgm, int N) {
    int i = blockIdx.x * blockDim.x + threadIdx.x;
    if (i >= N) return;
    float s = agg[i] + brel[0] + R[i];
    spre[i] = s;
    atomicMaxF(&sgm[batch[i]], s);
}

__global__ void sag_z_k(const float* __restrict__ spre, const int* __restrict__ batch,
                        const float* __restrict__ sgm, float* __restrict__ sgz, int N) {
    int i = blockIdx.x * blockDim.x + threadIdx.x;
    if (i >= N) return;
    int g = batch[i];
    atomicAdd(&sgz[g], __expf(spre[i] - sgm[g]));
}

__global__ void sag_scale_k(float* __restrict__ x, const float* __restrict__ spre,
                            const float* __restrict__ sgm, const float* __restrict__ sgz,
                            const int* __restrict__ batch, float* __restrict__ G, int N) {
    long i = (long)blockIdx.x * blockDim.x + threadIdx.x;
    if (i >= (long)N * 50) return;
    int n = (int)(i / 50), q = (int)(i - (long)n * 50);
    int g = batch[n];
    float score = __expf(spre[n] - sgm[g]) / (sgz[g] + 1e-16f);
    float4 v = *(float4*)(x + (size_t)n * DIM + 4 * q);
    v.x *= score; v.y *= score; v.z *= score; v.w *= score;
    *(float4*)(x + (size_t)n * DIM + 4 * q) = v;
    float* p = G + (size_t)g * DIM + 4 * q;
    asm volatile("red.global.add.v4.f32 [%0], {%1,%2,%3,%4};"
                 :: "l"(p), "f"(v.x), "f"(v.y), "f"(v.z), "f"(v.w) : "memory");
}

// ---------------- host orchestration ----------------
static void launch_edge_acc(const int* src, const int* dst, int E, int nloop,
                            const float* ALS, const float* ALD, const float* HS,
                            float* Z, float* out, int coloff) {
    long tot = (long)E + nloop;
    edge_acc_k<<<(tot * 32 + 255) / 256, 256>>>(src, dst, E, nloop, ALS, ALD, HS, Z, out, coloff);
}

static void run_ln(float* x, const int* batch,
                   const float* z1, const float* z2,
                   const float* b1, const float* b2,
                   const float* lnw, const float* lnb,
                   const float* Wrel, const float* Wroot,
                   float* T, float* R, int N, float* CNT) {
    // CNT, GSUM, GSQ contiguous
    cudaMemsetAsync(CNT, 0, 3 * NB * sizeof(float));
    ln_stats_fused_k<<<(N * 32 + 255) / 256, 256>>>(x, z1, z2, b1, b2, batch,
                                                    CNT, CNT + NB, CNT + 2 * NB, N);
    ln_apply_fused_k<<<(N * 32 + 255) / 256, 256>>>(x, z1, z2, b1, b2, batch,
                                                    CNT, CNT + NB, CNT + 2 * NB,
                                                    lnw, lnb, Wrel, Wroot, T, R, N);
}

static void run_sag_scalars(const int* src, const int* dst, int E, const int* batch,
                            const float* brel, const float* T, const float* R,
                            float* AGG, float* SPRE, float* SGM, float* SGZ, int N) {
    cudaMemsetAsync(AGG, 0, (size_t)N * sizeof(float));
    fill_k<<<(NB + 255) / 256, 256>>>(SGM, -1e30f, NB);
    cudaMemsetAsync(SGZ, 0, NB * sizeof(float));
    sag_edge_k<<<(E + 255) / 256, 256>>>(src, dst, E, T, AGG);
    sag_spre_k<<<(N + 255) / 256, 256>>>(AGG, R, brel, batch, SPRE, SGM, N);
    sag_z_k<<<(N + 255) / 256, 256>>>(SPRE, batch, SGM, SGZ, N);
}

extern "C" void kernel_launch(void* const* d_in, const int* in_sizes, int n_in,
                              void* d_out, int out_size) {
    const float* atom_x  = (const float*)d_in[0];
    const int*   aei     = (const int*)  d_in[1];
    const int*   abatch  = (const int*)  d_in[2];
    const float* aa_x    = (const float*)d_in[3];
    const int*   pei     = (const int*)  d_in[4];
    // d_in[5] = aa_edge_attr (unused by reference)
    const int*   pbatch  = (const int*)  d_in[6];
    const int*   m2p     = (const int*)  d_in[7];
    const float* Wd      = (const float*)d_in[8];
    const float* ad_src  = (const float*)d_in[9];
    const float* ad_dst  = (const float*)d_in[10];
    const float* bd      = (const float*)d_in[11];
    const float* Wp      = (const float*)d_in[12];
    const float* ap_src  = (const float*)d_in[13];
    const float* ap_dst  = (const float*)d_in[14];
    const float* bp      = (const float*)d_in[15];
    const float* Wi_src  = (const float*)d_in[16];
    const float* Wi_dst  = (const float*)d_in[17];
    const float* ai_src  = (const float*)d_in[18];
    const float* ai_dst  = (const float*)d_in[19];
    const float* bi      = (const float*)d_in[20];
    const float* ln_d_w  = (const float*)d_in[21];
    const float* ln_d_b  = (const float*)d_in[22];
    const float* ln_p_w  = (const float*)d_in[23];
    const float* ln_p_b  = (const float*)d_in[24];
    const float* pd_Wrel = (const float*)d_in[25];
    const float* pd_brel = (const float*)d_in[26];
    const float* pd_Wroot= (const float*)d_in[27];
    const float* pp_Wrel = (const float*)d_in[28];
    const float* pp_brel = (const float*)d_in[29];
    const float* pp_Wroot= (const float*)d_in[30];

    cudaFuncSetAttribute(gemm2_k, cudaFuncAttributeMaxDynamicSharedMemorySize, (int)GEMM_SMEM);

    float* S = nullptr;
    cudaGetSymbolAddress((void**)&S, g_scratch);

    float* HSA   = S + OFF_HSA;
    float* HSB   = S + OFF_HSB;
    float* ALS1  = S + OFF_ALS1;
    float* ALD1  = S + OFF_ALD1;
    float* ALS2  = S + OFF_ALS2;
    float* ALD2  = S + OFF_ALD2;
    float* Z1    = S + OFF_Z1;
    float* Z2    = S + OFF_Z2;
    float* V     = S + OFF_V;
    float* T     = S + OFF_T;
    float* R     = S + OFF_R;
    float* AGG   = S + OFF_AGG;
    float* SPREA = S + OFF_SPREA;
    float* SPREP = S + OFF_SPREP;
    float* SGMA  = S + OFF_SGMA;
    float* SGZA  = S + OFF_SGZA;
    float* SGMP  = S + OFF_SGMP;
    float* SGZP  = S + OFF_SGZP;
    float* CNT   = S + OFF_CNT;

    float* out = (float*)d_out;
    float* OA  = out;                                  // atom_h -> atom_out [25600,200]
    float* OP  = out + (size_t)NATOM * DIM;            // aa_h -> aa_out    [204800,200]
    float* DG  = out + (size_t)(NATOM + NAA) * DIM;    // drug_g [512,200]
    float* PG  = DG + (size_t)NB * DIM;                // prot_g [512,200]

    cudaMemsetAsync(d_out, 0, (size_t)out_size * sizeof(float));

    const int* a_src_e = aei;
    const int* a_dst_e = aei + EATOM;
    const int* p_src_e = pei;
    const int* p_dst_e = pei + EAA;
    const int* m_atom  = m2p;
    const int* m_aa    = m2p + EM2P;
    const int  nloop_i = NATOM;   // min(NATOM, NAA)

    // shared inter-GAT dst fold: v = Wi_dst @ ai_dst (same for both directions)
    fold_v_k<<<2, 256>>>(Wi_dst, ai_dst, V);

    // ============ atom phase ============
    cudaMemsetAsync(Z1, 0, 2 * 2 * NAA * sizeof(float) / 2);  // Z1+Z2 contiguous: 4*NAA? no:
    // Z1,Z2 each 2*NAA floats, contiguous:
    cudaMemsetAsync(Z1, 0, (size_t)4 * NAA * sizeof(float));

    // intra: hs + ALS1 + ALD1 (dual epilogue, hd == hs)
    gemm2_k<<<(NATOM + 63) / 64, 200, GEMM_SMEM>>>(atom_x, Wd, HSA, ALS1, ad_src, ad_dst, ALD1, NATOM, 1);
    // inter src (aa): hs + ALS2
    gemm2_k<<<(NAA + 63) / 64, 200, GEMM_SMEM>>>(aa_x, Wi_src, HSB, ALS2, ai_src, ai_dst, nullptr, NAA, 1);
    // inter dst (atom): ALD2
    ald_vec_k<<<(NATOM * 32 + 255) / 256, 256>>>(atom_x, V, ALD2, NATOM, 1);

    launch_edge_acc(a_src_e, a_dst_e, EATOM, NATOM, ALS1, ALD1, HSA, Z1, OA, 0);
    launch_edge_acc(m_aa, m_atom, EM2P, nloop_i, ALS2, ALD2, HSB, Z2, OA, HCD);

    // LN + elu -> atom_h in OA, plus SAG dots
    run_ln(OA, abatch, Z1, Z2, bd, bi, ln_d_w, ln_d_b,
           pd_Wrel, pd_Wroot, T, R, NATOM, CNT);
    run_sag_scalars(a_src_e, a_dst_e, EATOM, abatch, pd_brel, T, R,
                    AGG, SPREA, SGMA, SGZA, NATOM);

    // ============ aa phase ============
    cudaMemsetAsync(Z1, 0, (size_t)4 * NAA * sizeof(float));

    // intra: hs + ALS1 + ALD1
    gemm2_k<<<(NAA + 63) / 64, 200, GEMM_SMEM>>>(aa_x, Wp, HSB, ALS1, ap_src, ap_dst, ALD1, NAA, 1);
    // inter src (atom_h in OA, no elu): hs + ALS2 — consumes OA before scaling
    gemm2_k<<<(NATOM + 63) / 64, 200, GEMM_SMEM>>>(OA, Wi_src, HSA, ALS2, ai_src, ai_dst, nullptr, NATOM, 0);
    // inter dst (aa): ALD2
    ald_vec_k<<<((long)NAA * 32 + 255) / 256, 256>>>(aa_x, V, ALD2, NAA, 1);

    // DEFERRED atom SAG scale: OA -> atom_out (after OA consumed above)
    sag_scale_k<<<((long)NATOM * 50 + 255) / 256, 256>>>(OA, SPREA, SGMA, SGZA, abatch, DG, NATOM);

    launch_edge_acc(p_src_e, p_dst_e, EAA, NAA, ALS1, ALD1, HSB, Z1, OP, 0);
    launch_edge_acc(m_atom, m_aa, EM2P, nloop_i, ALS2, ALD2, HSA, Z2, OP, HCD);

    // LN + elu -> aa_h in OP, plus SAG dots
    run_ln(OP, pbatch, Z1, Z2, bp, bi, ln_p_w, ln_p_b,
           pp_Wrel, pp_Wroot, T, R, NAA, CNT);
    run_sag_scalars(p_src_e, p_dst_e, EAA, pbatch, pp_brel, T, R,
                    AGG, SPREP, SGMP, SGZP, NAA);
    sag_scale_k<<<((long)NAA * 50 + 255) / 256, 256>>>(OP, SPREP, SGMP, SGZP, pbatch, PG, NAA);
}

// round 5
// speedup vs baseline: 1.5168x; 1.1897x over previous
#include <cuda_runtime.h>
#include <cuda_bf16.h>
#include <cstdint>

// ---------------- problem constants ----------------
#define NATOM 25600
#define NAA   204800
#define EATOM 102400
#define EAA   1024000
#define EM2P  512000
#define DIM   200
#define HCD   100
#define NB    512

// ---------------- scratch layout (floats) ----------------
static const long OFF_HSA   = 0;                        // 25600*100
static const long OFF_HSB   = OFF_HSA   + 2560000L;     // 204800*100
static const long OFF_ALS1  = OFF_HSB   + 20480000L;    // 204800*2
static const long OFF_ALD1  = OFF_ALS1  + 409600L;      // 204800*2
static const long OFF_ALS2  = OFF_ALD1  + 409600L;      // 204800*2
static const long OFF_ALD2  = OFF_ALS2  + 409600L;      // 204800*2
static const long OFF_Z1    = OFF_ALD2  + 409600L;      // 204800*2
static const long OFF_Z2    = OFF_Z1    + 409600L;      // 204800*2 (Z1,Z2 contiguous)
static const long OFF_V     = OFF_Z2    + 409600L;      // 400 pad 512
static const long OFF_T     = OFF_V     + 512L;         // 204800
static const long OFF_R     = OFF_T     + 204800L;      // 204800
static const long OFF_AGG   = OFF_R     + 204800L;      // 204800
static const long OFF_SPREA = OFF_AGG   + 204800L;      // 25600
static const long OFF_SPREP = OFF_SPREA + 25600L;       // 204800
static const long OFF_SGMA  = OFF_SPREP + 204800L;      // 512
static const long OFF_SGZA  = OFF_SGMA  + 512L;         // 512
static const long OFF_SGMP  = OFF_SGZA  + 512L;         // 512
static const long OFF_SGZP  = OFF_SGMP  + 512L;         // 512
static const long OFF_CNT   = OFF_SGZP  + 512L;         // 512 (CNT,GSUM,GSQ contiguous)
static const long OFF_GSUM  = OFF_CNT   + 512L;         // 512
static const long OFF_GSQ   = OFF_GSUM  + 512L;         // 512
static const long SCRATCH_FLOATS = OFF_GSQ + 512L;

__device__ __align__(256) float g_scratch[SCRATCH_FLOATS];

// ---------------- device helpers ----------------
__device__ __forceinline__ float eluf(float x)  { return x > 0.f ? x : expm1f(x); }
__device__ __forceinline__ float lreluf(float x){ return x > 0.f ? x : 0.2f * x; }

__device__ __forceinline__ void atomicMaxF(float* a, float v) {
    if (v >= 0.f) atomicMax((int*)a, __float_as_int(v));
    else          atomicMin((unsigned int*)a, __float_as_uint(v));
}

__device__ __forceinline__ float warp_sum(float v) {
    #pragma unroll
    for (int o = 16; o > 0; o >>= 1) v += __shfl_down_sync(0xffffffffu, v, o);
    return v;
}

// ---------------- generic small kernels ----------------
__global__ void fill_k(float* p, float v, int n) {
    int i = blockIdx.x * blockDim.x + threadIdx.x;
    if (i < n) p[i] = v;
}

// ---------------- GEMM v3: 128 rows/block, 400 threads -----------------------
// Y[N,100] = elu?(X[N,200]) @ W[200,100]
// ALS[n,h]  = sum_c Y[n,h*50+c]*a_src[h*50+c]
// ALD[n,h]  = sum_c Y[n,h*50+c]*a_dst[h*50+c]      (if ALD)
// XALD[n,h] = sum_k elu?(X[n,k])*V[k,h]            (if XALD; V interleaved [k][h])
// threads: tx = tid%25 (4 cols each), ty = tid/25 (8 rows each) -> 128x100 tile
#define GEMM_SMEM (size_t)((20000 + 25600 + 512) * sizeof(float))
__global__ void __launch_bounds__(400, 1)
gemm3_k(const float* __restrict__ X, const float* __restrict__ W,
        float* __restrict__ Y, float* __restrict__ ALS,
        const float* __restrict__ a_src, const float* __restrict__ a_dst,
        float* __restrict__ ALD,
        const float* __restrict__ Vg, float* __restrict__ XALD,
        int N, int do_elu) {
    extern __shared__ float sm[];
    float* Ws = sm;               // 20000 : [k][c]
    float* Xs = sm + 20000;       // 25600 : [k][r], stride 128
    float* Vs = sm + 45600;       // 512

    int tid = threadIdx.x;
    int tx = tid % 25, ty = tid / 25;
    int row0 = blockIdx.x * 128;

    for (int i = tid; i < 5000; i += 400)
        ((float4*)Ws)[i] = ((const float4*)W)[i];
    if (XALD && tid < 400) {
        // V has 400 floats
        if (tid < 400) Vs[tid] = Vg[tid];
    }
    // X tile: 6400 float4; index so that consecutive lanes get consecutive rows
    // -> conflict-free STS into [k][r] layout (global read mildly strided).
    for (int i = tid; i < 6400; i += 400) {
        int r = i & 127, kq = i >> 7;
        int row = row0 + r;
        float4 v = make_float4(0.f, 0.f, 0.f, 0.f);
        if (row < N) v = ((const float4*)(X + (size_t)row * DIM))[kq];
        if (do_elu) { v.x = eluf(v.x); v.y = eluf(v.y); v.z = eluf(v.z); v.w = eluf(v.w); }
        int kb = kq * 4;
        Xs[(kb + 0) * 128 + r] = v.x;
        Xs[(kb + 1) * 128 + r] = v.y;
        Xs[(kb + 2) * 128 + r] = v.z;
        Xs[(kb + 3) * 128 + r] = v.w;
    }
    __syncthreads();

    float acc[8][4];
    #pragma unroll
    for (int r = 0; r < 8; r++)
        #pragma unroll
        for (int c = 0; c < 4; c++) acc[r][c] = 0.f;

    const float* wp = Ws + 4 * tx;
    const float* xp = Xs + 8 * ty;

    #pragma unroll 4
    for (int k = 0; k < DIM; k++) {
        float4 w4 = *(const float4*)(wp + k * HCD);
        float4 xa = *(const float4*)(xp + k * 128);
        float4 xb = *(const float4*)(xp + k * 128 + 4);
        float xr[8] = {xa.x, xa.y, xa.z, xa.w, xb.x, xb.y, xb.z, xb.w};
        #pragma unroll
        for (int r = 0; r < 8; r++) {
            acc[r][0] += xr[r] * w4.x;
            acc[r][1] += xr[r] * w4.y;
            acc[r][2] += xr[r] * w4.z;
            acc[r][3] += xr[r] * w4.w;
        }
    }
    __syncthreads();   // Ws region now reused for partial sums

    float* part_s = sm;          // 6400 : [row][head*25+tx]
    float* part_d = sm + 6400;   // 6400

    int c0 = 4 * tx;
    float4 af = *(const float4*)(a_src + c0);
    float4 bf = ALD ? *(const float4*)(a_dst + c0) : make_float4(0.f, 0.f, 0.f, 0.f);

    #pragma unroll
    for (int r = 0; r < 8; r++) {
        int lrow = 8 * ty + r;
        int row = row0 + lrow;
        float s0 = 0.f, s1 = 0.f, t0 = 0.f, t1 = 0.f;
        float ps[4] = {acc[r][0]*af.x, acc[r][1]*af.y, acc[r][2]*af.z, acc[r][3]*af.w};
        float pd[4] = {acc[r][0]*bf.x, acc[r][1]*bf.y, acc[r][2]*bf.z, acc[r][3]*bf.w};
        #pragma unroll
        for (int q = 0; q < 4; q++) {
            if (c0 + q < 50) { s0 += ps[q]; t0 += pd[q]; }
            else             { s1 += ps[q]; t1 += pd[q]; }
        }
        part_s[lrow * 50 + tx]      = s0;
        part_s[lrow * 50 + 25 + tx] = s1;
        part_d[lrow * 50 + tx]      = t0;
        part_d[lrow * 50 + 25 + tx] = t1;
        if (row < N)
            *(float4*)(Y + (size_t)row * HCD + c0) =
                make_float4(acc[r][0], acc[r][1], acc[r][2], acc[r][3]);
    }

    // inter-dst attention dot from the X tile (Xs untouched by partials)
    if (XALD && tid < 128) {
        int r = tid, row = row0 + r;
        float a0 = 0.f, a1 = 0.f;
        #pragma unroll 4
        for (int k = 0; k < DIM; k++) {
            float x = Xs[k * 128 + r];
            a0 += x * Vs[2 * k];
            a1 += x * Vs[2 * k + 1];
        }
        if (row < N) ((float2*)XALD)[row] = make_float2(a0, a1);
    }
    __syncthreads();

    if (tid < 256) {
        int r = tid >> 1, h = tid & 1;
        int row = row0 + r;
        if (row < N) {
            float s = 0.f, t = 0.f;
            const float* ps = part_s + r * 50 + h * 25;
            const float* pd = part_d + r * 50 + h * 25;
            #pragma unroll
            for (int i = 0; i < 25; i++) { s += ps[i]; t += pd[i]; }
            ALS[(size_t)row * 2 + h] = s;
            if (ALD) ALD[(size_t)row * 2 + h] = t;
        }
    }
}

// ---------------- fold v[k,h] = sum_c Wdst[k, h*50+c] * adst[h,c] -------------
__global__ void fold_v_k(const float* __restrict__ Wdst, const float* __restrict__ adst,
                         float* __restrict__ v) {
    int i = blockIdx.x * blockDim.x + threadIdx.x;
    if (i >= 2 * DIM) return;
    int k = i >> 1, h = i & 1;
    float s = 0.f;
    #pragma unroll
    for (int c = 0; c < 50; c++) s += Wdst[k * HCD + h * 50 + c] * adst[h * 50 + c];
    v[2 * k + h] = s;
}

// ---------------- edge pass: accumulate z and unnormalized out ----------------
__global__ void edge_acc_k(const int* __restrict__ src, const int* __restrict__ dst,
                           int E, int nloop,
                           const float* __restrict__ als, const float* __restrict__ ald,
                           const float* __restrict__ hs,
                           float* __restrict__ z, float* __restrict__ out, int coloff) {
    int w = (blockIdx.x * blockDim.x + threadIdx.x) >> 5;
    int lane = threadIdx.x & 31;
    if (w >= E + nloop) return;
    int s, d;
    if (w < E) { s = src[w]; d = dst[w]; } else { s = w - E; d = w - E; }
    float2 as = ((const float2*)als)[s];
    float2 ad = ((const float2*)ald)[d];
    float e0 = __expf(lreluf(as.x + ad.x));
    float e1 = __expf(lreluf(as.y + ad.y));
    if (lane == 25) atomicAdd(&z[2 * d],     e0);
    if (lane == 26) atomicAdd(&z[2 * d + 1], e1);
    if (lane < 25) {
        int j = lane * 4;
        const float4 h4 = *(const float4*)(hs + (size_t)s * HCD + j);
        float w0 = (j     < 50 ? e0 : e1) * h4.x;
        float w1 = (j + 1 < 50 ? e0 : e1) * h4.y;
        float w2 = (j + 2 < 50 ? e0 : e1) * h4.z;
        float w3 = (j + 3 < 50 ? e0 : e1) * h4.w;
        float* p = out + (size_t)d * DIM + coloff + j;
        asm volatile("red.global.add.v4.f32 [%0], {%1,%2,%3,%4};"
                     :: "l"(p), "f"(w0), "f"(w1), "f"(w2), "f"(w3) : "memory");
    }
}

// ---------------- fused: finalize (virtual) + LN stats + graph counts ---------
__global__ void ln_stats_fused_k(const float* __restrict__ out,
                                 const float* __restrict__ z1, const float* __restrict__ z2,
                                 const float* __restrict__ b1, const float* __restrict__ b2,
                                 const int* __restrict__ batch,
                                 float* __restrict__ cnt,
                                 float* __restrict__ gsum, float* __restrict__ gsq, int N) {
    int n = (blockIdx.x * blockDim.x + threadIdx.x) >> 5;
    int lane = threadIdx.x & 31;
    if (n >= N) return;
    float2 zz1 = ((const float2*)z1)[n];
    float2 zz2 = ((const float2*)z2)[n];
    float iz10 = 1.f / (zz1.x + 1e-16f), iz11 = 1.f / (zz1.y + 1e-16f);
    float iz20 = 1.f / (zz2.x + 1e-16f), iz21 = 1.f / (zz2.y + 1e-16f);
    const float4* xr = (const float4*)(out + (size_t)n * DIM);
    float s = 0.f, q = 0.f;
    #pragma unroll
    for (int c = lane; c < 50; c += 32) {
        float4 val = xr[c];
        int j = 4 * c;
        float4 b = (c < 25) ? ((const float4*)b1)[c] : ((const float4*)b2)[c - 25];
        float izA, izB;
        if (c < 25) { izA = iz10; izB = iz11; } else { izA = iz20; izB = iz21; }
        int jj = (c < 25) ? j : j - 100;
        float y0 = val.x * (jj     < 50 ? izA : izB) + b.x;
        float y1 = val.y * (jj + 1 < 50 ? izA : izB) + b.y;
        float y2 = val.z * (jj + 2 < 50 ? izA : izB) + b.z;
        float y3 = val.w * (jj + 3 < 50 ? izA : izB) + b.w;
        s += y0 + y1 + y2 + y3;
        q += y0*y0 + y1*y1 + y2*y2 + y3*y3;
    }
    s = warp_sum(s); q = warp_sum(q);
    if (lane == 0) {
        int g = batch[n];
        atomicAdd(&cnt[g], 1.f);
        atomicAdd(&gsum[g], s);
        atomicAdd(&gsq[g], q);
    }
}

// ---------------- fused: finalize + LN apply + elu + SAG T/R dots -------------
__global__ void ln_apply_fused_k(float* __restrict__ x,
                                 const float* __restrict__ z1, const float* __restrict__ z2,
                                 const float* __restrict__ b1, const float* __restrict__ b2,
                                 const int* __restrict__ batch,
                                 const float* __restrict__ cnt, const float* __restrict__ gsum,
                                 const float* __restrict__ gsq,
                                 const float* __restrict__ wv, const float* __restrict__ bv,
                                 const float* __restrict__ Wrel, const float* __restrict__ Wroot,
                                 float* __restrict__ T, float* __restrict__ R, int N) {
    int n = (blockIdx.x * blockDim.x + threadIdx.x) >> 5;
    int lane = threadIdx.x & 31;
    if (n >= N) return;
    int g = batch[n];
    float norm = fmaxf(cnt[g], 1.f) * (float)DIM;
    float mean = gsum[g] / norm;
    float var  = gsq[g] / norm - mean * mean;
    float rstd = rsqrtf(var + 1e-5f);
    float2 zz1 = ((const float2*)z1)[n];
    float2 zz2 = ((const float2*)z2)[n];
    float iz10 = 1.f / (zz1.x + 1e-16f), iz11 = 1.f / (zz1.y + 1e-16f);
    float iz20 = 1.f / (zz2.x + 1e-16f), iz21 = 1.f / (zz2.y + 1e-16f);
    float4* xr = (float4*)(x + (size_t)n * DIM);
    float t = 0.f, r = 0.f;
    #pragma unroll
    for (int c = lane; c < 50; c += 32) {
        float4 val = xr[c];
        int j = 4 * c;
        float4 b = (c < 25) ? ((const float4*)b1)[c] : ((const float4*)b2)[c - 25];
        float izA, izB;
        if (c < 25) { izA = iz10; izB = iz11; } else { izA = iz20; izB = iz21; }
        int jj = (c < 25) ? j : j - 100;
        float4 w4 = ((const float4*)wv)[c];
        float4 bb = ((const float4*)bv)[c];
        float4 wr = ((const float4*)Wrel)[c];
        float4 wo = ((const float4*)Wroot)[c];
        float y0 = val.x * (jj     < 50 ? izA : izB) + b.x;
        float y1 = val.y * (jj + 1 < 50 ? izA : izB) + b.y;
        float y2 = val.z * (jj + 2 < 50 ? izA : izB) + b.z;
        float y3 = val.w * (jj + 3 < 50 ? izA : izB) + b.w;
        float e0 = eluf((y0 - mean) * rstd * w4.x + bb.x);
        float e1 = eluf((y1 - mean) * rstd * w4.y + bb.y);
        float e2 = eluf((y2 - mean) * rstd * w4.z + bb.z);
        float e3 = eluf((y3 - mean) * rstd * w4.w + bb.w);
        xr[c] = make_float4(e0, e1, e2, e3);
        t += e0*wr.x + e1*wr.y + e2*wr.z + e3*wr.w;
        r += e0*wo.x + e1*wo.y + e2*wo.z + e3*wo.w;
    }
    t = warp_sum(t); r = warp_sum(r);
    if (lane == 0) { T[n] = t; R[n] = r; }
}

// ---------------- SAG pooling ----------------
__global__ void sag_edge_k(const int* __restrict__ src, const int* __restrict__ dst, int E,
                           const float* __restrict__ T, float* __restrict__ agg) {
    int e = blockIdx.x * blockDim.x + threadIdx.x;
    if (e < E) atomicAdd(&agg[dst[e]], T[src[e]]);
}

__global__ void sag_spre_k(const float* __restrict__ agg, const float* __restrict__ R,
                           const float* __restrict__ brel, const int* __restrict__ batch,
                           float* __restrict__ spre, float* __restrict__ sgm, int N) {
    int i = blockIdx.x * blockDim.x + threadIdx.x;
    if (i >= N) return;
    float s = agg[i] + brel[0] + R[i];
    spre[i] = s;
    atomicMaxF(&sgm[batch[i]], s);
}

__global__ void sag_z_k(const float* __restrict__ spre, const int* __restrict__ batch,
                        const float* __restrict__ sgm, float* __restrict__ sgz, int N) {
    int i = blockIdx.x * blockDim.x + threadIdx.x;
    if (i >= N) return;
    int g = batch[i];
    atomicAdd(&sgz[g], __expf(spre[i] - sgm[g]));
}

__global__ void sag_scale_k(float* __restrict__ x, const float* __restrict__ spre,
                            const float* __restrict__ sgm, const float* __restrict__ sgz,
                            const int* __restrict__ batch, float* __restrict__ G, int N) {
    long i = (long)blockIdx.x * blockDim.x + threadIdx.x;
    if (i >= (long)N * 50) return;
    int n = (int)(i / 50), q = (int)(i - (long)n * 50);
    int g = batch[n];
    float score = __expf(spre[n] - sgm[g]) / (sgz[g] + 1e-16f);
    float4 v = *(float4*)(x + (size_t)n * DIM + 4 * q);
    v.x *= score; v.y *= score; v.z *= score; v.w *= score;
    *(float4*)(x + (size_t)n * DIM + 4 * q) = v;
    float* p = G + (size_t)g * DIM + 4 * q;
    asm volatile("red.global.add.v4.f32 [%0], {%1,%2,%3,%4};"
                 :: "l"(p), "f"(v.x), "f"(v.y), "f"(v.z), "f"(v.w) : "memory");
}

// ---------------- host orchestration ----------------
static void launch_edge_acc(const int* src, const int* dst, int E, int nloop,
                            const float* ALS, const float* ALD, const float* HS,
                            float* Z, float* out, int coloff) {
    long tot = (long)E + nloop;
    edge_acc_k<<<(tot * 32 + 255) / 256, 256>>>(src, dst, E, nloop, ALS, ALD, HS, Z, out, coloff);
}

static void run_ln(float* x, const int* batch,
                   const float* z1, const float* z2,
                   const float* b1, const float* b2,
                   const float* lnw, const float* lnb,
                   const float* Wrel, const float* Wroot,
                   float* T, float* R, int N, float* CNT) {
    cudaMemsetAsync(CNT, 0, 3 * NB * sizeof(float));
    ln_stats_fused_k<<<(N * 32 + 255) / 256, 256>>>(x, z1, z2, b1, b2, batch,
                                                    CNT, CNT + NB, CNT + 2 * NB, N);
    ln_apply_fused_k<<<(N * 32 + 255) / 256, 256>>>(x, z1, z2, b1, b2, batch,
                                                    CNT, CNT + NB, CNT + 2 * NB,
                                                    lnw, lnb, Wrel, Wroot, T, R, N);
}

static void run_sag_scalars(const int* src, const int* dst, int E, const int* batch,
                            const float* brel, const float* T, const float* R,
                            float* AGG, float* SPRE, float* SGM, float* SGZ, int N) {
    cudaMemsetAsync(AGG, 0, (size_t)N * sizeof(float));
    fill_k<<<(NB + 255) / 256, 256>>>(SGM, -1e30f, NB);
    cudaMemsetAsync(SGZ, 0, NB * sizeof(float));
    sag_edge_k<<<(E + 255) / 256, 256>>>(src, dst, E, T, AGG);
    sag_spre_k<<<(N + 255) / 256, 256>>>(AGG, R, brel, batch, SPRE, SGM, N);
    sag_z_k<<<(N + 255) / 256, 256>>>(SPRE, batch, SGM, SGZ, N);
}

extern "C" void kernel_launch(void* const* d_in, const int* in_sizes, int n_in,
                              void* d_out, int out_size) {
    const float* atom_x  = (const float*)d_in[0];
    const int*   aei     = (const int*)  d_in[1];
    const int*   abatch  = (const int*)  d_in[2];
    const float* aa_x    = (const float*)d_in[3];
    const int*   pei     = (const int*)  d_in[4];
    // d_in[5] = aa_edge_attr (unused by reference)
    const int*   pbatch  = (const int*)  d_in[6];
    const int*   m2p     = (const int*)  d_in[7];
    const float* Wd      = (const float*)d_in[8];
    const float* ad_src  = (const float*)d_in[9];
    const float* ad_dst  = (const float*)d_in[10];
    const float* bd      = (const float*)d_in[11];
    const float* Wp      = (const float*)d_in[12];
    const float* ap_src  = (const float*)d_in[13];
    const float* ap_dst  = (const float*)d_in[14];
    const float* bp      = (const float*)d_in[15];
    const float* Wi_src  = (const float*)d_in[16];
    const float* Wi_dst  = (const float*)d_in[17];
    const float* ai_src  = (const float*)d_in[18];
    const float* ai_dst  = (const float*)d_in[19];
    const float* bi      = (const float*)d_in[20];
    const float* ln_d_w  = (const float*)d_in[21];
    const float* ln_d_b  = (const float*)d_in[22];
    const float* ln_p_w  = (const float*)d_in[23];
    const float* ln_p_b  = (const float*)d_in[24];
    const float* pd_Wrel = (const float*)d_in[25];
    const float* pd_brel = (const float*)d_in[26];
    const float* pd_Wroot= (const float*)d_in[27];
    const float* pp_Wrel = (const float*)d_in[28];
    const float* pp_brel = (const float*)d_in[29];
    const float* pp_Wroot= (const float*)d_in[30];

    cudaFuncSetAttribute(gemm3_k, cudaFuncAttributeMaxDynamicSharedMemorySize, (int)GEMM_SMEM);

    float* S = nullptr;
    cudaGetSymbolAddress((void**)&S, g_scratch);

    float* HSA   = S + OFF_HSA;
    float* HSB   = S + OFF_HSB;
    float* ALS1  = S + OFF_ALS1;
    float* ALD1  = S + OFF_ALD1;
    float* ALS2  = S + OFF_ALS2;
    float* ALD2  = S + OFF_ALD2;
    float* Z1    = S + OFF_Z1;
    float* Z2    = S + OFF_Z2;
    float* V     = S + OFF_V;
    float* T     = S + OFF_T;
    float* R     = S + OFF_R;
    float* AGG   = S + OFF_AGG;
    float* SPREA = S + OFF_SPREA;
    float* SPREP = S + OFF_SPREP;
    float* SGMA  = S + OFF_SGMA;
    float* SGZA  = S + OFF_SGZA;
    float* SGMP  = S + OFF_SGMP;
    float* SGZP  = S + OFF_SGZP;
    float* CNT   = S + OFF_CNT;

    float* out = (float*)d_out;
    float* OA  = out;                                  // atom_h -> atom_out [25600,200]
    float* OP  = out + (size_t)NATOM * DIM;            // aa_h -> aa_out    [204800,200]
    float* DG  = out + (size_t)(NATOM + NAA) * DIM;    // drug_g [512,200]
    float* PG  = DG + (size_t)NB * DIM;                // prot_g [512,200]

    cudaMemsetAsync(d_out, 0, (size_t)out_size * sizeof(float));

    const int* a_src_e = aei;
    const int* a_dst_e = aei + EATOM;
    const int* p_src_e = pei;
    const int* p_dst_e = pei + EAA;
    const int* m_atom  = m2p;
    const int* m_aa    = m2p + EM2P;
    const int  nloop_i = NATOM;   // min(NATOM, NAA)

    // shared inter-GAT dst fold: V = Wi_dst @ ai_dst (same for both directions)
    fold_v_k<<<2, 256>>>(Wi_dst, ai_dst, V);

    // ============ atom phase ============
    cudaMemsetAsync(Z1, 0, (size_t)4 * NAA * sizeof(float));   // Z1+Z2 contiguous

    // intra: hs + ALS1 + ALD1 + inter-dst dot XALD2 = elu(atom_x)@V
    gemm3_k<<<(NATOM + 127) / 128, 400, GEMM_SMEM>>>(atom_x, Wd, HSA, ALS1, ad_src, ad_dst, ALD1,
                                                     V, ALD2, NATOM, 1);
    // inter src (aa): hs + ALS2
    gemm3_k<<<(NAA + 127) / 128, 400, GEMM_SMEM>>>(aa_x, Wi_src, HSB, ALS2, ai_src, ai_dst, nullptr,
                                                   nullptr, nullptr, NAA, 1);

    launch_edge_acc(a_src_e, a_dst_e, EATOM, NATOM, ALS1, ALD1, HSA, Z1, OA, 0);
    launch_edge_acc(m_aa, m_atom, EM2P, nloop_i, ALS2, ALD2, HSB, Z2, OA, HCD);

    // LN + elu -> atom_h in OA, plus SAG dots
    run_ln(OA, abatch, Z1, Z2, bd, bi, ln_d_w, ln_d_b,
           pd_Wrel, pd_Wroot, T, R, NATOM, CNT);
    run_sag_scalars(a_src_e, a_dst_e, EATOM, abatch, pd_brel, T, R,
                    AGG, SPREA, SGMA, SGZA, NATOM);

    // ============ aa phase ============
    cudaMemsetAsync(Z1, 0, (size_t)4 * NAA * sizeof(float));

    // intra: hs + ALS1 + ALD1 + inter-dst dot XALD2 = elu(aa_x)@V
    gemm3_k<<<(NAA + 127) / 128, 400, GEMM_SMEM>>>(aa_x, Wp, HSB, ALS1, ap_src, ap_dst, ALD1,
                                                   V, ALD2, NAA, 1);
    // inter src (atom_h in OA, no elu): hs + ALS2 — consumes OA before scaling
    gemm3_k<<<(NATOM + 127) / 128, 400, GEMM_SMEM>>>(OA, Wi_src, HSA, ALS2, ai_src, ai_dst, nullptr,
                                                     nullptr, nullptr, NATOM, 0);

    // DEFERRED atom SAG scale: OA -> atom_out (after OA consumed above)
    sag_scale_k<<<((long)NATOM * 50 + 255) / 256, 256>>>(OA, SPREA, SGMA, SGZA, abatch, DG, NATOM);

    launch_edge_acc(p_src_e, p_dst_e, EAA, NAA, ALS1, ALD1, HSB, Z1, OP, 0);
    launch_edge_acc(m_atom, m_aa, EM2P, nloop_i, ALS2, ALD2, HSA, Z2, OP, HCD);

    // LN + elu -> aa_h in OP, plus SAG dots
    run_ln(OP, pbatch, Z1, Z2, bp, bi, ln_p_w, ln_p_b,
           pp_Wrel, pp_Wroot, T, R, NAA, CNT);
    run_sag_scalars(p_src_e, p_dst_e, EAA, pbatch, pp_brel, T, R,
                    AGG, SPREP, SGMP, SGZP, NAA);
    sag_scale_k<<<((long)NAA * 50 + 255) / 256, 256>>>(OP, SPREP, SGMP, SGZP, pbatch, PG, NAA);
}

// round 6
// speedup vs baseline: 1.6384x; 1.0802x over previous
#include <cuda_runtime.h>
#include <cuda_bf16.h>
#include <cstdint>

// ---------------- problem constants ----------------
#define NATOM 25600
#define NAA   204800
#define EATOM 102400
#define EAA   1024000
#define EM2P  512000
#define DIM   200
#define HCD   100
#define NB    512

// ---------------- scratch layout (floats) ----------------
static const long OFF_HSA   = 0;                         // 2,560,000
static const long OFF_HSB   = 2560000L;                  // 20,480,000
static const long OFF_ALS1  = 23040000L;                 // 409,600
static const long OFF_ALD1  = 23449600L;
static const long OFF_ALS2  = 23859200L;
static const long OFF_ALD2  = 24268800L;
// ---- zero block (one memset) ----
static const long OFF_ZSTART= 24678400L;
static const long OFF_ZA1   = 24678400L;                 // 2*NATOM
static const long OFF_ZA2   = 24729600L;                 // 2*NATOM
static const long OFF_ZP1   = 24780800L;                 // 2*NAA
static const long OFF_ZP2   = 25190400L;                 // 2*NAA
static const long OFF_AGGA  = 25600000L;                 // NATOM
static const long OFF_AGGP  = 25625600L;                 // NAA
static const long OFF_SGZA  = 25830400L;                 // 512
static const long OFF_SGZP  = 25830912L;                 // 512
static const long OFF_CNTA  = 25831424L;                 // 3*512
static const long OFF_CNTP  = 25832960L;                 // 3*512
static const long OFF_ZEND  = 25834496L;
// ---- fill block (-1e30, one fill) ----
static const long OFF_SGMA  = 25834496L;                 // 512
static const long OFF_SGMP  = 25835008L;                 // 512
// ---- rest ----
static const long OFF_V     = 25835520L;                 // 512
static const long OFF_T     = 25836032L;                 // NAA
static const long OFF_R     = 26040832L;                 // NAA
static const long OFF_SPREA = 26245632L;                 // NATOM
static const long OFF_SPREP = 26271232L;                 // NAA
static const long SCRATCH_FLOATS = 26476032L;

__device__ __align__(256) float g_scratch[SCRATCH_FLOATS];

// ---------------- device helpers ----------------
__device__ __forceinline__ float eluf(float x)  { return x > 0.f ? x : expm1f(x); }
__device__ __forceinline__ float lreluf(float x){ return x > 0.f ? x : 0.2f * x; }

__device__ __forceinline__ void atomicMaxF(float* a, float v) {
    if (v >= 0.f) atomicMax((int*)a, __float_as_int(v));
    else          atomicMin((unsigned int*)a, __float_as_uint(v));
}

__device__ __forceinline__ float warp_sum(float v) {
    #pragma unroll
    for (int o = 16; o > 0; o >>= 1) v += __shfl_down_sync(0xffffffffu, v, o);
    return v;
}

// ---------------- generic small kernels ----------------
__global__ void fill_k(float* p, float v, int n) {
    int i = blockIdx.x * blockDim.x + threadIdx.x;
    if (i < n) p[i] = v;
}

// ---------------- GEMM v3: 128 rows/block, 400 threads -----------------------
#define GEMM_SMEM (size_t)((20000 + 25600 + 512) * sizeof(float))
__global__ void __launch_bounds__(400, 1)
gemm3_k(const float* __restrict__ X, const float* __restrict__ W,
        float* __restrict__ Y, float* __restrict__ ALS,
        const float* __restrict__ a_src, const float* __restrict__ a_dst,
        float* __restrict__ ALD,
        const float* __restrict__ Vg, float* __restrict__ XALD,
        int N, int do_elu) {
    extern __shared__ float sm[];
    float* Ws = sm;               // 20000 : [k][c]
    float* Xs = sm + 20000;       // 25600 : [k][r], stride 128
    float* Vs = sm + 45600;       // 512

    int tid = threadIdx.x;
    int tx = tid % 25, ty = tid / 25;
    int row0 = blockIdx.x * 128;

    for (int i = tid; i < 5000; i += 400)
        ((float4*)Ws)[i] = ((const float4*)W)[i];
    if (XALD && tid < 400) Vs[tid] = Vg[tid];

    for (int i = tid; i < 6400; i += 400) {
        int r = i & 127, kq = i >> 7;
        int row = row0 + r;
        float4 v = make_float4(0.f, 0.f, 0.f, 0.f);
        if (row < N) v = ((const float4*)(X + (size_t)row * DIM))[kq];
        if (do_elu) { v.x = eluf(v.x); v.y = eluf(v.y); v.z = eluf(v.z); v.w = eluf(v.w); }
        int kb = kq * 4;
        Xs[(kb + 0) * 128 + r] = v.x;
        Xs[(kb + 1) * 128 + r] = v.y;
        Xs[(kb + 2) * 128 + r] = v.z;
        Xs[(kb + 3) * 128 + r] = v.w;
    }
    __syncthreads();

    float acc[8][4];
    #pragma unroll
    for (int r = 0; r < 8; r++)
        #pragma unroll
        for (int c = 0; c < 4; c++) acc[r][c] = 0.f;

    const float* wp = Ws + 4 * tx;
    const float* xp = Xs + 8 * ty;

    #pragma unroll 4
    for (int k = 0; k < DIM; k++) {
        float4 w4 = *(const float4*)(wp + k * HCD);
        float4 xa = *(const float4*)(xp + k * 128);
        float4 xb = *(const float4*)(xp + k * 128 + 4);
        float xr[8] = {xa.x, xa.y, xa.z, xa.w, xb.x, xb.y, xb.z, xb.w};
        #pragma unroll
        for (int r = 0; r < 8; r++) {
            acc[r][0] += xr[r] * w4.x;
            acc[r][1] += xr[r] * w4.y;
            acc[r][2] += xr[r] * w4.z;
            acc[r][3] += xr[r] * w4.w;
        }
    }
    __syncthreads();   // Ws region reused for partial sums

    float* part_s = sm;          // 6400
    float* part_d = sm + 6400;   // 6400

    int c0 = 4 * tx;
    float4 af = *(const float4*)(a_src + c0);
    float4 bf = ALD ? *(const float4*)(a_dst + c0) : make_float4(0.f, 0.f, 0.f, 0.f);

    #pragma unroll
    for (int r = 0; r < 8; r++) {
        int lrow = 8 * ty + r;
        int row = row0 + lrow;
        float s0 = 0.f, s1 = 0.f, t0 = 0.f, t1 = 0.f;
        float ps[4] = {acc[r][0]*af.x, acc[r][1]*af.y, acc[r][2]*af.z, acc[r][3]*af.w};
        float pd[4] = {acc[r][0]*bf.x, acc[r][1]*bf.y, acc[r][2]*bf.z, acc[r][3]*bf.w};
        #pragma unroll
        for (int q = 0; q < 4; q++) {
            if (c0 + q < 50) { s0 += ps[q]; t0 += pd[q]; }
            else             { s1 += ps[q]; t1 += pd[q]; }
        }
        part_s[lrow * 50 + tx]      = s0;
        part_s[lrow * 50 + 25 + tx] = s1;
        part_d[lrow * 50 + tx]      = t0;
        part_d[lrow * 50 + 25 + tx] = t1;
        if (row < N)
            *(float4*)(Y + (size_t)row * HCD + c0) =
                make_float4(acc[r][0], acc[r][1], acc[r][2], acc[r][3]);
    }

    if (XALD && tid < 128) {
        int r = tid, row = row0 + r;
        float a0 = 0.f, a1 = 0.f;
        #pragma unroll 4
        for (int k = 0; k < DIM; k++) {
            float x = Xs[k * 128 + r];
            a0 += x * Vs[2 * k];
            a1 += x * Vs[2 * k + 1];
        }
        if (row < N) ((float2*)XALD)[row] = make_float2(a0, a1);
    }
    __syncthreads();

    if (tid < 256) {
        int r = tid >> 1, h = tid & 1;
        int row = row0 + r;
        if (row < N) {
            float s = 0.f, t = 0.f;
            const float* ps = part_s + r * 50 + h * 25;
            const float* pd = part_d + r * 50 + h * 25;
            #pragma unroll
            for (int i = 0; i < 25; i++) { s += ps[i]; t += pd[i]; }
            ALS[(size_t)row * 2 + h] = s;
            if (ALD) ALD[(size_t)row * 2 + h] = t;
        }
    }
}

// ---------------- fold v[k,h] = sum_c Wdst[k, h*50+c] * adst[h,c] -------------
__global__ void fold_v_k(const float* __restrict__ Wdst, const float* __restrict__ adst,
                         float* __restrict__ v) {
    int i = blockIdx.x * blockDim.x + threadIdx.x;
    if (i >= 2 * DIM) return;
    int k = i >> 1, h = i & 1;
    float s = 0.f;
    #pragma unroll
    for (int c = 0; c < 50; c++) s += Wdst[k * HCD + h * 50 + c] * adst[h * 50 + c];
    v[2 * k + h] = s;
}

// ---------------- edge pass: 2 edges per warp, MLP=2 --------------------------
__global__ void edge_acc_k(const int* __restrict__ src, const int* __restrict__ dst,
                           int E, int nloop,
                           const float* __restrict__ als, const float* __restrict__ ald,
                           const float* __restrict__ hs,
                           float* __restrict__ z, float* __restrict__ out, int coloff) {
    long w = ((long)blockIdx.x * blockDim.x + threadIdx.x) >> 5;
    int lane = threadIdx.x & 31;
    long tot = (long)E + nloop;
    long e0 = 2 * w, e1 = e0 + 1;
    if (e0 >= tot) return;
    bool has1 = (e1 < tot);

    int s0, d0, s1 = 0, d1 = 0;
    if (e0 < E) { s0 = src[e0]; d0 = dst[e0]; } else { s0 = d0 = (int)(e0 - E); }
    if (has1) {
        if (e1 < E) { s1 = src[e1]; d1 = dst[e1]; } else { s1 = d1 = (int)(e1 - E); }
    }
    float2 as0 = ((const float2*)als)[s0];
    float2 ad0 = ((const float2*)ald)[d0];
    float2 as1 = make_float2(0.f, 0.f), ad1 = make_float2(0.f, 0.f);
    if (has1) { as1 = ((const float2*)als)[s1]; ad1 = ((const float2*)ald)[d1]; }

    float ex00 = __expf(lreluf(as0.x + ad0.x));
    float ex01 = __expf(lreluf(as0.y + ad0.y));
    float ex10 = 0.f, ex11 = 0.f;
    if (has1) {
        ex10 = __expf(lreluf(as1.x + ad1.x));
        ex11 = __expf(lreluf(as1.y + ad1.y));
    }

    if (lane == 25) atomicAdd(&z[2 * d0],     ex00);
    if (lane == 26) atomicAdd(&z[2 * d0 + 1], ex01);
    if (has1 && lane == 27) atomicAdd(&z[2 * d1],     ex10);
    if (has1 && lane == 28) atomicAdd(&z[2 * d1 + 1], ex11);

    if (lane < 25) {
        int j = lane * 4;
        const float4 h0 = *(const float4*)(hs + (size_t)s0 * HCD + j);
        float4 h1 = make_float4(0.f, 0.f, 0.f, 0.f);
        if (has1) h1 = *(const float4*)(hs + (size_t)s1 * HCD + j);

        float w0 = (j     < 50 ? ex00 : ex01) * h0.x;
        float w1 = (j + 1 < 50 ? ex00 : ex01) * h0.y;
        float w2 = (j + 2 < 50 ? ex00 : ex01) * h0.z;
        float w3 = (j + 3 < 50 ? ex00 : ex01) * h0.w;
        float* p0 = out + (size_t)d0 * DIM + coloff + j;
        asm volatile("red.global.add.v4.f32 [%0], {%1,%2,%3,%4};"
                     :: "l"(p0), "f"(w0), "f"(w1), "f"(w2), "f"(w3) : "memory");
        if (has1) {
            float u0 = (j     < 50 ? ex10 : ex11) * h1.x;
            float u1 = (j + 1 < 50 ? ex10 : ex11) * h1.y;
            float u2 = (j + 2 < 50 ? ex10 : ex11) * h1.z;
            float u3 = (j + 3 < 50 ? ex10 : ex11) * h1.w;
            float* p1 = out + (size_t)d1 * DIM + coloff + j;
            asm volatile("red.global.add.v4.f32 [%0], {%1,%2,%3,%4};"
                         :: "l"(p1), "f"(u0), "f"(u1), "f"(u2), "f"(u3) : "memory");
        }
    }
}

// ---------------- fused: finalize (virtual) + LN stats + graph counts ---------
__global__ void ln_stats_fused_k(const float* __restrict__ out,
                                 const float* __restrict__ z1, const float* __restrict__ z2,
                                 const float* __restrict__ b1, const float* __restrict__ b2,
                                 const int* __restrict__ batch,
                                 float* __restrict__ cnt,
                                 float* __restrict__ gsum, float* __restrict__ gsq, int N) {
    int n = (blockIdx.x * blockDim.x + threadIdx.x) >> 5;
    int lane = threadIdx.x & 31;
    if (n >= N) return;
    float2 zz1 = ((const float2*)z1)[n];
    float2 zz2 = ((const float2*)z2)[n];
    float iz10 = 1.f / (zz1.x + 1e-16f), iz11 = 1.f / (zz1.y + 1e-16f);
    float iz20 = 1.f / (zz2.x + 1e-16f), iz21 = 1.f / (zz2.y + 1e-16f);
    const float4* xr = (const float4*)(out + (size_t)n * DIM);
    float s = 0.f, q = 0.f;
    #pragma unroll
    for (int c = lane; c < 50; c += 32) {
        float4 val = xr[c];
        int j = 4 * c;
        float4 b = (c < 25) ? ((const float4*)b1)[c] : ((const float4*)b2)[c - 25];
        float izA, izB;
        if (c < 25) { izA = iz10; izB = iz11; } else { izA = iz20; izB = iz21; }
        int jj = (c < 25) ? j : j - 100;
        float y0 = val.x * (jj     < 50 ? izA : izB) + b.x;
        float y1 = val.y * (jj + 1 < 50 ? izA : izB) + b.y;
        float y2 = val.z * (jj + 2 < 50 ? izA : izB) + b.z;
        float y3 = val.w * (jj + 3 < 50 ? izA : izB) + b.w;
        s += y0 + y1 + y2 + y3;
        q += y0*y0 + y1*y1 + y2*y2 + y3*y3;
    }
    s = warp_sum(s); q = warp_sum(q);
    if (lane == 0) {
        int g = batch[n];
        atomicAdd(&cnt[g], 1.f);
        atomicAdd(&gsum[g], s);
        atomicAdd(&gsq[g], q);
    }
}

// ---------------- fused: finalize + LN apply + elu + SAG T/R dots -------------
__global__ void ln_apply_fused_k(float* __restrict__ x,
                                 const float* __restrict__ z1, const float* __restrict__ z2,
                                 const float* __restrict__ b1, const float* __restrict__ b2,
                                 const int* __restrict__ batch,
                                 const float* __restrict__ cnt, const float* __restrict__ gsum,
                                 const float* __restrict__ gsq,
                                 const float* __restrict__ wv, const float* __restrict__ bv,
                                 const float* __restrict__ Wrel, const float* __restrict__ Wroot,
                                 float* __restrict__ T, float* __restrict__ R, int N) {
    int n = (blockIdx.x * blockDim.x + threadIdx.x) >> 5;
    int lane = threadIdx.x & 31;
    if (n >= N) return;
    int g = batch[n];
    float norm = fmaxf(cnt[g], 1.f) * (float)DIM;
    float mean = gsum[g] / norm;
    float var  = gsq[g] / norm - mean * mean;
    float rstd = rsqrtf(var + 1e-5f);
    float2 zz1 = ((const float2*)z1)[n];
    float2 zz2 = ((const float2*)z2)[n];
    float iz10 = 1.f / (zz1.x + 1e-16f), iz11 = 1.f / (zz1.y + 1e-16f);
    float iz20 = 1.f / (zz2.x + 1e-16f), iz21 = 1.f / (zz2.y + 1e-16f);
    float4* xr = (float4*)(x + (size_t)n * DIM);
    float t = 0.f, r = 0.f;
    #pragma unroll
    for (int c = lane; c < 50; c += 32) {
        float4 val = xr[c];
        int j = 4 * c;
        float4 b = (c < 25) ? ((const float4*)b1)[c] : ((const float4*)b2)[c - 25];
        float izA, izB;
        if (c < 25) { izA = iz10; izB = iz11; } else { izA = iz20; izB = iz21; }
        int jj = (c < 25) ? j : j - 100;
        float4 w4 = ((const float4*)wv)[c];
        float4 bb = ((const float4*)bv)[c];
        float4 wr = ((const float4*)Wrel)[c];
        float4 wo = ((const float4*)Wroot)[c];
        float y0 = val.x * (jj     < 50 ? izA : izB) + b.x;
        float y1 = val.y * (jj + 1 < 50 ? izA : izB) + b.y;
        float y2 = val.z * (jj + 2 < 50 ? izA : izB) + b.z;
        float y3 = val.w * (jj + 3 < 50 ? izA : izB) + b.w;
        float e0 = eluf((y0 - mean) * rstd * w4.x + bb.x);
        float e1 = eluf((y1 - mean) * rstd * w4.y + bb.y);
        float e2 = eluf((y2 - mean) * rstd * w4.z + bb.z);
        float e3 = eluf((y3 - mean) * rstd * w4.w + bb.w);
        xr[c] = make_float4(e0, e1, e2, e3);
        t += e0*wr.x + e1*wr.y + e2*wr.z + e3*wr.w;
        r += e0*wo.x + e1*wo.y + e2*wo.z + e3*wo.w;
    }
    t = warp_sum(t); r = warp_sum(r);
    if (lane == 0) { T[n] = t; R[n] = r; }
}

// ---------------- SAG pooling ----------------
__global__ void sag_edge_k(const int* __restrict__ src, const int* __restrict__ dst, int E,
                           const float* __restrict__ T, float* __restrict__ agg) {
    int e = blockIdx.x * blockDim.x + threadIdx.x;
    if (e < E) atomicAdd(&agg[dst[e]], T[src[e]]);
}

__global__ void sag_spre_k(const float* __restrict__ agg, const float* __restrict__ R,
                           const float* __restrict__ brel, const int* __restrict__ batch,
                           float* __restrict__ spre, float* __restrict__ sgm, int N) {
    int i = blockIdx.x * blockDim.x + threadIdx.x;
    if (i >= N) return;
    float s = agg[i] + brel[0] + R[i];
    spre[i] = s;
    atomicMaxF(&sgm[batch[i]], s);
}

__global__ void sag_z_k(const float* __restrict__ spre, const int* __restrict__ batch,
                        const float* __restrict__ sgm, float* __restrict__ sgz, int N) {
    int i = blockIdx.x * blockDim.x + threadIdx.x;
    if (i >= N) return;
    int g = batch[i];
    atomicAdd(&sgz[g], __expf(spre[i] - sgm[g]));
}

__global__ void sag_scale_k(float* __restrict__ x, const float* __restrict__ spre,
                            const float* __restrict__ sgm, const float* __restrict__ sgz,
                            const int* __restrict__ batch, float* __restrict__ G, int N) {
    long i = (long)blockIdx.x * blockDim.x + threadIdx.x;
    if (i >= (long)N * 50) return;
    int n = (int)(i / 50), q = (int)(i - (long)n * 50);
    int g = batch[n];
    float score = __expf(spre[n] - sgm[g]) / (sgz[g] + 1e-16f);
    float4 v = *(float4*)(x + (size_t)n * DIM + 4 * q);
    v.x *= score; v.y *= score; v.z *= score; v.w *= score;
    *(float4*)(x + (size_t)n * DIM + 4 * q) = v;
    float* p = G + (size_t)g * DIM + 4 * q;
    asm volatile("red.global.add.v4.f32 [%0], {%1,%2,%3,%4};"
                 :: "l"(p), "f"(v.x), "f"(v.y), "f"(v.z), "f"(v.w) : "memory");
}

// ---------------- host orchestration ----------------
static void launch_edge_acc(const int* src, const int* dst, int E, int nloop,
                            const float* ALS, const float* ALD, const float* HS,
                            float* Z, float* out, int coloff) {
    long tot = (long)E + nloop;
    long nw = (tot + 1) / 2;
    edge_acc_k<<<(nw * 32 + 255) / 256, 256>>>(src, dst, E, nloop, ALS, ALD, HS, Z, out, coloff);
}

static void run_ln(float* x, const int* batch,
                   const float* z1, const float* z2,
                   const float* b1, const float* b2,
                   const float* lnw, const float* lnb,
                   const float* Wrel, const float* Wroot,
                   float* T, float* R, int N, float* CNT) {
    ln_stats_fused_k<<<(N * 32 + 255) / 256, 256>>>(x, z1, z2, b1, b2, batch,
                                                    CNT, CNT + NB, CNT + 2 * NB, N);
    ln_apply_fused_k<<<(N * 32 + 255) / 256, 256>>>(x, z1, z2, b1, b2, batch,
                                                    CNT, CNT + NB, CNT + 2 * NB,
                                                    lnw, lnb, Wrel, Wroot, T, R, N);
}

static void run_sag_scalars(const int* src, const int* dst, int E, const int* batch,
                            const float* brel, const float* T, const float* R,
                            float* AGG, float* SPRE, float* SGM, float* SGZ, int N) {
    sag_edge_k<<<(E + 255) / 256, 256>>>(src, dst, E, T, AGG);
    sag_spre_k<<<(N + 255) / 256, 256>>>(AGG, R, brel, batch, SPRE, SGM, N);
    sag_z_k<<<(N + 255) / 256, 256>>>(SPRE, batch, SGM, SGZ, N);
}

extern "C" void kernel_launch(void* const* d_in, const int* in_sizes, int n_in,
                              void* d_out, int out_size) {
    const float* atom_x  = (const float*)d_in[0];
    const int*   aei     = (const int*)  d_in[1];
    const int*   abatch  = (const int*)  d_in[2];
    const float* aa_x    = (const float*)d_in[3];
    const int*   pei     = (const int*)  d_in[4];
    // d_in[5] = aa_edge_attr (unused by reference)
    const int*   pbatch  = (const int*)  d_in[6];
    const int*   m2p     = (const int*)  d_in[7];
    const float* Wd      = (const float*)d_in[8];
    const float* ad_src  = (const float*)d_in[9];
    const float* ad_dst  = (const float*)d_in[10];
    const float* bd      = (const float*)d_in[11];
    const float* Wp      = (const float*)d_in[12];
    const float* ap_src  = (const float*)d_in[13];
    const float* ap_dst  = (const float*)d_in[14];
    const float* bp      = (const float*)d_in[15];
    const float* Wi_src  = (const float*)d_in[16];
    const float* Wi_dst  = (const float*)d_in[17];
    const float* ai_src  = (const float*)d_in[18];
    const float* ai_dst  = (const float*)d_in[19];
    const float* bi      = (const float*)d_in[20];
    const float* ln_d_w  = (const float*)d_in[21];
    const float* ln_d_b  = (const float*)d_in[22];
    const float* ln_p_w  = (const float*)d_in[23];
    const float* ln_p_b  = (const float*)d_in[24];
    const float* pd_Wrel = (const float*)d_in[25];
    const float* pd_brel = (const float*)d_in[26];
    const float* pd_Wroot= (const float*)d_in[27];
    const float* pp_Wrel = (const float*)d_in[28];
    const float* pp_brel = (const float*)d_in[29];
    const float* pp_Wroot= (const float*)d_in[30];

    cudaFuncSetAttribute(gemm3_k, cudaFuncAttributeMaxDynamicSharedMemorySize, (int)GEMM_SMEM);

    float* S = nullptr;
    cudaGetSymbolAddress((void**)&S, g_scratch);

    float* HSA   = S + OFF_HSA;
    float* HSB   = S + OFF_HSB;
    float* ALS1  = S + OFF_ALS1;
    float* ALD1  = S + OFF_ALD1;
    float* ALS2  = S + OFF_ALS2;
    float* ALD2  = S + OFF_ALD2;
    float* ZA1   = S + OFF_ZA1;
    float* ZA2   = S + OFF_ZA2;
    float* ZP1   = S + OFF_ZP1;
    float* ZP2   = S + OFF_ZP2;
    float* AGGA  = S + OFF_AGGA;
    float* AGGP  = S + OFF_AGGP;
    float* SGZA  = S + OFF_SGZA;
    float* SGZP  = S + OFF_SGZP;
    float* CNTA  = S + OFF_CNTA;
    float* CNTP  = S + OFF_CNTP;
    float* SGMA  = S + OFF_SGMA;
    float* SGMP  = S + OFF_SGMP;
    float* V     = S + OFF_V;
    float* T     = S + OFF_T;
    float* R     = S + OFF_R;
    float* SPREA = S + OFF_SPREA;
    float* SPREP = S + OFF_SPREP;

    float* out = (float*)d_out;
    float* OA  = out;                                  // atom_h -> atom_out [25600,200]
    float* OP  = out + (size_t)NATOM * DIM;            // aa_h -> aa_out    [204800,200]
    float* DG  = out + (size_t)(NATOM + NAA) * DIM;    // drug_g [512,200]
    float* PG  = DG + (size_t)NB * DIM;                // prot_g [512,200]

    // one memset for all accumulators + the output
    cudaMemsetAsync(d_out, 0, (size_t)out_size * sizeof(float));
    cudaMemsetAsync(S + OFF_ZSTART, 0, (size_t)(OFF_ZEND - OFF_ZSTART) * sizeof(float));
    fill_k<<<(1024 + 255) / 256, 256>>>(SGMA, -1e30f, 1024);   // SGMA|SGMP contiguous

    const int* a_src_e = aei;
    const int* a_dst_e = aei + EATOM;
    const int* p_src_e = pei;
    const int* p_dst_e = pei + EAA;
    const int* m_atom  = m2p;
    const int* m_aa    = m2p + EM2P;
    const int  nloop_i = NATOM;   // min(NATOM, NAA)

    // shared inter-GAT dst fold: V = Wi_dst @ ai_dst (same for both directions)
    fold_v_k<<<2, 256>>>(Wi_dst, ai_dst, V);

    // ============ atom phase ============
    gemm3_k<<<(NATOM + 127) / 128, 400, GEMM_SMEM>>>(atom_x, Wd, HSA, ALS1, ad_src, ad_dst, ALD1,
                                                     V, ALD2, NATOM, 1);
    gemm3_k<<<(NAA + 127) / 128, 400, GEMM_SMEM>>>(aa_x, Wi_src, HSB, ALS2, ai_src, ai_dst, nullptr,
                                                   nullptr, nullptr, NAA, 1);

    launch_edge_acc(a_src_e, a_dst_e, EATOM, NATOM, ALS1, ALD1, HSA, ZA1, OA, 0);
    launch_edge_acc(m_aa, m_atom, EM2P, nloop_i, ALS2, ALD2, HSB, ZA2, OA, HCD);

    run_ln(OA, abatch, ZA1, ZA2, bd, bi, ln_d_w, ln_d_b,
           pd_Wrel, pd_Wroot, T, R, NATOM, CNTA);
    run_sag_scalars(a_src_e, a_dst_e, EATOM, abatch, pd_brel, T, R,
                    AGGA, SPREA, SGMA, SGZA, NATOM);

    // ============ aa phase ============
    gemm3_k<<<(NAA + 127) / 128, 400, GEMM_SMEM>>>(aa_x, Wp, HSB, ALS1, ap_src, ap_dst, ALD1,
                                                   V, ALD2, NAA, 1);
    gemm3_k<<<(NATOM + 127) / 128, 400, GEMM_SMEM>>>(OA, Wi_src, HSA, ALS2, ai_src, ai_dst, nullptr,
                                                     nullptr, nullptr, NATOM, 0);

    // DEFERRED atom SAG scale: OA -> atom_out (after OA consumed above)
    sag_scale_k<<<((long)NATOM * 50 + 255) / 256, 256>>>(OA, SPREA, SGMA, SGZA, abatch, DG, NATOM);

    launch_edge_acc(p_src_e, p_dst_e, EAA, NAA, ALS1, ALD1, HSB, ZP1, OP, 0);
    launch_edge_acc(m_atom, m_aa, EM2P, nloop_i, ALS2, ALD2, HSA, ZP2, OP, HCD);

    run_ln(OP, pbatch, ZP1, ZP2, bp, bi, ln_p_w, ln_p_b,
           pp_Wrel, pp_Wroot, T, R, NAA, CNTP);
    run_sag_scalars(p_src_e, p_dst_e, EAA, pbatch, pp_brel, T, R,
                    AGGP, SPREP, SGMP, SGZP, NAA);
    sag_scale_k<<<((long)NAA * 50 + 255) / 256, 256>>>(OP, SPREP, SGMP, SGZP, pbatch, PG, NAA);
}

// round 7
// speedup vs baseline: 1.8405x; 1.1233x over previous
#include <cuda_runtime.h>
#include <cuda_bf16.h>
#include <cstdint>

// ---------------- problem constants ----------------
#define NATOM 25600
#define NAA   204800
#define EATOM 102400
#define EAA   1024000
#define EM2P  512000
#define DIM   200
#define HCD   100
#define NB    512

// ---------------- scratch layout (floats) ----------------
static const long OFF_HSA   = 0;                         // 2,560,000
static const long OFF_HSB   = 2560000L;                  // 20,480,000
static const long OFF_ALS1  = 23040000L;                 // 409,600
static const long OFF_ALD1  = 23449600L;
static const long OFF_ALS2  = 23859200L;
static const long OFF_ALD2  = 24268800L;
// ---- zero block (one memset) ----
static const long OFF_ZSTART= 24678400L;
static const long OFF_ZA1   = 24678400L;                 // 2*NATOM
static const long OFF_ZA2   = 24729600L;                 // 2*NATOM
static const long OFF_ZP1   = 24780800L;                 // 2*NAA
static const long OFF_ZP2   = 25190400L;                 // 2*NAA
static const long OFF_AGGA  = 25600000L;                 // NATOM
static const long OFF_AGGP  = 25625600L;                 // NAA
static const long OFF_SGZA  = 25830400L;                 // 512
static const long OFF_SGZP  = 25830912L;                 // 512
static const long OFF_CNTA  = 25831424L;                 // 3*512
static const long OFF_CNTP  = 25832960L;                 // 3*512
static const long OFF_ZEND  = 25834496L;
// ---- fill block (-1e30, one fill) ----
static const long OFF_SGMA  = 25834496L;                 // 512
static const long OFF_SGMP  = 25835008L;                 // 512
// ---- rest ----
static const long OFF_V     = 25835520L;                 // 512
static const long OFF_T     = 25836032L;                 // NAA
static const long OFF_R     = 26040832L;                 // NAA
static const long OFF_SPREA = 26245632L;                 // NATOM
static const long OFF_SPREP = 26271232L;                 // NAA
static const long SCRATCH_FLOATS = 26476032L;

__device__ __align__(256) float g_scratch[SCRATCH_FLOATS];

// ---------------- device helpers ----------------
__device__ __forceinline__ float eluf(float x)  { return x > 0.f ? x : expm1f(x); }
__device__ __forceinline__ float lreluf(float x){ return x > 0.f ? x : 0.2f * x; }

__device__ __forceinline__ void atomicMaxF(float* a, float v) {
    if (v >= 0.f) atomicMax((int*)a, __float_as_int(v));
    else          atomicMin((unsigned int*)a, __float_as_uint(v));
}

__device__ __forceinline__ float warp_sum(float v) {
    #pragma unroll
    for (int o = 16; o > 0; o >>= 1) v += __shfl_down_sync(0xffffffffu, v, o);
    return v;
}

// ---------------- generic small kernels ----------------
__global__ void fill_k(float* p, float v, int n) {
    int i = blockIdx.x * blockDim.x + threadIdx.x;
    if (i < n) p[i] = v;
}

// ---------------- GEMM v4: 128 rows/block, 400 threads, K chunked by 100 ------
// smem 91.2KB -> 2 blocks/SM (25 warps/SM) vs v3's 1 block (12.5 warps).
#define KC 100
#define GEMM_SMEM (size_t)((10000 + 12800) * sizeof(float))
__global__ void __launch_bounds__(400, 2)
gemm4_k(const float* __restrict__ X, const float* __restrict__ W,
        float* __restrict__ Y, float* __restrict__ ALS,
        const float* __restrict__ a_src, const float* __restrict__ a_dst,
        float* __restrict__ ALD,
        const float* __restrict__ Vg, float* __restrict__ XALD,
        int N, int do_elu) {
    extern __shared__ float sm[];
    float* Ws = sm;               // 10000 : chunk [k][c]
    float* Xs = sm + 10000;       // 12800 : chunk [k][r], stride 128
    __shared__ float Vs[400];

    int tid = threadIdx.x;
    int tx = tid % 25, ty = tid / 25;
    int row0 = blockIdx.x * 128;

    if (XALD && tid < 400) Vs[tid] = Vg[tid];

    float acc[8][4];
    #pragma unroll
    for (int r = 0; r < 8; r++)
        #pragma unroll
        for (int c = 0; c < 4; c++) acc[r][c] = 0.f;
    float xd0 = 0.f, xd1 = 0.f;   // XALD accumulators (tid<128)

    #pragma unroll
    for (int kc = 0; kc < 2; kc++) {
        // load W chunk: 10000 floats = 2500 float4
        const float4* Wg = (const float4*)(W + (size_t)kc * KC * HCD);
        for (int i = tid; i < 2500; i += 400)
            ((float4*)Ws)[i] = Wg[i];
        // load X chunk: 128 rows x 25 float4
        for (int i = tid; i < 3200; i += 400) {
            int r = i & 127, kq = i >> 7;   // kq 0..24
            int row = row0 + r;
            float4 v = make_float4(0.f, 0.f, 0.f, 0.f);
            if (row < N) v = ((const float4*)(X + (size_t)row * DIM))[kc * 25 + kq];
            if (do_elu) { v.x = eluf(v.x); v.y = eluf(v.y); v.z = eluf(v.z); v.w = eluf(v.w); }
            int kb = kq * 4;
            Xs[(kb + 0) * 128 + r] = v.x;
            Xs[(kb + 1) * 128 + r] = v.y;
            Xs[(kb + 2) * 128 + r] = v.z;
            Xs[(kb + 3) * 128 + r] = v.w;
        }
        __syncthreads();

        const float* wp = Ws + 4 * tx;
        const float* xp = Xs + 8 * ty;
        #pragma unroll 4
        for (int k = 0; k < KC; k++) {
            float4 w4 = *(const float4*)(wp + k * HCD);
            float4 xa = *(const float4*)(xp + k * 128);
            float4 xb = *(const float4*)(xp + k * 128 + 4);
            float xr[8] = {xa.x, xa.y, xa.z, xa.w, xb.x, xb.y, xb.z, xb.w};
            #pragma unroll
            for (int r = 0; r < 8; r++) {
                acc[r][0] += xr[r] * w4.x;
                acc[r][1] += xr[r] * w4.y;
                acc[r][2] += xr[r] * w4.z;
                acc[r][3] += xr[r] * w4.w;
            }
        }
        if (XALD && tid < 128) {
            int r = tid;
            #pragma unroll 4
            for (int k = 0; k < KC; k++) {
                float x = Xs[k * 128 + r];
                xd0 += x * Vs[2 * (kc * KC + k)];
                xd1 += x * Vs[2 * (kc * KC + k) + 1];
            }
        }
        __syncthreads();   // before overwriting smem (next chunk / partials)
    }

    if (XALD && tid < 128 && row0 + tid < N)
        ((float2*)XALD)[row0 + tid] = make_float2(xd0, xd1);

    // epilogue partials (reuse sm: 12800 floats needed, 22800 available)
    float* part_s = sm;          // 6400
    float* part_d = sm + 6400;   // 6400

    int c0 = 4 * tx;
    float4 af = *(const float4*)(a_src + c0);
    float4 bf = ALD ? *(const float4*)(a_dst + c0) : make_float4(0.f, 0.f, 0.f, 0.f);

    #pragma unroll
    for (int r = 0; r < 8; r++) {
        int lrow = 8 * ty + r;
        int row = row0 + lrow;
        float s0 = 0.f, s1 = 0.f, t0 = 0.f, t1 = 0.f;
        float ps[4] = {acc[r][0]*af.x, acc[r][1]*af.y, acc[r][2]*af.z, acc[r][3]*af.w};
        float pd[4] = {acc[r][0]*bf.x, acc[r][1]*bf.y, acc[r][2]*bf.z, acc[r][3]*bf.w};
        #pragma unroll
        for (int q = 0; q < 4; q++) {
            if (c0 + q < 50) { s0 += ps[q]; t0 += pd[q]; }
            else             { s1 += ps[q]; t1 += pd[q]; }
        }
        part_s[lrow * 50 + tx]      = s0;
        part_s[lrow * 50 + 25 + tx] = s1;
        part_d[lrow * 50 + tx]      = t0;
        part_d[lrow * 50 + 25 + tx] = t1;
        if (row < N)
            *(float4*)(Y + (size_t)row * HCD + c0) =
                make_float4(acc[r][0], acc[r][1], acc[r][2], acc[r][3]);
    }
    __syncthreads();

    if (tid < 256) {
        int r = tid >> 1, h = tid & 1;
        int row = row0 + r;
        if (row < N) {
            float s = 0.f, t = 0.f;
            const float* ps = part_s + r * 50 + h * 25;
            const float* pd = part_d + r * 50 + h * 25;
            #pragma unroll
            for (int i = 0; i < 25; i++) { s += ps[i]; t += pd[i]; }
            ALS[(size_t)row * 2 + h] = s;
            if (ALD) ALD[(size_t)row * 2 + h] = t;
        }
    }
}

// ---------------- fold v[k,h] = sum_c Wdst[k, h*50+c] * adst[h,c] -------------
__global__ void fold_v_k(const float* __restrict__ Wdst, const float* __restrict__ adst,
                         float* __restrict__ v) {
    int i = blockIdx.x * blockDim.x + threadIdx.x;
    if (i >= 2 * DIM) return;
    int k = i >> 1, h = i & 1;
    float s = 0.f;
    #pragma unroll
    for (int c = 0; c < 50; c++) s += Wdst[k * HCD + h * 50 + c] * adst[h * 50 + c];
    v[2 * k + h] = s;
}

// ---------------- edge pass: 2 edges per warp, MLP=2 --------------------------
__global__ void edge_acc_k(const int* __restrict__ src, const int* __restrict__ dst,
                           int E, int nloop,
                           const float* __restrict__ als, const float* __restrict__ ald,
                           const float* __restrict__ hs,
                           float* __restrict__ z, float* __restrict__ out, int coloff) {
    long w = ((long)blockIdx.x * blockDim.x + threadIdx.x) >> 5;
    int lane = threadIdx.x & 31;
    long tot = (long)E + nloop;
    long e0 = 2 * w, e1 = e0 + 1;
    if (e0 >= tot) return;
    bool has1 = (e1 < tot);

    int s0, d0, s1 = 0, d1 = 0;
    if (e0 < E) { s0 = src[e0]; d0 = dst[e0]; } else { s0 = d0 = (int)(e0 - E); }
    if (has1) {
        if (e1 < E) { s1 = src[e1]; d1 = dst[e1]; } else { s1 = d1 = (int)(e1 - E); }
    }
    float2 as0 = ((const float2*)als)[s0];
    float2 ad0 = ((const float2*)ald)[d0];
    float2 as1 = make_float2(0.f, 0.f), ad1 = make_float2(0.f, 0.f);
    if (has1) { as1 = ((const float2*)als)[s1]; ad1 = ((const float2*)ald)[d1]; }

    float ex00 = __expf(lreluf(as0.x + ad0.x));
    float ex01 = __expf(lreluf(as0.y + ad0.y));
    float ex10 = 0.f, ex11 = 0.f;
    if (has1) {
        ex10 = __expf(lreluf(as1.x + ad1.x));
        ex11 = __expf(lreluf(as1.y + ad1.y));
    }

    if (lane == 25) atomicAdd(&z[2 * d0],     ex00);
    if (lane == 26) atomicAdd(&z[2 * d0 + 1], ex01);
    if (has1 && lane == 27) atomicAdd(&z[2 * d1],     ex10);
    if (has1 && lane == 28) atomicAdd(&z[2 * d1 + 1], ex11);

    if (lane < 25) {
        int j = lane * 4;
        const float4 h0 = *(const float4*)(hs + (size_t)s0 * HCD + j);
        float4 h1 = make_float4(0.f, 0.f, 0.f, 0.f);
        if (has1) h1 = *(const float4*)(hs + (size_t)s1 * HCD + j);

        float w0 = (j     < 50 ? ex00 : ex01) * h0.x;
        float w1 = (j + 1 < 50 ? ex00 : ex01) * h0.y;
        float w2 = (j + 2 < 50 ? ex00 : ex01) * h0.z;
        float w3 = (j + 3 < 50 ? ex00 : ex01) * h0.w;
        float* p0 = out + (size_t)d0 * DIM + coloff + j;
        asm volatile("red.global.add.v4.f32 [%0], {%1,%2,%3,%4};"
                     :: "l"(p0), "f"(w0), "f"(w1), "f"(w2), "f"(w3) : "memory");
        if (has1) {
            float u0 = (j     < 50 ? ex10 : ex11) * h1.x;
            float u1 = (j + 1 < 50 ? ex10 : ex11) * h1.y;
            float u2 = (j + 2 < 50 ? ex10 : ex11) * h1.z;
            float u3 = (j + 3 < 50 ? ex10 : ex11) * h1.w;
            float* p1 = out + (size_t)d1 * DIM + coloff + j;
            asm volatile("red.global.add.v4.f32 [%0], {%1,%2,%3,%4};"
                         :: "l"(p1), "f"(u0), "f"(u1), "f"(u2), "f"(u3) : "memory");
        }
    }
}

// ---------------- fused: finalize (virtual) + LN stats + graph counts ---------
__global__ void ln_stats_fused_k(const float* __restrict__ out,
                                 const float* __restrict__ z1, const float* __restrict__ z2,
                                 const float* __restrict__ b1, const float* __restrict__ b2,
                                 const int* __restrict__ batch,
                                 float* __restrict__ cnt,
                                 float* __restrict__ gsum, float* __restrict__ gsq, int N) {
    int n = (blockIdx.x * blockDim.x + threadIdx.x) >> 5;
    int lane = threadIdx.x & 31;
    if (n >= N) return;
    float2 zz1 = ((const float2*)z1)[n];
    float2 zz2 = ((const float2*)z2)[n];
    float iz10 = 1.f / (zz1.x + 1e-16f), iz11 = 1.f / (zz1.y + 1e-16f);
    float iz20 = 1.f / (zz2.x + 1e-16f), iz21 = 1.f / (zz2.y + 1e-16f);
    const float4* xr = (const float4*)(out + (size_t)n * DIM);
    float s = 0.f, q = 0.f;
    #pragma unroll
    for (int c = lane; c < 50; c += 32) {
        float4 val = xr[c];
        int j = 4 * c;
        float4 b = (c < 25) ? ((const float4*)b1)[c] : ((const float4*)b2)[c - 25];
        float izA, izB;
        if (c < 25) { izA = iz10; izB = iz11; } else { izA = iz20; izB = iz21; }
        int jj = (c < 25) ? j : j - 100;
        float y0 = val.x * (jj     < 50 ? izA : izB) + b.x;
        float y1 = val.y * (jj + 1 < 50 ? izA : izB) + b.y;
        float y2 = val.z * (jj + 2 < 50 ? izA : izB) + b.z;
        float y3 = val.w * (jj + 3 < 50 ? izA : izB) + b.w;
        s += y0 + y1 + y2 + y3;
        q += y0*y0 + y1*y1 + y2*y2 + y3*y3;
    }
    s = warp_sum(s); q = warp_sum(q);
    if (lane == 0) {
        int g = batch[n];
        atomicAdd(&cnt[g], 1.f);
        atomicAdd(&gsum[g], s);
        atomicAdd(&gsq[g], q);
    }
}

// ---------------- fused: finalize + LN apply + elu + SAG T/R dots -------------
__global__ void ln_apply_fused_k(float* __restrict__ x,
                                 const float* __restrict__ z1, const float* __restrict__ z2,
                                 const float* __restrict__ b1, const float* __restrict__ b2,
                                 const int* __restrict__ batch,
                                 const float* __restrict__ cnt, const float* __restrict__ gsum,
                                 const float* __restrict__ gsq,
                                 const float* __restrict__ wv, const float* __restrict__ bv,
                                 const float* __restrict__ Wrel, const float* __restrict__ Wroot,
                                 float* __restrict__ T, float* __restrict__ R, int N) {
    int n = (blockIdx.x * blockDim.x + threadIdx.x) >> 5;
    int lane = threadIdx.x & 31;
    if (n >= N) return;
    int g = batch[n];
    float norm = fmaxf(cnt[g], 1.f) * (float)DIM;
    float mean = gsum[g] / norm;
    float var  = gsq[g] / norm - mean * mean;
    float rstd = rsqrtf(var + 1e-5f);
    float2 zz1 = ((const float2*)z1)[n];
    float2 zz2 = ((const float2*)z2)[n];
    float iz10 = 1.f / (zz1.x + 1e-16f), iz11 = 1.f / (zz1.y + 1e-16f);
    float iz20 = 1.f / (zz2.x + 1e-16f), iz21 = 1.f / (zz2.y + 1e-16f);
    float4* xr = (float4*)(x + (size_t)n * DIM);
    float t = 0.f, r = 0.f;
    #pragma unroll
    for (int c = lane; c < 50; c += 32) {
        float4 val = xr[c];
        int j = 4 * c;
        float4 b = (c < 25) ? ((const float4*)b1)[c] : ((const float4*)b2)[c - 25];
        float izA, izB;
        if (c < 25) { izA = iz10; izB = iz11; } else { izA = iz20; izB = iz21; }
        int jj = (c < 25) ? j : j - 100;
        float4 w4 = ((const float4*)wv)[c];
        float4 bb = ((const float4*)bv)[c];
        float4 wr = ((const float4*)Wrel)[c];
        float4 wo = ((const float4*)Wroot)[c];
        float y0 = val.x * (jj     < 50 ? izA : izB) + b.x;
        float y1 = val.y * (jj + 1 < 50 ? izA : izB) + b.y;
        float y2 = val.z * (jj + 2 < 50 ? izA : izB) + b.z;
        float y3 = val.w * (jj + 3 < 50 ? izA : izB) + b.w;
        float e0 = eluf((y0 - mean) * rstd * w4.x + bb.x);
        float e1 = eluf((y1 - mean) * rstd * w4.y + bb.y);
        float e2 = eluf((y2 - mean) * rstd * w4.z + bb.z);
        float e3 = eluf((y3 - mean) * rstd * w4.w + bb.w);
        xr[c] = make_float4(e0, e1, e2, e3);
        t += e0*wr.x + e1*wr.y + e2*wr.z + e3*wr.w;
        r += e0*wo.x + e1*wo.y + e2*wo.z + e3*wo.w;
    }
    t = warp_sum(t); r = warp_sum(r);
    if (lane == 0) { T[n] = t; R[n] = r; }
}

// ---------------- SAG pooling ----------------
__global__ void sag_edge_k(const int* __restrict__ src, const int* __restrict__ dst, int E,
                           const float* __restrict__ T, float* __restrict__ agg) {
    int e = blockIdx.x * blockDim.x + threadIdx.x;
    if (e < E) atomicAdd(&agg[dst[e]], T[src[e]]);
}

__global__ void sag_spre_k(const float* __restrict__ agg, const float* __restrict__ R,
                           const float* __restrict__ brel, const int* __restrict__ batch,
                           float* __restrict__ spre, float* __restrict__ sgm, int N) {
    int i = blockIdx.x * blockDim.x + threadIdx.x;
    if (i >= N) return;
    float s = agg[i] + brel[0] + R[i];
    spre[i] = s;
    atomicMaxF(&sgm[batch[i]], s);
}

__global__ void sag_z_k(const float* __restrict__ spre, const int* __restrict__ batch,
                        const float* __restrict__ sgm, float* __restrict__ sgz, int N) {
    int i = blockIdx.x * blockDim.x + threadIdx.x;
    if (i >= N) return;
    int g = batch[i];
    atomicAdd(&sgz[g], __expf(spre[i] - sgm[g]));
}

__global__ void sag_scale_k(float* __restrict__ x, const float* __restrict__ spre,
                            const float* __restrict__ sgm, const float* __restrict__ sgz,
                            const int* __restrict__ batch, float* __restrict__ G, int N) {
    long i = (long)blockIdx.x * blockDim.x + threadIdx.x;
    if (i >= (long)N * 50) return;
    int n = (int)(i / 50), q = (int)(i - (long)n * 50);
    int g = batch[n];
    float score = __expf(spre[n] - sgm[g]) / (sgz[g] + 1e-16f);
    float4 v = *(float4*)(x + (size_t)n * DIM + 4 * q);
    v.x *= score; v.y *= score; v.z *= score; v.w *= score;
    *(float4*)(x + (size_t)n * DIM + 4 * q) = v;
    float* p = G + (size_t)g * DIM + 4 * q;
    asm volatile("red.global.add.v4.f32 [%0], {%1,%2,%3,%4};"
                 :: "l"(p), "f"(v.x), "f"(v.y), "f"(v.z), "f"(v.w) : "memory");
}

// ---------------- host orchestration ----------------
static void launch_edge_acc(const int* src, const int* dst, int E, int nloop,
                            const float* ALS, const float* ALD, const float* HS,
                            float* Z, float* out, int coloff) {
    long tot = (long)E + nloop;
    long nw = (tot + 1) / 2;
    edge_acc_k<<<(nw * 32 + 255) / 256, 256>>>(src, dst, E, nloop, ALS, ALD, HS, Z, out, coloff);
}

static void run_ln(float* x, const int* batch,
                   const float* z1, const float* z2,
                   const float* b1, const float* b2,
                   const float* lnw, const float* lnb,
                   const float* Wrel, const float* Wroot,
                   float* T, float* R, int N, float* CNT) {
    ln_stats_fused_k<<<(N * 32 + 255) / 256, 256>>>(x, z1, z2, b1, b2, batch,
                                                    CNT, CNT + NB, CNT + 2 * NB, N);
    ln_apply_fused_k<<<(N * 32 + 255) / 256, 256>>>(x, z1, z2, b1, b2, batch,
                                                    CNT, CNT + NB, CNT + 2 * NB,
                                                    lnw, lnb, Wrel, Wroot, T, R, N);
}

static void run_sag_scalars(const int* src, const int* dst, int E, const int* batch,
                            const float* brel, const float* T, const float* R,
                            float* AGG, float* SPRE, float* SGM, float* SGZ, int N) {
    sag_edge_k<<<(E + 255) / 256, 256>>>(src, dst, E, T, AGG);
    sag_spre_k<<<(N + 255) / 256, 256>>>(AGG, R, brel, batch, SPRE, SGM, N);
    sag_z_k<<<(N + 255) / 256, 256>>>(SPRE, batch, SGM, SGZ, N);
}

extern "C" void kernel_launch(void* const* d_in, const int* in_sizes, int n_in,
                              void* d_out, int out_size) {
    const float* atom_x  = (const float*)d_in[0];
    const int*   aei     = (const int*)  d_in[1];
    const int*   abatch  = (const int*)  d_in[2];
    const float* aa_x    = (const float*)d_in[3];
    const int*   pei     = (const int*)  d_in[4];
    // d_in[5] = aa_edge_attr (unused by reference)
    const int*   pbatch  = (const int*)  d_in[6];
    const int*   m2p     = (const int*)  d_in[7];
    const float* Wd      = (const float*)d_in[8];
    const float* ad_src  = (const float*)d_in[9];
    const float* ad_dst  = (const float*)d_in[10];
    const float* bd      = (const float*)d_in[11];
    const float* Wp      = (const float*)d_in[12];
    const float* ap_src  = (const float*)d_in[13];
    const float* ap_dst  = (const float*)d_in[14];
    const float* bp      = (const float*)d_in[15];
    const float* Wi_src  = (const float*)d_in[16];
    const float* Wi_dst  = (const float*)d_in[17];
    const float* ai_src  = (const float*)d_in[18];
    const float* ai_dst  = (const float*)d_in[19];
    const float* bi      = (const float*)d_in[20];
    const float* ln_d_w  = (const float*)d_in[21];
    const float* ln_d_b  = (const float*)d_in[22];
    const float* ln_p_w  = (const float*)d_in[23];
    const float* ln_p_b  = (const float*)d_in[24];
    const float* pd_Wrel = (const float*)d_in[25];
    const float* pd_brel = (const float*)d_in[26];
    const float* pd_Wroot= (const float*)d_in[27];
    const float* pp_Wrel = (const float*)d_in[28];
    const float* pp_brel = (const float*)d_in[29];
    const float* pp_Wroot= (const float*)d_in[30];

    cudaFuncSetAttribute(gemm4_k, cudaFuncAttributeMaxDynamicSharedMemorySize, (int)GEMM_SMEM);

    float* S = nullptr;
    cudaGetSymbolAddress((void**)&S, g_scratch);

    float* HSA   = S + OFF_HSA;
    float* HSB   = S + OFF_HSB;
    float* ALS1  = S + OFF_ALS1;
    float* ALD1  = S + OFF_ALD1;
    float* ALS2  = S + OFF_ALS2;
    float* ALD2  = S + OFF_ALD2;
    float* ZA1   = S + OFF_ZA1;
    float* ZA2   = S + OFF_ZA2;
    float* ZP1   = S + OFF_ZP1;
    float* ZP2   = S + OFF_ZP2;
    float* AGGA  = S + OFF_AGGA;
    float* AGGP  = S + OFF_AGGP;
    float* SGZA  = S + OFF_SGZA;
    float* SGZP  = S + OFF_SGZP;
    float* CNTA  = S + OFF_CNTA;
    float* CNTP  = S + OFF_CNTP;
    float* SGMA  = S + OFF_SGMA;
    float* SGMP  = S + OFF_SGMP;
    float* V     = S + OFF_V;
    float* T     = S + OFF_T;
    float* R     = S + OFF_R;
    float* SPREA = S + OFF_SPREA;
    float* SPREP = S + OFF_SPREP;

    float* out = (float*)d_out;
    float* OA  = out;                                  // atom_h -> atom_out [25600,200]
    float* OP  = out + (size_t)NATOM * DIM;            // aa_h -> aa_out    [204800,200]
    float* DG  = out + (size_t)(NATOM + NAA) * DIM;    // drug_g [512,200]
    float* PG  = DG + (size_t)NB * DIM;                // prot_g [512,200]

    cudaMemsetAsync(d_out, 0, (size_t)out_size * sizeof(float));
    cudaMemsetAsync(S + OFF_ZSTART, 0, (size_t)(OFF_ZEND - OFF_ZSTART) * sizeof(float));
    fill_k<<<(1024 + 255) / 256, 256>>>(SGMA, -1e30f, 1024);   // SGMA|SGMP contiguous

    const int* a_src_e = aei;
    const int* a_dst_e = aei + EATOM;
    const int* p_src_e = pei;
    const int* p_dst_e = pei + EAA;
    const int* m_atom  = m2p;
    const int* m_aa    = m2p + EM2P;
    const int  nloop_i = NATOM;   // min(NATOM, NAA)

    // shared inter-GAT dst fold: V = Wi_dst @ ai_dst (same for both directions)
    fold_v_k<<<2, 256>>>(Wi_dst, ai_dst, V);

    // ============ atom phase ============
    gemm4_k<<<(NATOM + 127) / 128, 400, GEMM_SMEM>>>(atom_x, Wd, HSA, ALS1, ad_src, ad_dst, ALD1,
                                                     V, ALD2, NATOM, 1);
    gemm4_k<<<(NAA + 127) / 128, 400, GEMM_SMEM>>>(aa_x, Wi_src, HSB, ALS2, ai_src, ai_dst, nullptr,
                                                   nullptr, nullptr, NAA, 1);

    launch_edge_acc(a_src_e, a_dst_e, EATOM, NATOM, ALS1, ALD1, HSA, ZA1, OA, 0);
    launch_edge_acc(m_aa, m_atom, EM2P, nloop_i, ALS2, ALD2, HSB, ZA2, OA, HCD);

    run_ln(OA, abatch, ZA1, ZA2, bd, bi, ln_d_w, ln_d_b,
           pd_Wrel, pd_Wroot, T, R, NATOM, CNTA);
    run_sag_scalars(a_src_e, a_dst_e, EATOM, abatch, pd_brel, T, R,
                    AGGA, SPREA, SGMA, SGZA, NATOM);

    // ============ aa phase ============
    gemm4_k<<<(NAA + 127) / 128, 400, GEMM_SMEM>>>(aa_x, Wp, HSB, ALS1, ap_src, ap_dst, ALD1,
                                                   V, ALD2, NAA, 1);
    gemm4_k<<<(NATOM + 127) / 128, 400, GEMM_SMEM>>>(OA, Wi_src, HSA, ALS2, ai_src, ai_dst, nullptr,
                                                     nullptr, nullptr, NATOM, 0);

    // DEFERRED atom SAG scale: OA -> atom_out (after OA consumed above)
    sag_scale_k<<<((long)NATOM * 50 + 255) / 256, 256>>>(OA, SPREA, SGMA, SGZA, abatch, DG, NATOM);

    launch_edge_acc(p_src_e, p_dst_e, EAA, NAA, ALS1, ALD1, HSB, ZP1, OP, 0);
    launch_edge_acc(m_atom, m_aa, EM2P, nloop_i, ALS2, ALD2, HSA, ZP2, OP, HCD);

    run_ln(OP, pbatch, ZP1, ZP2, bp, bi, ln_p_w, ln_p_b,
           pp_Wrel, pp_Wroot, T, R, NAA, CNTP);
    run_sag_scalars(p_src_e, p_dst_e, EAA, pbatch, pp_brel, T, R,
                    AGGP, SPREP, SGMP, SGZP, NAA);
    sag_scale_k<<<((long)NAA * 50 + 255) / 256, 256>>>(OP, SPREP, SGMP, SGZP, pbatch, PG, NAA);
}

// round 8
// speedup vs baseline: 1.9227x; 1.0446x over previous
#include <cuda_runtime.h>
#include <cuda_bf16.h>
#include <cstdint>

// ---------------- problem constants ----------------
#define NATOM 25600
#define NAA   204800
#define EATOM 102400
#define EAA   1024000
#define EM2P  512000
#define DIM   200
#define HCD   100
#define NB    512

// ---------------- scratch layout (floats) ----------------
static const long OFF_HSA   = 0;                         // 2,560,000
static const long OFF_HSB   = 2560000L;                  // 20,480,000
static const long OFF_ALS1  = 23040000L;                 // 409,600
static const long OFF_ALD1  = 23449600L;
static const long OFF_ALS2  = 23859200L;
static const long OFF_ALD2  = 24268800L;
// ---- zero block (one memset) ----
static const long OFF_ZSTART= 24678400L;
static const long OFF_ZA1   = 24678400L;                 // 2*NATOM
static const long OFF_ZA2   = 24729600L;                 // 2*NATOM
static const long OFF_ZP1   = 24780800L;                 // 2*NAA
static const long OFF_ZP2   = 25190400L;                 // 2*NAA
static const long OFF_AGGA  = 25600000L;                 // NATOM
static const long OFF_AGGP  = 25625600L;                 // NAA
static const long OFF_SGZA  = 25830400L;                 // 512
static const long OFF_SGZP  = 25830912L;                 // 512
static const long OFF_CNTA  = 25831424L;                 // 3*512
static const long OFF_CNTP  = 25832960L;                 // 3*512
static const long OFF_ZEND  = 25834496L;
// ---- rest ----
static const long OFF_V     = 25835520L;                 // 512
static const long OFF_T     = 25836032L;                 // NAA
static const long OFF_R     = 26040832L;                 // NAA
static const long OFF_SPREA = 26245632L;                 // NATOM
static const long OFF_SPREP = 26271232L;                 // NAA
static const long SCRATCH_FLOATS = 26476032L;

__device__ __align__(256) float g_scratch[SCRATCH_FLOATS];

// ---------------- device helpers ----------------
__device__ __forceinline__ float eluf(float x)  { return x > 0.f ? x : expm1f(x); }
__device__ __forceinline__ float lreluf(float x){ return x > 0.f ? x : 0.2f * x; }

__device__ __forceinline__ float warp_sum(float v) {
    #pragma unroll
    for (int o = 16; o > 0; o >>= 1) v += __shfl_down_sync(0xffffffffu, v, o);
    return v;
}

// ---------------- GEMM v4: 128 rows/block, 400 threads, K chunked by 100 ------
#define KC 100
#define GEMM_SMEM (size_t)((10000 + 12800) * sizeof(float))
__global__ void __launch_bounds__(400, 2)
gemm4_k(const float* __restrict__ X, const float* __restrict__ W,
        float* __restrict__ Y, float* __restrict__ ALS,
        const float* __restrict__ a_src, const float* __restrict__ a_dst,
        float* __restrict__ ALD,
        const float* __restrict__ Vg, float* __restrict__ XALD,
        int N, int do_elu) {
    extern __shared__ float sm[];
    float* Ws = sm;               // 10000 : chunk [k][c]
    float* Xs = sm + 10000;       // 12800 : chunk [k][r], stride 128
    __shared__ float Vs[400];

    int tid = threadIdx.x;
    int tx = tid % 25, ty = tid / 25;
    int row0 = blockIdx.x * 128;

    if (XALD && tid < 400) Vs[tid] = Vg[tid];

    float acc[8][4];
    #pragma unroll
    for (int r = 0; r < 8; r++)
        #pragma unroll
        for (int c = 0; c < 4; c++) acc[r][c] = 0.f;
    float xd0 = 0.f, xd1 = 0.f;

    #pragma unroll
    for (int kc = 0; kc < 2; kc++) {
        const float4* Wg = (const float4*)(W + (size_t)kc * KC * HCD);
        for (int i = tid; i < 2500; i += 400)
            ((float4*)Ws)[i] = Wg[i];
        for (int i = tid; i < 3200; i += 400) {
            int r = i & 127, kq = i >> 7;
            int row = row0 + r;
            float4 v = make_float4(0.f, 0.f, 0.f, 0.f);
            if (row < N) v = ((const float4*)(X + (size_t)row * DIM))[kc * 25 + kq];
            if (do_elu) { v.x = eluf(v.x); v.y = eluf(v.y); v.z = eluf(v.z); v.w = eluf(v.w); }
            int kb = kq * 4;
            Xs[(kb + 0) * 128 + r] = v.x;
            Xs[(kb + 1) * 128 + r] = v.y;
            Xs[(kb + 2) * 128 + r] = v.z;
            Xs[(kb + 3) * 128 + r] = v.w;
        }
        __syncthreads();

        const float* wp = Ws + 4 * tx;
        const float* xp = Xs + 8 * ty;
        #pragma unroll 4
        for (int k = 0; k < KC; k++) {
            float4 w4 = *(const float4*)(wp + k * HCD);
            float4 xa = *(const float4*)(xp + k * 128);
            float4 xb = *(const float4*)(xp + k * 128 + 4);
            float xr[8] = {xa.x, xa.y, xa.z, xa.w, xb.x, xb.y, xb.z, xb.w};
            #pragma unroll
            for (int r = 0; r < 8; r++) {
                acc[r][0] += xr[r] * w4.x;
                acc[r][1] += xr[r] * w4.y;
                acc[r][2] += xr[r] * w4.z;
                acc[r][3] += xr[r] * w4.w;
            }
        }
        if (XALD && tid < 128) {
            int r = tid;
            #pragma unroll 4
            for (int k = 0; k < KC; k++) {
                float x = Xs[k * 128 + r];
                xd0 += x * Vs[2 * (kc * KC + k)];
                xd1 += x * Vs[2 * (kc * KC + k) + 1];
            }
        }
        __syncthreads();
    }

    if (XALD && tid < 128 && row0 + tid < N)
        ((float2*)XALD)[row0 + tid] = make_float2(xd0, xd1);

    float* part_s = sm;
    float* part_d = sm + 6400;

    int c0 = 4 * tx;
    float4 af = *(const float4*)(a_src + c0);
    float4 bf = ALD ? *(const float4*)(a_dst + c0) : make_float4(0.f, 0.f, 0.f, 0.f);

    #pragma unroll
    for (int r = 0; r < 8; r++) {
        int lrow = 8 * ty + r;
        int row = row0 + lrow;
        float s0 = 0.f, s1 = 0.f, t0 = 0.f, t1 = 0.f;
        float ps[4] = {acc[r][0]*af.x, acc[r][1]*af.y, acc[r][2]*af.z, acc[r][3]*af.w};
        float pd[4] = {acc[r][0]*bf.x, acc[r][1]*bf.y, acc[r][2]*bf.z, acc[r][3]*bf.w};
        #pragma unroll
        for (int q = 0; q < 4; q++) {
            if (c0 + q < 50) { s0 += ps[q]; t0 += pd[q]; }
            else             { s1 += ps[q]; t1 += pd[q]; }
        }
        part_s[lrow * 50 + tx]      = s0;
        part_s[lrow * 50 + 25 + tx] = s1;
        part_d[lrow * 50 + tx]      = t0;
        part_d[lrow * 50 + 25 + tx] = t1;
        if (row < N)
            *(float4*)(Y + (size_t)row * HCD + c0) =
                make_float4(acc[r][0], acc[r][1], acc[r][2], acc[r][3]);
    }
    __syncthreads();

    if (tid < 256) {
        int r = tid >> 1, h = tid & 1;
        int row = row0 + r;
        if (row < N) {
            float s = 0.f, t = 0.f;
            const float* ps = part_s + r * 50 + h * 25;
            const float* pd = part_d + r * 50 + h * 25;
            #pragma unroll
            for (int i = 0; i < 25; i++) { s += ps[i]; t += pd[i]; }
            ALS[(size_t)row * 2 + h] = s;
            if (ALD) ALD[(size_t)row * 2 + h] = t;
        }
    }
}

// ---------------- fold v[k,h] = sum_c Wdst[k, h*50+c] * adst[h,c] -------------
__global__ void fold_v_k(const float* __restrict__ Wdst, const float* __restrict__ adst,
                         float* __restrict__ v) {
    int i = blockIdx.x * blockDim.x + threadIdx.x;
    if (i >= 2 * DIM) return;
    int k = i >> 1, h = i & 1;
    float s = 0.f;
    #pragma unroll
    for (int c = 0; c < 50; c++) s += Wdst[k * HCD + h * 50 + c] * adst[h * 50 + c];
    v[2 * k + h] = s;
}

// ---------------- merged edge pass: both edge sets, 4 edges/warp --------------
// Set 1 -> out cols [0,100), z1. Set 2 -> out cols [100,200), z2.
__global__ void edge_acc2_k(
    const int* __restrict__ src1, const int* __restrict__ dst1, int E1, long tot1, long W1,
    const float* __restrict__ als1, const float* __restrict__ ald1,
    const float* __restrict__ hs1, float* __restrict__ z1,
    const int* __restrict__ src2, const int* __restrict__ dst2, int E2, long tot2,
    const float* __restrict__ als2, const float* __restrict__ ald2,
    const float* __restrict__ hs2, float* __restrict__ z2,
    float* __restrict__ out) {
    long gw = ((long)blockIdx.x * blockDim.x + threadIdx.x) >> 5;
    int lane = threadIdx.x & 31;

    const int *src, *dst;
    const float *als, *ald, *hs;
    float* z;
    int E, coloff;
    long e0, tot;
    if (gw < W1) {
        src = src1; dst = dst1; als = als1; ald = ald1; hs = hs1; z = z1;
        E = E1; coloff = 0; tot = tot1; e0 = gw * 4;
    } else {
        src = src2; dst = dst2; als = als2; ald = ald2; hs = hs2; z = z2;
        E = E2; coloff = HCD; tot = tot2; e0 = (gw - W1) * 4;
    }
    if (e0 >= tot) return;
    int ne = (int)((tot - e0 < 4) ? (tot - e0) : 4);

    int s[4], d[4];
    #pragma unroll
    for (int k = 0; k < 4; k++) {
        if (k < ne) {
            long e = e0 + k;
            if (e < E) { s[k] = src[e]; d[k] = dst[e]; }
            else       { s[k] = d[k] = (int)(e - E); }
        } else { s[k] = s[0]; d[k] = d[0]; }
    }

    float ex[4][2];
    #pragma unroll
    for (int k = 0; k < 4; k++) {
        float2 as = ((const float2*)als)[s[k]];
        float2 ad = ((const float2*)ald)[d[k]];
        ex[k][0] = __expf(lreluf(as.x + ad.x));
        ex[k][1] = __expf(lreluf(as.y + ad.y));
    }

    if (lane >= 24) {
        int kk = (lane - 24) >> 1, h = (lane - 24) & 1;
        if (kk < ne) atomicAdd(&z[2 * d[kk] + h], ex[kk][h]);
    }

    if (lane < 25) {
        int j = lane * 4;
        float4 h4[4];
        #pragma unroll
        for (int k = 0; k < 4; k++)
            if (k < ne) h4[k] = *(const float4*)(hs + (size_t)s[k] * HCD + j);
        #pragma unroll
        for (int k = 0; k < 4; k++) {
            if (k < ne) {
                float w0 = (j     < 50 ? ex[k][0] : ex[k][1]) * h4[k].x;
                float w1 = (j + 1 < 50 ? ex[k][0] : ex[k][1]) * h4[k].y;
                float w2 = (j + 2 < 50 ? ex[k][0] : ex[k][1]) * h4[k].z;
                float w3 = (j + 3 < 50 ? ex[k][0] : ex[k][1]) * h4[k].w;
                float* p = out + (size_t)d[k] * DIM + coloff + j;
                asm volatile("red.global.add.v4.f32 [%0], {%1,%2,%3,%4};"
                             :: "l"(p), "f"(w0), "f"(w1), "f"(w2), "f"(w3) : "memory");
            }
        }
    }
}

// ---------------- fused: finalize (virtual) + LN stats + graph counts ---------
__global__ void ln_stats_fused_k(const float* __restrict__ out,
                                 const float* __restrict__ z1, const float* __restrict__ z2,
                                 const float* __restrict__ b1, const float* __restrict__ b2,
                                 const int* __restrict__ batch,
                                 float* __restrict__ cnt,
                                 float* __restrict__ gsum, float* __restrict__ gsq, int N) {
    int n = (blockIdx.x * blockDim.x + threadIdx.x) >> 5;
    int lane = threadIdx.x & 31;
    if (n >= N) return;
    float2 zz1 = ((const float2*)z1)[n];
    float2 zz2 = ((const float2*)z2)[n];
    float iz10 = 1.f / (zz1.x + 1e-16f), iz11 = 1.f / (zz1.y + 1e-16f);
    float iz20 = 1.f / (zz2.x + 1e-16f), iz21 = 1.f / (zz2.y + 1e-16f);
    const float4* xr = (const float4*)(out + (size_t)n * DIM);
    float s = 0.f, q = 0.f;
    #pragma unroll
    for (int c = lane; c < 50; c += 32) {
        float4 val = xr[c];
        int j = 4 * c;
        float4 b = (c < 25) ? ((const float4*)b1)[c] : ((const float4*)b2)[c - 25];
        float izA, izB;
        if (c < 25) { izA = iz10; izB = iz11; } else { izA = iz20; izB = iz21; }
        int jj = (c < 25) ? j : j - 100;
        float y0 = val.x * (jj     < 50 ? izA : izB) + b.x;
        float y1 = val.y * (jj + 1 < 50 ? izA : izB) + b.y;
        float y2 = val.z * (jj + 2 < 50 ? izA : izB) + b.z;
        float y3 = val.w * (jj + 3 < 50 ? izA : izB) + b.w;
        s += y0 + y1 + y2 + y3;
        q += y0*y0 + y1*y1 + y2*y2 + y3*y3;
    }
    s = warp_sum(s); q = warp_sum(q);
    if (lane == 0) {
        int g = batch[n];
        atomicAdd(&cnt[g], 1.f);
        atomicAdd(&gsum[g], s);
        atomicAdd(&gsq[g], q);
    }
}

// ---------------- fused: finalize + LN apply + elu + SAG T/R dots -------------
__global__ void ln_apply_fused_k(float* __restrict__ x,
                                 const float* __restrict__ z1, const float* __restrict__ z2,
                                 const float* __restrict__ b1, const float* __restrict__ b2,
                                 const int* __restrict__ batch,
                                 const float* __restrict__ cnt, const float* __restrict__ gsum,
                                 const float* __restrict__ gsq,
                                 const float* __restrict__ wv, const float* __restrict__ bv,
                                 const float* __restrict__ Wrel, const float* __restrict__ Wroot,
                                 float* __restrict__ T, float* __restrict__ R, int N) {
    int n = (blockIdx.x * blockDim.x + threadIdx.x) >> 5;
    int lane = threadIdx.x & 31;
    if (n >= N) return;
    int g = batch[n];
    float norm = fmaxf(cnt[g], 1.f) * (float)DIM;
    float mean = gsum[g] / norm;
    float var  = gsq[g] / norm - mean * mean;
    float rstd = rsqrtf(var + 1e-5f);
    float2 zz1 = ((const float2*)z1)[n];
    float2 zz2 = ((const float2*)z2)[n];
    float iz10 = 1.f / (zz1.x + 1e-16f), iz11 = 1.f / (zz1.y + 1e-16f);
    float iz20 = 1.f / (zz2.x + 1e-16f), iz21 = 1.f / (zz2.y + 1e-16f);
    float4* xr = (float4*)(x + (size_t)n * DIM);
    float t = 0.f, r = 0.f;
    #pragma unroll
    for (int c = lane; c < 50; c += 32) {
        float4 val = xr[c];
        int j = 4 * c;
        float4 b = (c < 25) ? ((const float4*)b1)[c] : ((const float4*)b2)[c - 25];
        float izA, izB;
        if (c < 25) { izA = iz10; izB = iz11; } else { izA = iz20; izB = iz21; }
        int jj = (c < 25) ? j : j - 100;
        float4 w4 = ((const float4*)wv)[c];
        float4 bb = ((const float4*)bv)[c];
        float4 wr = ((const float4*)Wrel)[c];
        float4 wo = ((const float4*)Wroot)[c];
        float y0 = val.x * (jj     < 50 ? izA : izB) + b.x;
        float y1 = val.y * (jj + 1 < 50 ? izA : izB) + b.y;
        float y2 = val.z * (jj + 2 < 50 ? izA : izB) + b.z;
        float y3 = val.w * (jj + 3 < 50 ? izA : izB) + b.w;
        float e0 = eluf((y0 - mean) * rstd * w4.x + bb.x);
        float e1 = eluf((y1 - mean) * rstd * w4.y + bb.y);
        float e2 = eluf((y2 - mean) * rstd * w4.z + bb.z);
        float e3 = eluf((y3 - mean) * rstd * w4.w + bb.w);
        xr[c] = make_float4(e0, e1, e2, e3);
        t += e0*wr.x + e1*wr.y + e2*wr.z + e3*wr.w;
        r += e0*wo.x + e1*wo.y + e2*wo.z + e3*wo.w;
    }
    t = warp_sum(t); r = warp_sum(r);
    if (lane == 0) { T[n] = t; R[n] = r; }
}

// ---------------- SAG pooling (no-max softmax) ----------------
__global__ void sag_edge_k(const int* __restrict__ src, const int* __restrict__ dst, int E,
                           const float* __restrict__ T, float* __restrict__ agg) {
    int e = blockIdx.x * blockDim.x + threadIdx.x;
    if (e < E) atomicAdd(&agg[dst[e]], T[src[e]]);
}

// spre + per-graph z accumulation in one pass (no max subtraction)
__global__ void sag_spre_k(const float* __restrict__ agg, const float* __restrict__ R,
                           const float* __restrict__ brel, const int* __restrict__ batch,
                           float* __restrict__ spre, float* __restrict__ sgz, int N) {
    int i = blockIdx.x * blockDim.x + threadIdx.x;
    if (i >= N) return;
    float s = agg[i] + brel[0] + R[i];
    spre[i] = s;
    atomicAdd(&sgz[batch[i]], __expf(s));
}

__global__ void sag_scale_k(float* __restrict__ x, const float* __restrict__ spre,
                            const float* __restrict__ sgz,
                            const int* __restrict__ batch, float* __restrict__ G, int N) {
    long i = (long)blockIdx.x * blockDim.x + threadIdx.x;
    if (i >= (long)N * 50) return;
    int n = (int)(i / 50), q = (int)(i - (long)n * 50);
    int g = batch[n];
    float score = __expf(spre[n]) / (sgz[g] + 1e-16f);
    float4 v = *(float4*)(x + (size_t)n * DIM + 4 * q);
    v.x *= score; v.y *= score; v.z *= score; v.w *= score;
    *(float4*)(x + (size_t)n * DIM + 4 * q) = v;
    float* p = G + (size_t)g * DIM + 4 * q;
    asm volatile("red.global.add.v4.f32 [%0], {%1,%2,%3,%4};"
                 :: "l"(p), "f"(v.x), "f"(v.y), "f"(v.z), "f"(v.w) : "memory");
}

// ---------------- host orchestration ----------------
static void launch_edge_acc2(const int* src1, const int* dst1, int E1, int nloop1,
                             const float* als1, const float* ald1, const float* hs1, float* z1,
                             const int* src2, const int* dst2, int E2, int nloop2,
                             const float* als2, const float* ald2, const float* hs2, float* z2,
                             float* out) {
    long tot1 = (long)E1 + nloop1, tot2 = (long)E2 + nloop2;
    long W1 = (tot1 + 3) / 4, W2 = (tot2 + 3) / 4;
    long WT = W1 + W2;
    edge_acc2_k<<<(WT * 32 + 255) / 256, 256>>>(
        src1, dst1, E1, tot1, W1, als1, ald1, hs1, z1,
        src2, dst2, E2, tot2, als2, ald2, hs2, z2, out);
}

static void run_ln(float* x, const int* batch,
                   const float* z1, const float* z2,
                   const float* b1, const float* b2,
                   const float* lnw, const float* lnb,
                   const float* Wrel, const float* Wroot,
                   float* T, float* R, int N, float* CNT) {
    ln_stats_fused_k<<<(N * 32 + 255) / 256, 256>>>(x, z1, z2, b1, b2, batch,
                                                    CNT, CNT + NB, CNT + 2 * NB, N);
    ln_apply_fused_k<<<(N * 32 + 255) / 256, 256>>>(x, z1, z2, b1, b2, batch,
                                                    CNT, CNT + NB, CNT + 2 * NB,
                                                    lnw, lnb, Wrel, Wroot, T, R, N);
}

extern "C" void kernel_launch(void* const* d_in, const int* in_sizes, int n_in,
                              void* d_out, int out_size) {
    const float* atom_x  = (const float*)d_in[0];
    const int*   aei     = (const int*)  d_in[1];
    const int*   abatch  = (const int*)  d_in[2];
    const float* aa_x    = (const float*)d_in[3];
    const int*   pei     = (const int*)  d_in[4];
    // d_in[5] = aa_edge_attr (unused by reference)
    const int*   pbatch  = (const int*)  d_in[6];
    const int*   m2p     = (const int*)  d_in[7];
    const float* Wd      = (const float*)d_in[8];
    const float* ad_src  = (const float*)d_in[9];
    const float* ad_dst  = (const float*)d_in[10];
    const float* bd      = (const float*)d_in[11];
    const float* Wp      = (const float*)d_in[12];
    const float* ap_src  = (const float*)d_in[13];
    const float* ap_dst  = (const float*)d_in[14];
    const float* bp      = (const float*)d_in[15];
    const float* Wi_src  = (const float*)d_in[16];
    const float* Wi_dst  = (const float*)d_in[17];
    const float* ai_src  = (const float*)d_in[18];
    const float* ai_dst  = (const float*)d_in[19];
    const float* bi      = (const float*)d_in[20];
    const float* ln_d_w  = (const float*)d_in[21];
    const float* ln_d_b  = (const float*)d_in[22];
    const float* ln_p_w  = (const float*)d_in[23];
    const float* ln_p_b  = (const float*)d_in[24];
    const float* pd_Wrel = (const float*)d_in[25];
    const float* pd_brel = (const float*)d_in[26];
    const float* pd_Wroot= (const float*)d_in[27];
    const float* pp_Wrel = (const float*)d_in[28];
    const float* pp_brel = (const float*)d_in[29];
    const float* pp_Wroot= (const float*)d_in[30];

    cudaFuncSetAttribute(gemm4_k, cudaFuncAttributeMaxDynamicSharedMemorySize, (int)GEMM_SMEM);

    float* S = nullptr;
    cudaGetSymbolAddress((void**)&S, g_scratch);

    float* HSA   = S + OFF_HSA;
    float* HSB   = S + OFF_HSB;
    float* ALS1  = S + OFF_ALS1;
    float* ALD1  = S + OFF_ALD1;
    float* ALS2  = S + OFF_ALS2;
    float* ALD2  = S + OFF_ALD2;
    float* ZA1   = S + OFF_ZA1;
    float* ZA2   = S + OFF_ZA2;
    float* ZP1   = S + OFF_ZP1;
    float* ZP2   = S + OFF_ZP2;
    float* AGGA  = S + OFF_AGGA;
    float* AGGP  = S + OFF_AGGP;
    float* SGZA  = S + OFF_SGZA;
    float* SGZP  = S + OFF_SGZP;
    float* CNTA  = S + OFF_CNTA;
    float* CNTP  = S + OFF_CNTP;
    float* V     = S + OFF_V;
    float* T     = S + OFF_T;
    float* R     = S + OFF_R;
    float* SPREA = S + OFF_SPREA;
    float* SPREP = S + OFF_SPREP;

    float* out = (float*)d_out;
    float* OA  = out;                                  // atom_h -> atom_out [25600,200]
    float* OP  = out + (size_t)NATOM * DIM;            // aa_h -> aa_out    [204800,200]
    float* DG  = out + (size_t)(NATOM + NAA) * DIM;    // drug_g [512,200]
    float* PG  = DG + (size_t)NB * DIM;                // prot_g [512,200]

    cudaMemsetAsync(d_out, 0, (size_t)out_size * sizeof(float));
    cudaMemsetAsync(S + OFF_ZSTART, 0, (size_t)(OFF_ZEND - OFF_ZSTART) * sizeof(float));

    const int* a_src_e = aei;
    const int* a_dst_e = aei + EATOM;
    const int* p_src_e = pei;
    const int* p_dst_e = pei + EAA;
    const int* m_atom  = m2p;
    const int* m_aa    = m2p + EM2P;
    const int  nloop_i = NATOM;   // min(NATOM, NAA)

    // shared inter-GAT dst fold: V = Wi_dst @ ai_dst (same for both directions)
    fold_v_k<<<2, 256>>>(Wi_dst, ai_dst, V);

    // ============ atom phase ============
    gemm4_k<<<(NATOM + 127) / 128, 400, GEMM_SMEM>>>(atom_x, Wd, HSA, ALS1, ad_src, ad_dst, ALD1,
                                                     V, ALD2, NATOM, 1);
    gemm4_k<<<(NAA + 127) / 128, 400, GEMM_SMEM>>>(aa_x, Wi_src, HSB, ALS2, ai_src, ai_dst, nullptr,
                                                   nullptr, nullptr, NAA, 1);

    // merged atom edge pass: intra (cols 0-99) + inter (cols 100-199)
    launch_edge_acc2(a_src_e, a_dst_e, EATOM, NATOM, ALS1, ALD1, HSA, ZA1,
                     m_aa, m_atom, EM2P, nloop_i, ALS2, ALD2, HSB, ZA2, OA);

    run_ln(OA, abatch, ZA1, ZA2, bd, bi, ln_d_w, ln_d_b,
           pd_Wrel, pd_Wroot, T, R, NATOM, CNTA);
    sag_edge_k<<<(EATOM + 255) / 256, 256>>>(a_src_e, a_dst_e, EATOM, T, AGGA);
    sag_spre_k<<<(NATOM + 255) / 256, 256>>>(AGGA, R, pd_brel, abatch, SPREA, SGZA, NATOM);

    // ============ aa phase ============
    gemm4_k<<<(NAA + 127) / 128, 400, GEMM_SMEM>>>(aa_x, Wp, HSB, ALS1, ap_src, ap_dst, ALD1,
                                                   V, ALD2, NAA, 1);
    gemm4_k<<<(NATOM + 127) / 128, 400, GEMM_SMEM>>>(OA, Wi_src, HSA, ALS2, ai_src, ai_dst, nullptr,
                                                     nullptr, nullptr, NATOM, 0);

    // DEFERRED atom SAG scale: OA -> atom_out (after OA consumed above)
    sag_scale_k<<<((long)NATOM * 50 + 255) / 256, 256>>>(OA, SPREA, SGZA, abatch, DG, NATOM);

    // merged aa edge pass: intra (cols 0-99) + inter (cols 100-199)
    launch_edge_acc2(p_src_e, p_dst_e, EAA, NAA, ALS1, ALD1, HSB, ZP1,
                     m_atom, m_aa, EM2P, nloop_i, ALS2, ALD2, HSA, ZP2, OP);

    run_ln(OP, pbatch, ZP1, ZP2, bp, bi, ln_p_w, ln_p_b,
           pp_Wrel, pp_Wroot, T, R, NAA, CNTP);
    sag_edge_k<<<(EAA + 255) / 256, 256>>>(p_src_e, p_dst_e, EAA, T, AGGP);
    sag_spre_k<<<(NAA + 255) / 256, 256>>>(AGGP, R, pp_brel, pbatch, SPREP, SGZP, NAA);
    sag_scale_k<<<((long)NAA * 50 + 255) / 256, 256>>>(OP, SPREP, SGZP, pbatch, PG, NAA);
}

// round 11
// speedup vs baseline: 1.9813x; 1.0305x over previous
#include <cuda_runtime.h>
#include <cuda_bf16.h>
#include <cstdint>

// ---------------- problem constants ----------------
#define NATOM 25600
#define NAA   204800
#define EATOM 102400
#define EAA   1024000
#define EM2P  512000
#define DIM   200
#define HCD   100
#define NB    512

// ---------------- scratch layout (floats) ----------------
static const long OFF_HSA   = 0L;                        // 2,560,000
static const long OFF_HSB   = 2560000L;                  // 20,480,000
static const long OFF_HSC   = 23040000L;                 // 20,480,000
static const long OFF_ALS1  = 43520000L;                 // 409,600 each below
static const long OFF_ALD1  = 43929600L;
static const long OFF_ALS2  = 44339200L;
static const long OFF_ALD2  = 44748800L;
static const long OFF_ALS3  = 45158400L;
static const long OFF_ALD3  = 45568000L;
static const long OFF_ALS4  = 45977600L;
static const long OFF_ALD4  = 46387200L;
// ---- zero block (one memset) ----
static const long OFF_ZSTART= 46796800L;
static const long OFF_ZA1   = 46796800L;                 // 2*NATOM
static const long OFF_ZA2   = 46848000L;                 // 2*NATOM
static const long OFF_ZP1   = 46899200L;                 // 2*NAA
static const long OFF_ZP2   = 47308800L;                 // 2*NAA
static const long OFF_AGGA  = 47718400L;                 // NATOM
static const long OFF_AGGP  = 47744000L;                 // NAA
static const long OFF_SGZA  = 47948800L;                 // 512
static const long OFF_SGZP  = 47949312L;                 // 512
static const long OFF_CNTA  = 47949824L;                 // 3*512
static const long OFF_CNTP  = 47951360L;                 // 3*512
static const long OFF_ZEND  = 47952896L;
// ---- rest ----
static const long OFF_V     = 47952896L;                 // 512
static const long OFF_T     = 47953408L;                 // NAA
static const long OFF_R     = 48158208L;                 // NAA
static const long OFF_SPREA = 48363008L;                 // NATOM
static const long OFF_SPREP = 48388608L;                 // NAA
static const long SCRATCH_FLOATS = 48593408L;

__device__ __align__(256) float g_scratch[SCRATCH_FLOATS];

// ---------------- device helpers ----------------
__device__ __forceinline__ float eluf(float x)  { return x > 0.f ? x : expm1f(x); }
__device__ __forceinline__ float lreluf(float x){ return x > 0.f ? x : 0.2f * x; }

__device__ __forceinline__ float warp_sum(float v) {
    #pragma unroll
    for (int o = 16; o > 0; o >>= 1) v += __shfl_down_sync(0xffffffffu, v, o);
    return v;
}

// ---------------- GEMM v4: 128 rows/block, 400 threads, K chunked by 100 ------
#define KC 100
#define GEMM_SMEM (size_t)((10000 + 12800) * sizeof(float))
__global__ void __launch_bounds__(400, 2)
gemm4_k(const float* __restrict__ X, const float* __restrict__ W,
        float* __restrict__ Y, float* __restrict__ ALS,
        const float* __restrict__ a_src, const float* __restrict__ a_dst,
        float* __restrict__ ALD,
        const float* __restrict__ Vg, float* __restrict__ XALD,
        int N, int do_elu) {
    extern __shared__ float sm[];
    float* Ws = sm;               // 10000 : chunk [k][c]
    float* Xs = sm + 10000;       // 12800 : chunk [k][r], stride 128
    __shared__ float Vs[400];

    int tid = threadIdx.x;
    int tx = tid % 25, ty = tid / 25;
    int row0 = blockIdx.x * 128;

    if (XALD && tid < 400) Vs[tid] = Vg[tid];

    float acc[8][4];
    #pragma unroll
    for (int r = 0; r < 8; r++)
        #pragma unroll
        for (int c = 0; c < 4; c++) acc[r][c] = 0.f;
    float xd0 = 0.f, xd1 = 0.f;

    #pragma unroll
    for (int kc = 0; kc < 2; kc++) {
        const float4* Wg = (const float4*)(W + (size_t)kc * KC * HCD);
        for (int i = tid; i < 2500; i += 400)
            ((float4*)Ws)[i] = Wg[i];
        for (int i = tid; i < 3200; i += 400) {
            int r = i & 127, kq = i >> 7;
            int row = row0 + r;
            float4 v = make_float4(0.f, 0.f, 0.f, 0.f);
            if (row < N) v = ((const float4*)(X + (size_t)row * DIM))[kc * 25 + kq];
            if (do_elu) { v.x = eluf(v.x); v.y = eluf(v.y); v.z = eluf(v.z); v.w = eluf(v.w); }
            int kb = kq * 4;
            Xs[(kb + 0) * 128 + r] = v.x;
            Xs[(kb + 1) * 128 + r] = v.y;
            Xs[(kb + 2) * 128 + r] = v.z;
            Xs[(kb + 3) * 128 + r] = v.w;
        }
        __syncthreads();

        const float* wp = Ws + 4 * tx;
        const float* xp = Xs + 8 * ty;
        #pragma unroll 4
        for (int k = 0; k < KC; k++) {
            float4 w4 = *(const float4*)(wp + k * HCD);
            float4 xa = *(const float4*)(xp + k * 128);
            float4 xb = *(const float4*)(xp + k * 128 + 4);
            float xr[8] = {xa.x, xa.y, xa.z, xa.w, xb.x, xb.y, xb.z, xb.w};
            #pragma unroll
            for (int r = 0; r < 8; r++) {
                acc[r][0] += xr[r] * w4.x;
                acc[r][1] += xr[r] * w4.y;
                acc[r][2] += xr[r] * w4.z;
                acc[r][3] += xr[r] * w4.w;
            }
        }
        if (XALD && tid < 128) {
            int r = tid;
            #pragma unroll 4
            for (int k = 0; k < KC; k++) {
                float x = Xs[k * 128 + r];
                xd0 += x * Vs[2 * (kc * KC + k)];
                xd1 += x * Vs[2 * (kc * KC + k) + 1];
            }
        }
        __syncthreads();
    }

    if (XALD && tid < 128 && row0 + tid < N)
        ((float2*)XALD)[row0 + tid] = make_float2(xd0, xd1);

    float* part_s = sm;
    float* part_d = sm + 6400;

    int c0 = 4 * tx;
    float4 af = *(const float4*)(a_src + c0);
    float4 bf = ALD ? *(const float4*)(a_dst + c0) : make_float4(0.f, 0.f, 0.f, 0.f);

    #pragma unroll
    for (int r = 0; r < 8; r++) {
        int lrow = 8 * ty + r;
        int row = row0 + lrow;
        float s0 = 0.f, s1 = 0.f, t0 = 0.f, t1 = 0.f;
        float ps[4] = {acc[r][0]*af.x, acc[r][1]*af.y, acc[r][2]*af.z, acc[r][3]*af.w};
        float pd[4] = {acc[r][0]*bf.x, acc[r][1]*bf.y, acc[r][2]*bf.z, acc[r][3]*bf.w};
        #pragma unroll
        for (int q = 0; q < 4; q++) {
            if (c0 + q < 50) { s0 += ps[q]; t0 += pd[q]; }
            else             { s1 += ps[q]; t1 += pd[q]; }
        }
        part_s[lrow * 50 + tx]      = s0;
        part_s[lrow * 50 + 25 + tx] = s1;
        part_d[lrow * 50 + tx]      = t0;
        part_d[lrow * 50 + 25 + tx] = t1;
        if (row < N)
            *(float4*)(Y + (size_t)row * HCD + c0) =
                make_float4(acc[r][0], acc[r][1], acc[r][2], acc[r][3]);
    }
    __syncthreads();

    if (tid < 256) {
        int r = tid >> 1, h = tid & 1;
        int row = row0 + r;
        if (row < N) {
            float s = 0.f, t = 0.f;
            const float* ps = part_s + r * 50 + h * 25;
            const float* pd = part_d + r * 50 + h * 25;
            #pragma unroll
            for (int i = 0; i < 25; i++) { s += ps[i]; t += pd[i]; }
            ALS[(size_t)row * 2 + h] = s;
            if (ALD) ALD[(size_t)row * 2 + h] = t;
        }
    }
}

// ---------------- fold v[k,h] = sum_c Wdst[k, h*50+c] * adst[h,c] -------------
__global__ void fold_v_k(const float* __restrict__ Wdst, const float* __restrict__ adst,
                         float* __restrict__ v) {
    int i = blockIdx.x * blockDim.x + threadIdx.x;
    if (i >= 2 * DIM) return;
    int k = i >> 1, h = i & 1;
    float s = 0.f;
    #pragma unroll
    for (int c = 0; c < 50; c++) s += Wdst[k * HCD + h * 50 + c] * adst[h * 50 + c];
    v[2 * k + h] = s;
}

// ---------------- merged edge pass: both edge sets, 4 edges/warp --------------
__global__ void edge_acc2_k(
    const int* __restrict__ src1, const int* __restrict__ dst1, int E1, long tot1, long W1,
    const float* __restrict__ als1, const float* __restrict__ ald1,
    const float* __restrict__ hs1, float* __restrict__ z1,
    const int* __restrict__ src2, const int* __restrict__ dst2, int E2, long tot2,
    const float* __restrict__ als2, const float* __restrict__ ald2,
    const float* __restrict__ hs2, float* __restrict__ z2,
    float* __restrict__ out) {
    long gw = ((long)blockIdx.x * blockDim.x + threadIdx.x) >> 5;
    int lane = threadIdx.x & 31;

    const int *src, *dst;
    const float *als, *ald, *hs;
    float* z;
    int E, coloff;
    long e0, tot;
    if (gw < W1) {
        src = src1; dst = dst1; als = als1; ald = ald1; hs = hs1; z = z1;
        E = E1; coloff = 0; tot = tot1; e0 = gw * 4;
    } else {
        src = src2; dst = dst2; als = als2; ald = ald2; hs = hs2; z = z2;
        E = E2; coloff = HCD; tot = tot2; e0 = (gw - W1) * 4;
    }
    if (e0 >= tot) return;
    int ne = (int)((tot - e0 < 4) ? (tot - e0) : 4);

    int s[4], d[4];
    #pragma unroll
    for (int k = 0; k < 4; k++) {
        if (k < ne) {
            long e = e0 + k;
            if (e < E) { s[k] = src[e]; d[k] = dst[e]; }
            else       { s[k] = d[k] = (int)(e - E); }
        } else { s[k] = s[0]; d[k] = d[0]; }
    }

    float ex[4][2];
    #pragma unroll
    for (int k = 0; k < 4; k++) {
        float2 as = ((const float2*)als)[s[k]];
        float2 ad = ((const float2*)ald)[d[k]];
        ex[k][0] = __expf(lreluf(as.x + ad.x));
        ex[k][1] = __expf(lreluf(as.y + ad.y));
    }

    if (lane >= 24) {
        int kk = (lane - 24) >> 1, h = (lane - 24) & 1;
        if (kk < ne) atomicAdd(&z[2 * d[kk] + h], ex[kk][h]);
    }

    if (lane < 25) {
        int j = lane * 4;
        float4 h4[4];
        #pragma unroll
        for (int k = 0; k < 4; k++)
            if (k < ne) h4[k] = *(const float4*)(hs + (size_t)s[k] * HCD + j);
        #pragma unroll
        for (int k = 0; k < 4; k++) {
            if (k < ne) {
                float w0 = (j     < 50 ? ex[k][0] : ex[k][1]) * h4[k].x;
                float w1 = (j + 1 < 50 ? ex[k][0] : ex[k][1]) * h4[k].y;
                float w2 = (j + 2 < 50 ? ex[k][0] : ex[k][1]) * h4[k].z;
                float w3 = (j + 3 < 50 ? ex[k][0] : ex[k][1]) * h4[k].w;
                float* p = out + (size_t)d[k] * DIM + coloff + j;
                asm volatile("red.global.add.v4.f32 [%0], {%1,%2,%3,%4};"
                             :: "l"(p), "f"(w0), "f"(w1), "f"(w2), "f"(w3) : "memory");
            }
        }
    }
}

// ---------------- fused: finalize (virtual) + LN stats + graph counts ---------
__global__ void ln_stats_fused_k(const float* __restrict__ out,
                                 const float* __restrict__ z1, const float* __restrict__ z2,
                                 const float* __restrict__ b1, const float* __restrict__ b2,
                                 const int* __restrict__ batch,
                                 float* __restrict__ cnt,
                                 float* __restrict__ gsum, float* __restrict__ gsq, int N) {
    int n = (blockIdx.x * blockDim.x + threadIdx.x) >> 5;
    int lane = threadIdx.x & 31;
    if (n >= N) return;
    float2 zz1 = ((const float2*)z1)[n];
    float2 zz2 = ((const float2*)z2)[n];
    float iz10 = 1.f / (zz1.x + 1e-16f), iz11 = 1.f / (zz1.y + 1e-16f);
    float iz20 = 1.f / (zz2.x + 1e-16f), iz21 = 1.f / (zz2.y + 1e-16f);
    const float4* xr = (const float4*)(out + (size_t)n * DIM);
    float s = 0.f, q = 0.f;
    #pragma unroll
    for (int c = lane; c < 50; c += 32) {
        float4 val = xr[c];
        int j = 4 * c;
        float4 b = (c < 25) ? ((const float4*)b1)[c] : ((const float4*)b2)[c - 25];
        float izA, izB;
        if (c < 25) { izA = iz10; izB = iz11; } else { izA = iz20; izB = iz21; }
        int jj = (c < 25) ? j : j - 100;
        float y0 = val.x * (jj     < 50 ? izA : izB) + b.x;
        float y1 = val.y * (jj + 1 < 50 ? izA : izB) + b.y;
        float y2 = val.z * (jj + 2 < 50 ? izA : izB) + b.z;
        float y3 = val.w * (jj + 3 < 50 ? izA : izB) + b.w;
        s += y0 + y1 + y2 + y3;
        q += y0*y0 + y1*y1 + y2*y2 + y3*y3;
    }
    s = warp_sum(s); q = warp_sum(q);
    if (lane == 0) {
        int g = batch[n];
        atomicAdd(&cnt[g], 1.f);
        atomicAdd(&gsum[g], s);
        atomicAdd(&gsq[g], q);
    }
}

// ---------------- fused: finalize + LN apply + elu + SAG T/R dots -------------
__global__ void ln_apply_fused_k(float* __restrict__ x,
                                 const float* __restrict__ z1, const float* __restrict__ z2,
                                 const float* __restrict__ b1, const float* __restrict__ b2,
                                 const int* __restrict__ batch,
                                 const float* __restrict__ cnt, const float* __restrict__ gsum,
                                 const float* __restrict__ gsq,
                                 const float* __restrict__ wv, const float* __restrict__ bv,
                                 const float* __restrict__ Wrel, const float* __restrict__ Wroot,
                                 float* __restrict__ T, float* __restrict__ R, int N) {
    int n = (blockIdx.x * blockDim.x + threadIdx.x) >> 5;
    int lane = threadIdx.x & 31;
    if (n >= N) return;
    int g = batch[n];
    float norm = fmaxf(cnt[g], 1.f) * (float)DIM;
    float mean = gsum[g] / norm;
    float var  = gsq[g] / norm - mean * mean;
    float rstd = rsqrtf(var + 1e-5f);
    float2 zz1 = ((const float2*)z1)[n];
    float2 zz2 = ((const float2*)z2)[n];
    float iz10 = 1.f / (zz1.x + 1e-16f), iz11 = 1.f / (zz1.y + 1e-16f);
    float iz20 = 1.f / (zz2.x + 1e-16f), iz21 = 1.f / (zz2.y + 1e-16f);
    float4* xr = (float4*)(x + (size_t)n * DIM);
    float t = 0.f, r = 0.f;
    #pragma unroll
    for (int c = lane; c < 50; c += 32) {
        float4 val = xr[c];
        int j = 4 * c;
        float4 b = (c < 25) ? ((const float4*)b1)[c] : ((const float4*)b2)[c - 25];
        float izA, izB;
        if (c < 25) { izA = iz10; izB = iz11; } else { izA = iz20; izB = iz21; }
        int jj = (c < 25) ? j : j - 100;
        float4 w4 = ((const float4*)wv)[c];
        float4 bb = ((const float4*)bv)[c];
        float4 wr = ((const float4*)Wrel)[c];
        float4 wo = ((const float4*)Wroot)[c];
        float y0 = val.x * (jj     < 50 ? izA : izB) + b.x;
        float y1 = val.y * (jj + 1 < 50 ? izA : izB) + b.y;
        float y2 = val.z * (jj + 2 < 50 ? izA : izB) + b.z;
        float y3 = val.w * (jj + 3 < 50 ? izA : izB) + b.w;
        float e0 = eluf((y0 - mean) * rstd * w4.x + bb.x);
        float e1 = eluf((y1 - mean) * rstd * w4.y + bb.y);
        float e2 = eluf((y2 - mean) * rstd * w4.z + bb.z);
        float e3 = eluf((y3 - mean) * rstd * w4.w + bb.w);
        xr[c] = make_float4(e0, e1, e2, e3);
        t += e0*wr.x + e1*wr.y + e2*wr.z + e3*wr.w;
        r += e0*wo.x + e1*wo.y + e2*wo.z + e3*wo.w;
    }
    t = warp_sum(t); r = warp_sum(r);
    if (lane == 0) { T[n] = t; R[n] = r; }
}

// ---------------- SAG pooling (no-max softmax) ----------------
__global__ void sag_edge_k(const int* __restrict__ src, const int* __restrict__ dst, int E,
                           const float* __restrict__ T, float* __restrict__ agg) {
    int e = blockIdx.x * blockDim.x + threadIdx.x;
    if (e < E) atomicAdd(&agg[dst[e]], T[src[e]]);
}

__global__ void sag_spre_k(const float* __restrict__ agg, const float* __restrict__ R,
                           const float* __restrict__ brel, const int* __restrict__ batch,
                           float* __restrict__ spre, float* __restrict__ sgz, int N) {
    int i = blockIdx.x * blockDim.x + threadIdx.x;
    if (i >= N) return;
    float s = agg[i] + brel[0] + R[i];
    spre[i] = s;
    atomicAdd(&sgz[batch[i]], __expf(s));
}

__global__ void sag_scale_k(float* __restrict__ x, const float* __restrict__ spre,
                            const float* __restrict__ sgz,
                            const int* __restrict__ batch, float* __restrict__ G, int N) {
    long i = (long)blockIdx.x * blockDim.x + threadIdx.x;
    if (i >= (long)N * 50) return;
    int n = (int)(i / 50), q = (int)(i - (long)n * 50);
    int g = batch[n];
    float score = __expf(spre[n]) / (sgz[g] + 1e-16f);
    float4 v = *(float4*)(x + (size_t)n * DIM + 4 * q);
    v.x *= score; v.y *= score; v.z *= score; v.w *= score;
    *(float4*)(x + (size_t)n * DIM + 4 * q) = v;
    float* p = G + (size_t)g * DIM + 4 * q;
    asm volatile("red.global.add.v4.f32 [%0], {%1,%2,%3,%4};"
                 :: "l"(p), "f"(v.x), "f"(v.y), "f"(v.z), "f"(v.w) : "memory");
}

// ---------------- host orchestration ----------------
static void launch_edge_acc2(cudaStream_t st,
                             const int* src1, const int* dst1, int E1, int nloop1,
                             const float* als1, const float* ald1, const float* hs1, float* z1,
                             const int* src2, const int* dst2, int E2, int nloop2,
                             const float* als2, const float* ald2, const float* hs2, float* z2,
                             float* out) {
    long tot1 = (long)E1 + nloop1, tot2 = (long)E2 + nloop2;
    long W1 = (tot1 + 3) / 4, W2 = (tot2 + 3) / 4;
    long WT = W1 + W2;
    edge_acc2_k<<<(WT * 32 + 255) / 256, 256, 0, st>>>(
        src1, dst1, E1, tot1, W1, als1, ald1, hs1, z1,
        src2, dst2, E2, tot2, als2, ald2, hs2, z2, out);
}

static void run_ln(cudaStream_t st, float* x, const int* batch,
                   const float* z1, const float* z2,
                   const float* b1, const float* b2,
                   const float* lnw, const float* lnb,
                   const float* Wrel, const float* Wroot,
                   float* T, float* R, int N, float* CNT) {
    ln_stats_fused_k<<<(N * 32 + 255) / 256, 256, 0, st>>>(x, z1, z2, b1, b2, batch,
                                                    CNT, CNT + NB, CNT + 2 * NB, N);
    ln_apply_fused_k<<<(N * 32 + 255) / 256, 256, 0, st>>>(x, z1, z2, b1, b2, batch,
                                                    CNT, CNT + NB, CNT + 2 * NB,
                                                    lnw, lnb, Wrel, Wroot, T, R, N);
}

extern "C" void kernel_launch(void* const* d_in, const int* in_sizes, int n_in,
                              void* d_out, int out_size) {
    const float* atom_x  = (const float*)d_in[0];
    const int*   aei     = (const int*)  d_in[1];
    const int*   abatch  = (const int*)  d_in[2];
    const float* aa_x    = (const float*)d_in[3];
    const int*   pei     = (const int*)  d_in[4];
    // d_in[5] = aa_edge_attr (unused by reference)
    const int*   pbatch  = (const int*)  d_in[6];
    const int*   m2p     = (const int*)  d_in[7];
    const float* Wd      = (const float*)d_in[8];
    const float* ad_src  = (const float*)d_in[9];
    const float* ad_dst  = (const float*)d_in[10];
    const float* bd      = (const float*)d_in[11];
    const float* Wp      = (const float*)d_in[12];
    const float* ap_src  = (const float*)d_in[13];
    const float* ap_dst  = (const float*)d_in[14];
    const float* bp      = (const float*)d_in[15];
    const float* Wi_src  = (const float*)d_in[16];
    const float* Wi_dst  = (const float*)d_in[17];
    const float* ai_src  = (const float*)d_in[18];
    const float* ai_dst  = (const float*)d_in[19];
    const float* bi      = (const float*)d_in[20];
    const float* ln_d_w  = (const float*)d_in[21];
    const float* ln_d_b  = (const float*)d_in[22];
    const float* ln_p_w  = (const float*)d_in[23];
    const float* ln_p_b  = (const float*)d_in[24];
    const float* pd_Wrel = (const float*)d_in[25];
    const float* pd_brel = (const float*)d_in[26];
    const float* pd_Wroot= (const float*)d_in[27];
    const float* pp_Wrel = (const float*)d_in[28];
    const float* pp_brel = (const float*)d_in[29];
    const float* pp_Wroot= (const float*)d_in[30];

    cudaFuncSetAttribute(gemm4_k, cudaFuncAttributeMaxDynamicSharedMemorySize, (int)GEMM_SMEM);

    float* S = nullptr;
    cudaGetSymbolAddress((void**)&S, g_scratch);

    float* HSA   = S + OFF_HSA;
    float* HSB   = S + OFF_HSB;
    float* HSC   = S + OFF_HSC;
    float* ALS1  = S + OFF_ALS1;
    float* ALD1  = S + OFF_ALD1;
    float* ALS2  = S + OFF_ALS2;
    float* ALD2  = S + OFF_ALD2;
    float* ALS3  = S + OFF_ALS3;
    float* ALD3  = S + OFF_ALD3;
    float* ALS4  = S + OFF_ALS4;
    float* ALD4  = S + OFF_ALD4;
    float* ZA1   = S + OFF_ZA1;
    float* ZA2   = S + OFF_ZA2;
    float* ZP1   = S + OFF_ZP1;
    float* ZP2   = S + OFF_ZP2;
    float* AGGA  = S + OFF_AGGA;
    float* AGGP  = S + OFF_AGGP;
    float* SGZA  = S + OFF_SGZA;
    float* SGZP  = S + OFF_SGZP;
    float* CNTA  = S + OFF_CNTA;
    float* CNTP  = S + OFF_CNTP;
    float* V     = S + OFF_V;
    float* T     = S + OFF_T;
    float* R     = S + OFF_R;
    float* SPREA = S + OFF_SPREA;
    float* SPREP = S + OFF_SPREP;

    float* out = (float*)d_out;
    float* OA  = out;                                  // atom_h -> atom_out [25600,200]
    float* OP  = out + (size_t)NATOM * DIM;            // aa_h -> aa_out    [204800,200]
    float* DG  = out + (size_t)(NATOM + NAA) * DIM;    // drug_g [512,200]
    float* PG  = DG + (size_t)NB * DIM;                // prot_g [512,200]

    const int* a_src_e = aei;
    const int* a_dst_e = aei + EATOM;
    const int* p_src_e = pei;
    const int* p_dst_e = pei + EAA;
    const int* m_atom  = m2p;
    const int* m_aa    = m2p + EM2P;
    const int  nloop_i = NATOM;   // min(NATOM, NAA)

    // Streams/events created ONCE (first call = correctness run, BEFORE the
    // harness takes its pre-capture memory baseline). Reused on every call so
    // no device-side resources are allocated during or after graph capture.
    static cudaStream_t s2 = nullptr, s3 = nullptr;
    static cudaEvent_t evF = nullptr, evG1 = nullptr, evG3 = nullptr;
    if (!s2) {
        cudaStreamCreateWithFlags(&s2, cudaStreamNonBlocking);
        cudaStreamCreateWithFlags(&s3, cudaStreamNonBlocking);
        cudaEventCreateWithFlags(&evF,  cudaEventDisableTiming);
        cudaEventCreateWithFlags(&evG1, cudaEventDisableTiming);
        cudaEventCreateWithFlags(&evG3, cudaEventDisableTiming);
    }
    cudaStream_t s0 = 0;   // legacy default (the captured stream)

    // ---- main stream: init ----
    cudaMemsetAsync(d_out, 0, (size_t)out_size * sizeof(float), s0);
    cudaMemsetAsync(S + OFF_ZSTART, 0, (size_t)(OFF_ZEND - OFF_ZSTART) * sizeof(float), s0);
    fold_v_k<<<2, 256, 0, s0>>>(Wi_dst, ai_dst, V);

    // ---- fork ----
    cudaEventRecord(evF, s0);
    cudaStreamWaitEvent(s2, evF, 0);
    cudaStreamWaitEvent(s3, evF, 0);

    // s2: G1 = atom intra GEMM (+ atom inter-dst dot -> ALD2)
    gemm4_k<<<(NATOM + 127) / 128, 400, GEMM_SMEM, s2>>>(atom_x, Wd, HSA, ALS1, ad_src, ad_dst, ALD1,
                                                         V, ALD2, NATOM, 1);
    cudaEventRecord(evG1, s2);

    // s3: G3 = aa intra GEMM (+ aa inter-dst dot -> ALD4), private HSC
    gemm4_k<<<(NAA + 127) / 128, 400, GEMM_SMEM, s3>>>(aa_x, Wp, HSC, ALS3, ap_src, ap_dst, ALD3,
                                                       V, ALD4, NAA, 1);
    cudaEventRecord(evG3, s3);

    // s0: G2 = atom-phase inter source GEMM (aa_x @ Wi_src)
    gemm4_k<<<(NAA + 127) / 128, 400, GEMM_SMEM, s0>>>(aa_x, Wi_src, HSB, ALS2, ai_src, ai_dst, nullptr,
                                                       nullptr, nullptr, NAA, 1);

    // join G1 into main, then atom edge pass (intra + inter)
    cudaStreamWaitEvent(s0, evG1, 0);
    launch_edge_acc2(s0,
                     a_src_e, a_dst_e, EATOM, NATOM, ALS1, ALD1, HSA, ZA1,
                     m_aa, m_atom, EM2P, nloop_i, ALS2, ALD2, HSB, ZA2, OA);

    // atom LN + SAG scalars
    run_ln(s0, OA, abatch, ZA1, ZA2, bd, bi, ln_d_w, ln_d_b,
           pd_Wrel, pd_Wroot, T, R, NATOM, CNTA);
    sag_edge_k<<<(EATOM + 255) / 256, 256, 0, s0>>>(a_src_e, a_dst_e, EATOM, T, AGGA);
    sag_spre_k<<<(NATOM + 255) / 256, 256, 0, s0>>>(AGGA, R, pd_brel, abatch, SPREA, SGZA, NATOM);

    // G4 = aa-phase inter source GEMM (atom_h @ Wi_src); overwrites HSA (atom edge done)
    gemm4_k<<<(NATOM + 127) / 128, 400, GEMM_SMEM, s0>>>(OA, Wi_src, HSA, ALS4, ai_src, ai_dst, nullptr,
                                                         nullptr, nullptr, NATOM, 0);

    // DEFERRED atom SAG scale: OA -> atom_out (after OA consumed by G4)
    sag_scale_k<<<((long)NATOM * 50 + 255) / 256, 256, 0, s0>>>(OA, SPREA, SGZA, abatch, DG, NATOM);

    // join G3, then aa edge pass (intra uses HSC/ALS3/ALD3, inter uses HSA/ALS4/ALD4)
    cudaStreamWaitEvent(s0, evG3, 0);
    launch_edge_acc2(s0,
                     p_src_e, p_dst_e, EAA, NAA, ALS3, ALD3, HSC, ZP1,
                     m_atom, m_aa, EM2P, nloop_i, ALS4, ALD4, HSA, ZP2, OP);

    // aa LN + SAG
    run_ln(s0, OP, pbatch, ZP1, ZP2, bp, bi, ln_p_w, ln_p_b,
           pp_Wrel, pp_Wroot, T, R, NAA, CNTP);
    sag_edge_k<<<(EAA + 255) / 256, 256, 0, s0>>>(p_src_e, p_dst_e, EAA, T, AGGP);
    sag_spre_k<<<(NAA + 255) / 256, 256, 0, s0>>>(AGGP, R, pp_brel, pbatch, SPREP, SGZP, NAA);
    sag_scale_k<<<((long)NAA * 50 + 255) / 256, 256, 0, s0>>>(OP, SPREP, SGZP, pbatch, PG, NAA);
}

// round 15
// speedup vs baseline: 2.0425x; 1.0309x over previous
#include <cuda_runtime.h>
#include <cuda_bf16.h>
#include <cstdint>

// ---------------- problem constants ----------------
#define NATOM 25600
#define NAA   204800
#define EATOM 102400
#define EAA   1024000
#define EM2P  512000
#define DIM   200
#define HCD   100
#define NB    512

// ---------------- scratch layout (floats) ----------------
static const long OFF_HSA   = 0L;                        // 2,560,000
static const long OFF_HSB   = 2560000L;                  // 20,480,000
static const long OFF_HSC   = 23040000L;                 // 20,480,000
static const long OFF_ALS1  = 43520000L;                 // 409,600 each below
static const long OFF_ALD1  = 43929600L;
static const long OFF_ALS2  = 44339200L;
static const long OFF_ALD2  = 44748800L;
static const long OFF_ALS3  = 45158400L;
static const long OFF_ALD3  = 45568000L;
static const long OFF_ALS4  = 45977600L;
static const long OFF_ALD4  = 46387200L;
// ---- zero block (one memset) ----
static const long OFF_ZSTART= 46796800L;
static const long OFF_ZA1   = 46796800L;                 // 2*NATOM
static const long OFF_ZA2   = 46848000L;                 // 2*NATOM
static const long OFF_ZP1   = 46899200L;                 // 2*NAA
static const long OFF_ZP2   = 47308800L;                 // 2*NAA
static const long OFF_AGGA  = 47718400L;                 // NATOM
static const long OFF_AGGP  = 47744000L;                 // NAA
static const long OFF_SGZA  = 47948800L;                 // 512
static const long OFF_SGZP  = 47949312L;                 // 512
static const long OFF_CNTA  = 47949824L;                 // 3*512
static const long OFF_CNTP  = 47951360L;                 // 3*512
static const long OFF_ZEND  = 47952896L;
// ---- rest ----
static const long OFF_V     = 47952896L;                 // 512
static const long OFF_T     = 47953408L;                 // NAA
static const long OFF_R     = 48158208L;                 // NAA
static const long OFF_SPREA = 48363008L;                 // NATOM
static const long OFF_SPREP = 48388608L;                 // NAA
static const long SCRATCH_FLOATS = 48593408L;

__device__ __align__(256) float g_scratch[SCRATCH_FLOATS];

// ---------------- device helpers ----------------
__device__ __forceinline__ float eluf(float x)  { return x > 0.f ? x : expm1f(x); }
__device__ __forceinline__ float lreluf(float x){ return x > 0.f ? x : 0.2f * x; }

__device__ __forceinline__ float warp_sum(float v) {
    #pragma unroll
    for (int o = 16; o > 0; o >>= 1) v += __shfl_down_sync(0xffffffffu, v, o);
    return v;
}

// ---------------- GEMM v4: 128 rows/block, 400 threads, K chunked by 100 ------
#define KC 100
#define GEMM_SMEM (size_t)((10000 + 12800) * sizeof(float))
__global__ void __launch_bounds__(400, 2)
gemm4_k(const float* __restrict__ X, const float* __restrict__ W,
        float* __restrict__ Y, float* __restrict__ ALS,
        const float* __restrict__ a_src, const float* __restrict__ a_dst,
        float* __restrict__ ALD,
        const float* __restrict__ Vg, float* __restrict__ XALD,
        int N, int do_elu) {
    extern __shared__ float sm[];
    float* Ws = sm;               // 10000 : chunk [k][c]
    float* Xs = sm + 10000;       // 12800 : chunk [k][r], stride 128
    __shared__ float Vs[400];

    int tid = threadIdx.x;
    int tx = tid % 25, ty = tid / 25;
    int row0 = blockIdx.x * 128;

    if (XALD && tid < 400) Vs[tid] = Vg[tid];

    float acc[8][4];
    #pragma unroll
    for (int r = 0; r < 8; r++)
        #pragma unroll
        for (int c = 0; c < 4; c++) acc[r][c] = 0.f;
    float xd0 = 0.f, xd1 = 0.f;

    #pragma unroll
    for (int kc = 0; kc < 2; kc++) {
        const float4* Wg = (const float4*)(W + (size_t)kc * KC * HCD);
        for (int i = tid; i < 2500; i += 400)
            ((float4*)Ws)[i] = Wg[i];
        for (int i = tid; i < 3200; i += 400) {
            int r = i & 127, kq = i >> 7;
            int row = row0 + r;
            float4 v = make_float4(0.f, 0.f, 0.f, 0.f);
            if (row < N) v = ((const float4*)(X + (size_t)row * DIM))[kc * 25 + kq];
            if (do_elu) { v.x = eluf(v.x); v.y = eluf(v.y); v.z = eluf(v.z); v.w = eluf(v.w); }
            int kb = kq * 4;
            Xs[(kb + 0) * 128 + r] = v.x;
            Xs[(kb + 1) * 128 + r] = v.y;
            Xs[(kb + 2) * 128 + r] = v.z;
            Xs[(kb + 3) * 128 + r] = v.w;
        }
        __syncthreads();

        const float* wp = Ws + 4 * tx;
        const float* xp = Xs + 8 * ty;
        #pragma unroll 4
        for (int k = 0; k < KC; k++) {
            float4 w4 = *(const float4*)(wp + k * HCD);
            float4 xa = *(const float4*)(xp + k * 128);
            float4 xb = *(const float4*)(xp + k * 128 + 4);
            float xr[8] = {xa.x, xa.y, xa.z, xa.w, xb.x, xb.y, xb.z, xb.w};
            #pragma unroll
            for (int r = 0; r < 8; r++) {
                acc[r][0] += xr[r] * w4.x;
                acc[r][1] += xr[r] * w4.y;
                acc[r][2] += xr[r] * w4.z;
                acc[r][3] += xr[r] * w4.w;
            }
        }
        if (XALD && tid < 128) {
            int r = tid;
            #pragma unroll 4
            for (int k = 0; k < KC; k++) {
                float x = Xs[k * 128 + r];
                xd0 += x * Vs[2 * (kc * KC + k)];
                xd1 += x * Vs[2 * (kc * KC + k) + 1];
            }
        }
        __syncthreads();
    }

    if (XALD && tid < 128 && row0 + tid < N)
        ((float2*)XALD)[row0 + tid] = make_float2(xd0, xd1);

    float* part_s = sm;
    float* part_d = sm + 6400;

    int c0 = 4 * tx;
    float4 af = *(const float4*)(a_src + c0);
    float4 bf = ALD ? *(const float4*)(a_dst + c0) : make_float4(0.f, 0.f, 0.f, 0.f);

    #pragma unroll
    for (int r = 0; r < 8; r++) {
        int lrow = 8 * ty + r;
        int row = row0 + lrow;
        float s0 = 0.f, s1 = 0.f, t0 = 0.f, t1 = 0.f;
        float ps[4] = {acc[r][0]*af.x, acc[r][1]*af.y, acc[r][2]*af.z, acc[r][3]*af.w};
        float pd[4] = {acc[r][0]*bf.x, acc[r][1]*bf.y, acc[r][2]*bf.z, acc[r][3]*bf.w};
        #pragma unroll
        for (int q = 0; q < 4; q++) {
            if (c0 + q < 50) { s0 += ps[q]; t0 += pd[q]; }
            else             { s1 += ps[q]; t1 += pd[q]; }
        }
        part_s[lrow * 50 + tx]      = s0;
        part_s[lrow * 50 + 25 + tx] = s1;
        part_d[lrow * 50 + tx]      = t0;
        part_d[lrow * 50 + 25 + tx] = t1;
        if (row < N)
            *(float4*)(Y + (size_t)row * HCD + c0) =
                make_float4(acc[r][0], acc[r][1], acc[r][2], acc[r][3]);
    }
    __syncthreads();

    if (tid < 256) {
        int r = tid >> 1, h = tid & 1;
        int row = row0 + r;
        if (row < N) {
            float s = 0.f, t = 0.f;
            const float* ps = part_s + r * 50 + h * 25;
            const float* pd = part_d + r * 50 + h * 25;
            #pragma unroll
            for (int i = 0; i < 25; i++) { s += ps[i]; t += pd[i]; }
            ALS[(size_t)row * 2 + h] = s;
            if (ALD) ALD[(size_t)row * 2 + h] = t;
        }
    }
}

// ---------------- fold v[k,h] = sum_c Wdst[k, h*50+c] * adst[h,c] -------------
__global__ void fold_v_k(const float* __restrict__ Wdst, const float* __restrict__ adst,
                         float* __restrict__ v) {
    int i = blockIdx.x * blockDim.x + threadIdx.x;
    if (i >= 2 * DIM) return;
    int k = i >> 1, h = i & 1;
    float s = 0.f;
    #pragma unroll
    for (int c = 0; c < 50; c++) s += Wdst[k * HCD + h * 50 + c] * adst[h * 50 + c];
    v[2 * k + h] = s;
}

// ---------------- edge core: 4 edges/warp ----------------
__device__ __forceinline__ void edge4_body(
    const int* __restrict__ src, const int* __restrict__ dst, int E, long tot, long e0,
    const float* __restrict__ als, const float* __restrict__ ald,
    const float* __restrict__ hs, float* __restrict__ z,
    float* __restrict__ out, int coloff, int lane) {
    int ne = (int)((tot - e0 < 4) ? (tot - e0) : 4);

    int s[4], d[4];
    #pragma unroll
    for (int k = 0; k < 4; k++) {
        if (k < ne) {
            long e = e0 + k;
            if (e < E) { s[k] = src[e]; d[k] = dst[e]; }
            else       { s[k] = d[k] = (int)(e - E); }
        } else { s[k] = s[0]; d[k] = d[0]; }
    }

    float ex[4][2];
    #pragma unroll
    for (int k = 0; k < 4; k++) {
        float2 as = ((const float2*)als)[s[k]];
        float2 ad = ((const float2*)ald)[d[k]];
        ex[k][0] = __expf(lreluf(as.x + ad.x));
        ex[k][1] = __expf(lreluf(as.y + ad.y));
    }

    if (lane >= 24) {
        int kk = (lane - 24) >> 1, h = (lane - 24) & 1;
        if (kk < ne) atomicAdd(&z[2 * d[kk] + h], ex[kk][h]);
    }

    if (lane < 25) {
        int j = lane * 4;
        float4 h4[4];
        #pragma unroll
        for (int k = 0; k < 4; k++)
            if (k < ne) h4[k] = *(const float4*)(hs + (size_t)s[k] * HCD + j);
        #pragma unroll
        for (int k = 0; k < 4; k++) {
            if (k < ne) {
                float w0 = (j     < 50 ? ex[k][0] : ex[k][1]) * h4[k].x;
                float w1 = (j + 1 < 50 ? ex[k][0] : ex[k][1]) * h4[k].y;
                float w2 = (j + 2 < 50 ? ex[k][0] : ex[k][1]) * h4[k].z;
                float w3 = (j + 3 < 50 ? ex[k][0] : ex[k][1]) * h4[k].w;
                float* p = out + (size_t)d[k] * DIM + coloff + j;
                asm volatile("red.global.add.v4.f32 [%0], {%1,%2,%3,%4};"
                             :: "l"(p), "f"(w0), "f"(w1), "f"(w2), "f"(w3) : "memory");
            }
        }
    }
}

// merged two-set variant (atom phase)
__global__ void edge_acc2_k(
    const int* __restrict__ src1, const int* __restrict__ dst1, int E1, long tot1, long W1,
    const float* __restrict__ als1, const float* __restrict__ ald1,
    const float* __restrict__ hs1, float* __restrict__ z1,
    const int* __restrict__ src2, const int* __restrict__ dst2, int E2, long tot2,
    const float* __restrict__ als2, const float* __restrict__ ald2,
    const float* __restrict__ hs2, float* __restrict__ z2,
    float* __restrict__ out) {
    long gw = ((long)blockIdx.x * blockDim.x + threadIdx.x) >> 5;
    int lane = threadIdx.x & 31;
    if (gw < W1) {
        long e0 = gw * 4;
        if (e0 < tot1)
            edge4_body(src1, dst1, E1, tot1, e0, als1, ald1, hs1, z1, out, 0, lane);
    } else {
        long e0 = (gw - W1) * 4;
        if (e0 < tot2)
            edge4_body(src2, dst2, E2, tot2, e0, als2, ald2, hs2, z2, out, HCD, lane);
    }
}

// single-set variant (aa phase halves)
__global__ void edge_acc1_k(
    const int* __restrict__ src, const int* __restrict__ dst, int E, long tot,
    const float* __restrict__ als, const float* __restrict__ ald,
    const float* __restrict__ hs, float* __restrict__ z,
    float* __restrict__ out, int coloff) {
    long gw = ((long)blockIdx.x * blockDim.x + threadIdx.x) >> 5;
    int lane = threadIdx.x & 31;
    long e0 = gw * 4;
    if (e0 < tot)
        edge4_body(src, dst, E, tot, e0, als, ald, hs, z, out, coloff, lane);
}

// ---------------- fused: finalize (virtual) + LN stats + graph counts ---------
__global__ void ln_stats_fused_k(const float* __restrict__ out,
                                 const float* __restrict__ z1, const float* __restrict__ z2,
                                 const float* __restrict__ b1, const float* __restrict__ b2,
                                 const int* __restrict__ batch,
                                 float* __restrict__ cnt,
                                 float* __restrict__ gsum, float* __restrict__ gsq, int N) {
    int n = (blockIdx.x * blockDim.x + threadIdx.x) >> 5;
    int lane = threadIdx.x & 31;
    if (n >= N) return;
    float2 zz1 = ((const float2*)z1)[n];
    float2 zz2 = ((const float2*)z2)[n];
    float iz10 = 1.f / (zz1.x + 1e-16f), iz11 = 1.f / (zz1.y + 1e-16f);
    float iz20 = 1.f / (zz2.x + 1e-16f), iz21 = 1.f / (zz2.y + 1e-16f);
    const float4* xr = (const float4*)(out + (size_t)n * DIM);
    float s = 0.f, q = 0.f;
    #pragma unroll
    for (int c = lane; c < 50; c += 32) {
        float4 val = xr[c];
        int j = 4 * c;
        float4 b = (c < 25) ? ((const float4*)b1)[c] : ((const float4*)b2)[c - 25];
        float izA, izB;
        if (c < 25) { izA = iz10; izB = iz11; } else { izA = iz20; izB = iz21; }
        int jj = (c < 25) ? j : j - 100;
        float y0 = val.x * (jj     < 50 ? izA : izB) + b.x;
        float y1 = val.y * (jj + 1 < 50 ? izA : izB) + b.y;
        float y2 = val.z * (jj + 2 < 50 ? izA : izB) + b.z;
        float y3 = val.w * (jj + 3 < 50 ? izA : izB) + b.w;
        s += y0 + y1 + y2 + y3;
        q += y0*y0 + y1*y1 + y2*y2 + y3*y3;
    }
    s = warp_sum(s); q = warp_sum(q);
    if (lane == 0) {
        int g = batch[n];
        atomicAdd(&cnt[g], 1.f);
        atomicAdd(&gsum[g], s);
        atomicAdd(&gsq[g], q);
    }
}

// ---------------- fused: finalize + LN apply + elu + SAG T/R dots -------------
__global__ void ln_apply_fused_k(float* __restrict__ x,
                                 const float* __restrict__ z1, const float* __restrict__ z2,
                                 const float* __restrict__ b1, const float* __restrict__ b2,
                                 const int* __restrict__ batch,
                                 const float* __restrict__ cnt, const float* __restrict__ gsum,
                                 const float* __restrict__ gsq,
                                 const float* __restrict__ wv, const float* __restrict__ bv,
                                 const float* __restrict__ Wrel, const float* __restrict__ Wroot,
                                 float* __restrict__ T, float* __restrict__ R, int N) {
    int n = (blockIdx.x * blockDim.x + threadIdx.x) >> 5;
    int lane = threadIdx.x & 31;
    if (n >= N) return;
    int g = batch[n];
    float norm = fmaxf(cnt[g], 1.f) * (float)DIM;
    float mean = gsum[g] / norm;
    float var  = gsq[g] / norm - mean * mean;
    float rstd = rsqrtf(var + 1e-5f);
    float2 zz1 = ((const float2*)z1)[n];
    float2 zz2 = ((const float2*)z2)[n];
    float iz10 = 1.f / (zz1.x + 1e-16f), iz11 = 1.f / (zz1.y + 1e-16f);
    float iz20 = 1.f / (zz2.x + 1e-16f), iz21 = 1.f / (zz2.y + 1e-16f);
    float4* xr = (float4*)(x + (size_t)n * DIM);
    float t = 0.f, r = 0.f;
    #pragma unroll
    for (int c = lane; c < 50; c += 32) {
        float4 val = xr[c];
        int j = 4 * c;
        float4 b = (c < 25) ? ((const float4*)b1)[c] : ((const float4*)b2)[c - 25];
        float izA, izB;
        if (c < 25) { izA = iz10; izB = iz11; } else { izA = iz20; izB = iz21; }
        int jj = (c < 25) ? j : j - 100;
        float4 w4 = ((const float4*)wv)[c];
        float4 bb = ((const float4*)bv)[c];
        float4 wr = ((const float4*)Wrel)[c];
        float4 wo = ((const float4*)Wroot)[c];
        float y0 = val.x * (jj     < 50 ? izA : izB) + b.x;
        float y1 = val.y * (jj + 1 < 50 ? izA : izB) + b.y;
        float y2 = val.z * (jj + 2 < 50 ? izA : izB) + b.z;
        float y3 = val.w * (jj + 3 < 50 ? izA : izB) + b.w;
        float e0 = eluf((y0 - mean) * rstd * w4.x + bb.x);
        float e1 = eluf((y1 - mean) * rstd * w4.y + bb.y);
        float e2 = eluf((y2 - mean) * rstd * w4.z + bb.z);
        float e3 = eluf((y3 - mean) * rstd * w4.w + bb.w);
        xr[c] = make_float4(e0, e1, e2, e3);
        t += e0*wr.x + e1*wr.y + e2*wr.z + e3*wr.w;
        r += e0*wo.x + e1*wo.y + e2*wo.z + e3*wo.w;
    }
    t = warp_sum(t); r = warp_sum(r);
    if (lane == 0) { T[n] = t; R[n] = r; }
}

// ---------------- SAG pooling (no-max softmax) ----------------
__global__ void sag_edge_k(const int* __restrict__ src, const int* __restrict__ dst, int E,
                           const float* __restrict__ T, float* __restrict__ agg) {
    int e = blockIdx.x * blockDim.x + threadIdx.x;
    if (e < E) atomicAdd(&agg[dst[e]], T[src[e]]);
}

__global__ void sag_spre_k(const float* __restrict__ agg, const float* __restrict__ R,
                           const float* __restrict__ brel, const int* __restrict__ batch,
                           float* __restrict__ spre, float* __restrict__ sgz, int N) {
    int i = blockIdx.x * blockDim.x + threadIdx.x;
    if (i >= N) return;
    float s = agg[i] + brel[0] + R[i];
    spre[i] = s;
    atomicAdd(&sgz[batch[i]], __expf(s));
}

__global__ void sag_scale_k(float* __restrict__ x, const float* __restrict__ spre,
                            const float* __restrict__ sgz,
                            const int* __restrict__ batch, float* __restrict__ G, int N) {
    long i = (long)blockIdx.x * blockDim.x + threadIdx.x;
    if (i >= (long)N * 50) return;
    int n = (int)(i / 50), q = (int)(i - (long)n * 50);
    int g = batch[n];
    float score = __expf(spre[n]) / (sgz[g] + 1e-16f);
    float4 v = *(float4*)(x + (size_t)n * DIM + 4 * q);
    v.x *= score; v.y *= score; v.z *= score; v.w *= score;
    *(float4*)(x + (size_t)n * DIM + 4 * q) = v;
    float* p = G + (size_t)g * DIM + 4 * q;
    asm volatile("red.global.add.v4.f32 [%0], {%1,%2,%3,%4};"
                 :: "l"(p), "f"(v.x), "f"(v.y), "f"(v.z), "f"(v.w) : "memory");
}

extern "C" void kernel_launch(void* const* d_in, const int* in_sizes, int n_in,
                              void* d_out, int out_size) {
    const float* atom_x  = (const float*)d_in[0];
    const int*   aei     = (const int*)  d_in[1];
    const int*   abatch  = (const int*)  d_in[2];
    const float* aa_x    = (const float*)d_in[3];
    const int*   pei     = (const int*)  d_in[4];
    // d_in[5] = aa_edge_attr (unused by reference)
    const int*   pbatch  = (const int*)  d_in[6];
    const int*   m2p     = (const int*)  d_in[7];
    const float* Wd      = (const float*)d_in[8];
    const float* ad_src  = (const float*)d_in[9];
    const float* ad_dst  = (const float*)d_in[10];
    const float* bd      = (const float*)d_in[11];
    const float* Wp      = (const float*)d_in[12];
    const float* ap_src  = (const float*)d_in[13];
    const float* ap_dst  = (const float*)d_in[14];
    const float* bp      = (const float*)d_in[15];
    const float* Wi_src  = (const float*)d_in[16];
    const float* Wi_dst  = (const float*)d_in[17];
    const float* ai_src  = (const float*)d_in[18];
    const float* ai_dst  = (const float*)d_in[19];
    const float* bi      = (const float*)d_in[20];
    const float* ln_d_w  = (const float*)d_in[21];
    const float* ln_d_b  = (const float*)d_in[22];
    const float* ln_p_w  = (const float*)d_in[23];
    const float* ln_p_b  = (const float*)d_in[24];
    const float* pd_Wrel = (const float*)d_in[25];
    const float* pd_brel = (const float*)d_in[26];
    const float* pd_Wroot= (const float*)d_in[27];
    const float* pp_Wrel = (const float*)d_in[28];
    const float* pp_brel = (const float*)d_in[29];
    const float* pp_Wroot= (const float*)d_in[30];

    cudaFuncSetAttribute(gemm4_k, cudaFuncAttributeMaxDynamicSharedMemorySize, (int)GEMM_SMEM);

    float* S = nullptr;
    cudaGetSymbolAddress((void**)&S, g_scratch);

    float* HSA   = S + OFF_HSA;
    float* HSB   = S + OFF_HSB;
    float* HSC   = S + OFF_HSC;
    float* ALS1  = S + OFF_ALS1;
    float* ALD1  = S + OFF_ALD1;
    float* ALS2  = S + OFF_ALS2;
    float* ALD2  = S + OFF_ALD2;
    float* ALS3  = S + OFF_ALS3;
    float* ALD3  = S + OFF_ALD3;
    float* ALS4  = S + OFF_ALS4;
    float* ALD4  = S + OFF_ALD4;
    float* ZA1   = S + OFF_ZA1;
    float* ZA2   = S + OFF_ZA2;
    float* ZP1   = S + OFF_ZP1;
    float* ZP2   = S + OFF_ZP2;
    float* AGGA  = S + OFF_AGGA;
    float* AGGP  = S + OFF_AGGP;
    float* SGZA  = S + OFF_SGZA;
    float* SGZP  = S + OFF_SGZP;
    float* CNTA  = S + OFF_CNTA;
    float* CNTP  = S + OFF_CNTP;
    float* V     = S + OFF_V;
    float* T     = S + OFF_T;
    float* R     = S + OFF_R;
    float* SPREA = S + OFF_SPREA;
    float* SPREP = S + OFF_SPREP;

    float* out = (float*)d_out;
    float* OA  = out;                                  // atom_h -> atom_out [25600,200]
    float* OP  = out + (size_t)NATOM * DIM;            // aa_h -> aa_out    [204800,200]
    float* DG  = out + (size_t)(NATOM + NAA) * DIM;    // drug_g [512,200]
    float* PG  = DG + (size_t)NB * DIM;                // prot_g [512,200]

    const int* a_src_e = aei;
    const int* a_dst_e = aei + EATOM;
    const int* p_src_e = pei;
    const int* p_dst_e = pei + EAA;
    const int* m_atom  = m2p;
    const int* m_aa    = m2p + EM2P;
    const int  nloop_i = NATOM;   // min(NATOM, NAA)

    // Streams/events created ONCE (first call = correctness run, before the
    // harness's pre-capture memory baseline). Reused every call.
    static cudaStream_t s2 = nullptr, s3 = nullptr;
    static cudaEvent_t evF = nullptr, evG1 = nullptr, evE3 = nullptr,
                       evLNa = nullptr, evSAGa = nullptr, evG4 = nullptr,
                       evSCa = nullptr;
    if (!s2) {
        cudaStreamCreateWithFlags(&s2, cudaStreamNonBlocking);
        cudaStreamCreateWithFlags(&s3, cudaStreamNonBlocking);
        cudaEventCreateWithFlags(&evF,    cudaEventDisableTiming);
        cudaEventCreateWithFlags(&evG1,   cudaEventDisableTiming);
        cudaEventCreateWithFlags(&evE3,   cudaEventDisableTiming);
        cudaEventCreateWithFlags(&evLNa,  cudaEventDisableTiming);
        cudaEventCreateWithFlags(&evSAGa, cudaEventDisableTiming);
        cudaEventCreateWithFlags(&evG4,   cudaEventDisableTiming);
        cudaEventCreateWithFlags(&evSCa,  cudaEventDisableTiming);
    }
    cudaStream_t s0 = 0;   // legacy default (the captured stream)

    // ---- main stream: init ----
    cudaMemsetAsync(d_out, 0, (size_t)out_size * sizeof(float), s0);
    cudaMemsetAsync(S + OFF_ZSTART, 0, (size_t)(OFF_ZEND - OFF_ZSTART) * sizeof(float), s0);
    fold_v_k<<<2, 256, 0, s0>>>(Wi_dst, ai_dst, V);

    // ---- fork ----
    cudaEventRecord(evF, s0);
    cudaStreamWaitEvent(s2, evF, 0);
    cudaStreamWaitEvent(s3, evF, 0);

    // s2: G1 = atom intra GEMM (+ atom inter-dst dot -> ALD2)
    gemm4_k<<<(NATOM + 127) / 128, 400, GEMM_SMEM, s2>>>(atom_x, Wd, HSA, ALS1, ad_src, ad_dst, ALD1,
                                                         V, ALD2, NATOM, 1);
    cudaEventRecord(evG1, s2);

    // s3: G3 = aa intra GEMM (+ aa inter-dst dot -> ALD4), private HSC,
    //     then IMMEDIATELY the aa-intra edge pass (depends only on G3 + memset)
    gemm4_k<<<(NAA + 127) / 128, 400, GEMM_SMEM, s3>>>(aa_x, Wp, HSC, ALS3, ap_src, ap_dst, ALD3,
                                                       V, ALD4, NAA, 1);
    {
        long tot = (long)EAA + NAA;
        long nw = (tot + 3) / 4;
        edge_acc1_k<<<(nw * 32 + 255) / 256, 256, 0, s3>>>(
            p_src_e, p_dst_e, EAA, tot, ALS3, ALD3, HSC, ZP1, OP, 0);
    }
    cudaEventRecord(evE3, s3);

    // s0: G2 = atom-phase inter source GEMM (aa_x @ Wi_src)
    gemm4_k<<<(NAA + 127) / 128, 400, GEMM_SMEM, s0>>>(aa_x, Wi_src, HSB, ALS2, ai_src, ai_dst, nullptr,
                                                       nullptr, nullptr, NAA, 1);

    // join G1, then merged atom edge pass (intra + inter)
    cudaStreamWaitEvent(s0, evG1, 0);
    {
        long tot1 = (long)EATOM + NATOM, tot2 = (long)EM2P + nloop_i;
        long W1 = (tot1 + 3) / 4, W2 = (tot2 + 3) / 4;
        edge_acc2_k<<<((W1 + W2) * 32 + 255) / 256, 256, 0, s0>>>(
            a_src_e, a_dst_e, EATOM, tot1, W1, ALS1, ALD1, HSA, ZA1,
            m_aa, m_atom, EM2P, tot2, ALS2, ALD2, HSB, ZA2, OA);
    }

    // atom LN (stats + apply) on s0
    ln_stats_fused_k<<<(NATOM * 32 + 255) / 256, 256, 0, s0>>>(OA, ZA1, ZA2, bd, bi, abatch,
                                                               CNTA, CNTA + NB, CNTA + 2 * NB, NATOM);
    ln_apply_fused_k<<<(NATOM * 32 + 255) / 256, 256, 0, s0>>>(OA, ZA1, ZA2, bd, bi, abatch,
                                                               CNTA, CNTA + NB, CNTA + 2 * NB,
                                                               ln_d_w, ln_d_b, pd_Wrel, pd_Wroot,
                                                               T, R, NATOM);
    cudaEventRecord(evLNa, s0);

    // s2: atom SAG scalars (reads T/R), concurrent with G4 on s0
    cudaStreamWaitEvent(s2, evLNa, 0);
    sag_edge_k<<<(EATOM + 255) / 256, 256, 0, s2>>>(a_src_e, a_dst_e, EATOM, T, AGGA);
    sag_spre_k<<<(NATOM + 255) / 256, 256, 0, s2>>>(AGGA, R, pd_brel, abatch, SPREA, SGZA, NATOM);
    cudaEventRecord(evSAGa, s2);

    // s0: G4 = aa-phase inter source GEMM (atom_h @ Wi_src); overwrites HSA
    gemm4_k<<<(NATOM + 127) / 128, 400, GEMM_SMEM, s0>>>(OA, Wi_src, HSA, ALS4, ai_src, ai_dst, nullptr,
                                                         nullptr, nullptr, NATOM, 0);
    cudaEventRecord(evG4, s0);

    // s2: deferred atom SAG scale (OA -> atom_out, drug_g) after G4 consumed OA
    cudaStreamWaitEvent(s2, evG4, 0);
    sag_scale_k<<<((long)NATOM * 50 + 255) / 256, 256, 0, s2>>>(OA, SPREA, SGZA, abatch, DG, NATOM);
    cudaEventRecord(evSCa, s2);   // join point for s2's tail

    // s0: aa-inter edge pass (needs G4 on s0 and ALD4 from G3 via evE3)
    cudaStreamWaitEvent(s0, evE3, 0);
    {
        long tot = (long)EM2P + nloop_i;
        long nw = (tot + 3) / 4;
        edge_acc1_k<<<(nw * 32 + 255) / 256, 256, 0, s0>>>(
            m_atom, m_aa, EM2P, tot, ALS4, ALD4, HSA, ZP2, OP, HCD);
    }

    // aa LN: stats, then (after s2 done reading T/R) apply
    ln_stats_fused_k<<<(NAA * 32 + 255) / 256, 256, 0, s0>>>(OP, ZP1, ZP2, bp, bi, pbatch,
                                                             CNTP, CNTP + NB, CNTP + 2 * NB, NAA);
    cudaStreamWaitEvent(s0, evSAGa, 0);
    ln_apply_fused_k<<<(NAA * 32 + 255) / 256, 256, 0, s0>>>(OP, ZP1, ZP2, bp, bi, pbatch,
                                                             CNTP, CNTP + NB, CNTP + 2 * NB,
                                                             ln_p_w, ln_p_b, pp_Wrel, pp_Wroot,
                                                             T, R, NAA);
    // aa SAG
    sag_edge_k<<<(EAA + 255) / 256, 256, 0, s0>>>(p_src_e, p_dst_e, EAA, T, AGGP);
    sag_spre_k<<<(NAA + 255) / 256, 256, 0, s0>>>(AGGP, R, pp_brel, pbatch, SPREP, SGZP, NAA);

    // join s2's tail (sag_scale atom) back into s0 before the final kernel so
    // every forked branch rejoins the capture-origin stream.
    cudaStreamWaitEvent(s0, evSCa, 0);
    sag_scale_k<<<((long)NAA * 50 + 255) / 256, 256, 0, s0>>>(OP, SPREP, SGZP, pbatch, PG, NAA);
}